// round 2
// baseline (speedup 1.0000x reference)
#include <cuda_runtime.h>

#define NS 2048
#define NC 4096
#define NG 2048
#define D  256
#define NH 8
#define DK 32
#define TT 4097   // 1 + NS + NG

// ---------------- device scratch (static globals; no runtime alloc) ----------------
__device__ float g_HS[NS * D];
__device__ float g_HC[NC * D];
__device__ float g_Q[NS * D];
__device__ float g_K[NC * D];
__device__ float g_V[NC * D];
__device__ float g_P[67108864];          // [s][h][c] = 2048*8*4096 exp(gated score)
__device__ float g_Z[NS * NH];           // softmax denominators
__device__ float g_Hnew[NS * D];         // attn @ V  (s, h*32+d)
__device__ float g_tmp[NS * D];          // O-proj output
__device__ float g_tok[TT * D];          // [fusion; HSu; HG]
__device__ float g_k2[TT * D];
__device__ float g_v2[TT * D];
__device__ float g_q0[D];
__device__ float g_p0[TT * NH];
__device__ float g_Z0[NH];
__device__ float g_a0[D];

__device__ __forceinline__ float warpSum(float v) {
#pragma unroll
    for (int o = 16; o; o >>= 1) v += __shfl_xor_sync(0xffffffffu, v, o);
    return v;
}

// ---------------- zero accumulators ----------------
__global__ void zero_kernel() {
    int i = blockIdx.x * blockDim.x + threadIdx.x;
    if (i < NS * NH) g_Z[i] = 0.f;
    if (i < NH) g_Z0[i] = 0.f;
    if (i < D) g_a0[i] = 0.f;
}

// ---------------- generic GEMM: C[m,n] = sum_k A[m,k]*W[n,k] + bias[n] ----------------
// BM=64 BN=64 BK=16, 256 threads, 4x4 per thread. K % 16 == 0, N % 64 == 0.
__global__ __launch_bounds__(256) void gemm_bias_kernel(
    const float* __restrict__ A, const float* __restrict__ W,
    const float* __restrict__ bias, float* __restrict__ C,
    int M, int N, int K)
{
    __shared__ float As[64][16];
    __shared__ float Bs[64][17];
    int bm = blockIdx.y * 64, bn = blockIdx.x * 64;
    int tid = threadIdx.x;
    int tx = tid & 15, ty = tid >> 4;
    float acc[4][4] = {};
    for (int k0 = 0; k0 < K; k0 += 16) {
#pragma unroll
        for (int t = 0; t < 4; t++) {
            int idx = tid + t * 256;
            int r = idx >> 4, c = idx & 15;
            int gm = bm + r;
            As[r][c] = (gm < M) ? A[(size_t)gm * K + k0 + c] : 0.f;
        }
#pragma unroll
        for (int t = 0; t < 4; t++) {
            int idx = tid + t * 256;
            int r = idx >> 4, c = idx & 15;
            Bs[r][c] = W[(size_t)(bn + r) * K + k0 + c];
        }
        __syncthreads();
#pragma unroll
        for (int kk = 0; kk < 16; kk++) {
            float a[4], b[4];
#pragma unroll
            for (int i = 0; i < 4; i++) a[i] = As[ty * 4 + i][kk];
#pragma unroll
            for (int j = 0; j < 4; j++) b[j] = Bs[tx * 4 + j][kk];
#pragma unroll
            for (int i = 0; i < 4; i++)
#pragma unroll
                for (int j = 0; j < 4; j++) acc[i][j] += a[i] * b[j];
        }
        __syncthreads();
    }
#pragma unroll
    for (int i = 0; i < 4; i++) {
        int gm = bm + ty * 4 + i;
        if (gm >= M) continue;
#pragma unroll
        for (int j = 0; j < 4; j++) {
            int gn = bn + tx * 4 + j;
            float bv = bias ? bias[gn] : 0.f;
            C[(size_t)gm * N + gn] = acc[i][j] + bv;
        }
    }
}

// ---------------- pass A: P = exp(gate * QK / sqrt(dk)); Z = row sums ----------------
// block: 32 s-rows x 64 c-cols, all 8 heads.  grid (NC/64, NS/32)
__global__ __launch_bounds__(256) void pass_a_kernel(const float* __restrict__ G)
{
    __shared__ float Qs[32][257];
    __shared__ float Ks[64][33];
    const float isq = 0.17677669529663687f; // 1/sqrt(32)
    int s0 = blockIdx.y * 32, c0 = blockIdx.x * 64;
    int tid = threadIdx.x;
    int tx = tid & 15, ty = tid >> 4;  // ty 0..15 -> 2 s rows, tx 0..15 -> 4 c cols

#pragma unroll
    for (int t = 0; t < 32; t++)
        Qs[t][tid] = g_Q[(size_t)(s0 + t) * D + tid];

    float4 gv[2];
#pragma unroll
    for (int i = 0; i < 2; i++)
        gv[i] = *(const float4*)(G + (size_t)(s0 + ty * 2 + i) * NC + c0 + tx * 4);

    for (int h = 0; h < NH; h++) {
        __syncthreads();
#pragma unroll
        for (int t = 0; t < 8; t++) {
            int idx = t * 256 + tid;
            int r = idx >> 5, d = idx & 31;
            Ks[r][d] = g_K[(size_t)(c0 + r) * D + h * 32 + d];
        }
        __syncthreads();
        float acc[2][4] = {};
#pragma unroll
        for (int d = 0; d < 32; d++) {
            float a0 = Qs[ty * 2 + 0][h * 32 + d];
            float a1 = Qs[ty * 2 + 1][h * 32 + d];
            float b0 = Ks[tx * 4 + 0][d];
            float b1 = Ks[tx * 4 + 1][d];
            float b2 = Ks[tx * 4 + 2][d];
            float b3 = Ks[tx * 4 + 3][d];
            acc[0][0] += a0 * b0; acc[0][1] += a0 * b1; acc[0][2] += a0 * b2; acc[0][3] += a0 * b3;
            acc[1][0] += a1 * b0; acc[1][1] += a1 * b1; acc[1][2] += a1 * b2; acc[1][3] += a1 * b3;
        }
#pragma unroll
        for (int i = 0; i < 2; i++) {
            const float* gp = (const float*)&gv[i];
            float4 p4;
            float* pp = (float*)&p4;
            float rsum = 0.f;
#pragma unroll
            for (int j = 0; j < 4; j++) {
                float p = __expf(acc[i][j] * isq * gp[j]);
                pp[j] = p;
                rsum += p;
            }
            size_t base = ((size_t)(s0 + ty * 2 + i) * NH + h) * NC + c0 + tx * 4;
            *(float4*)(g_P + base) = p4;
            // reduce over 16 tx lanes (same s row)
#pragma unroll
            for (int o = 8; o; o >>= 1) rsum += __shfl_down_sync(0xffffffffu, rsum, o, 16);
            if ((tid & 15) == 0)
                atomicAdd(&g_Z[(s0 + ty * 2 + i) * NH + h], rsum);
        }
    }
}

// ---------------- pass B: Hnew = softmax(P) @ V ; attn_map = mean_h softmax ----------------
// block: 16 s-rows, all heads (256 out cols). grid NS/16 = 128. c tiles of 16.
__global__ __launch_bounds__(256) void pass_b_kernel(float* __restrict__ attn_map)
{
    __shared__ float Ps[128][17];    // [s*8+h][c]
    __shared__ float Vs[16][256];
    __shared__ float sZ[128];        // 1/Z
    int s0 = blockIdx.x * 16;
    int tid = threadIdx.x;
    if (tid < 128) sZ[tid] = 1.0f / g_Z[s0 * NH + tid];
    int colg = tid & 63;
    int col0 = colg * 4;
    int h = colg >> 3;
    int sBase = (tid >> 6) * 4;
    float acc[4][4] = {};
    __syncthreads();
    for (int c0 = 0; c0 < NC; c0 += 16) {
        __syncthreads();
#pragma unroll
        for (int t = 0; t < 8; t++) {
            int idx = t * 256 + tid;
            int r = idx >> 4, c = idx & 15;
            Ps[r][c] = g_P[((size_t)s0 * NH + r) * NC + c0 + c];
        }
#pragma unroll
        for (int t = 0; t < 16; t++)
            Vs[t][tid] = g_V[(size_t)(c0 + t) * D + tid];
        __syncthreads();
#pragma unroll
        for (int cc = 0; cc < 16; cc++) {
            float4 v4 = *(const float4*)&Vs[cc][col0];
#pragma unroll
            for (int i = 0; i < 4; i++) {
                float p = Ps[(sBase + i) * 8 + h][cc];
                acc[i][0] += p * v4.x;
                acc[i][1] += p * v4.y;
                acc[i][2] += p * v4.z;
                acc[i][3] += p * v4.w;
            }
        }
        // attn_map tile: 16 s x 16 c, one entry per thread
        {
            int s = tid >> 4, c = tid & 15;
            float am = 0.f;
#pragma unroll
            for (int hh = 0; hh < 8; hh++) am += Ps[s * 8 + hh][c] * sZ[s * 8 + hh];
            attn_map[(size_t)(s0 + s) * NC + c0 + c] = am * 0.125f;
        }
    }
#pragma unroll
    for (int i = 0; i < 4; i++) {
        float iz = sZ[(sBase + i) * 8 + h];
#pragma unroll
        for (int j = 0; j < 4; j++)
            g_Hnew[(size_t)(s0 + sBase + i) * D + col0 + j] = acc[i][j] * iz;
    }
}

// ---------------- cross-attn epilogue LN: tokens[1..NS] = LN(tmp + HS); tokens[0] = fusion ----------------
__global__ __launch_bounds__(256) void ln_ca_kernel(
    const float* __restrict__ g, const float* __restrict__ b, const float* __restrict__ fusion)
{
    int tid = threadIdx.x;
    if (blockIdx.x == 0 && tid < D) g_tok[tid] = fusion[tid];
    int warp = tid >> 5, lane = tid & 31;
    int row = blockIdx.x * 8 + warp;
    float x[8];
    float s = 0.f;
#pragma unroll
    for (int j = 0; j < 8; j++) {
        int c = lane + 32 * j;
        x[j] = g_tmp[(size_t)row * D + c] + g_HS[(size_t)row * D + c];
        s += x[j];
    }
    s = warpSum(s);
    float m = s * (1.0f / D);
    float vs = 0.f;
#pragma unroll
    for (int j = 0; j < 8; j++) { float d = x[j] - m; vs += d * d; }
    vs = warpSum(vs);
    float r = rsqrtf(vs * (1.0f / D) + 1e-5f);
#pragma unroll
    for (int j = 0; j < 8; j++) {
        int c = lane + 32 * j;
        g_tok[(size_t)(1 + row) * D + c] = (x[j] - m) * r * g[c] + b[c];
    }
}

// ---------------- q0 = fusion @ Wq.T + bq ----------------
__global__ void q0_kernel(const float* __restrict__ fusion,
                          const float* __restrict__ w, const float* __restrict__ bqkv)
{
    __shared__ float fs[D];
    int tid = threadIdx.x;
    fs[tid] = fusion[tid];
    __syncthreads();
    float a = bqkv[tid];
    for (int c = 0; c < D; c++) a += fs[c] * w[(size_t)tid * D + c];
    g_q0[tid] = a;
}

// ---------------- row-0 scores: p0[u][h] = exp(q0_h . k_u_h / sqrt(dk)); Z0[h] ----------------
__global__ __launch_bounds__(256) void score0_kernel()
{
    __shared__ float q0s[D];
    __shared__ float zpart[NH];
    int tid = threadIdx.x;
    if (tid < D) q0s[tid] = g_q0[tid];
    if (tid < NH) zpart[tid] = 0.f;
    __syncthreads();
    int warp = tid >> 5, lane = tid & 31;
    int wtotal = gridDim.x * 8;
    const float isq = 0.17677669529663687f;
    for (int u = blockIdx.x * 8 + warp; u < TT; u += wtotal) {
        float mine = 0.f;
#pragma unroll
        for (int j = 0; j < 8; j++) {
            int c = lane + 32 * j;
            float v = q0s[c] * g_k2[(size_t)u * D + c];
            v = warpSum(v);
            if (lane == j) mine = v;
        }
        if (lane < 8) {
            float p = __expf(mine * isq);
            g_p0[u * NH + lane] = p;
            atomicAdd(&zpart[lane], p);
        }
    }
    __syncthreads();
    if (tid < NH) atomicAdd(&g_Z0[tid], zpart[tid]);
}

// ---------------- row-0 AV: a0[col] += sum_u p0[u][h] * v[u][col] ----------------
__global__ __launch_bounds__(256) void av0_kernel()
{
    int col = threadIdx.x;
    int h = col >> 5;
    int u0 = blockIdx.x * 257;
    int u1 = u0 + 257; if (u1 > TT) u1 = TT;
    float acc = 0.f;
    for (int u = u0; u < u1; u++)
        acc += g_p0[u * NH + h] * g_v2[(size_t)u * D + col];
    atomicAdd(&g_a0[col], acc);
}

// ---------------- final: out proj + ln1 + ffn + ln2 -> z_fused ----------------
__device__ __forceinline__ float blockSum256(float v, volatile float* red) {
    int lane = threadIdx.x & 31, w = threadIdx.x >> 5;
    v = warpSum(v);
    __syncthreads();
    if (lane == 0) red[w] = v;
    __syncthreads();
    float s = 0.f;
#pragma unroll
    for (int i = 0; i < 8; i++) s += red[i];
    return s;
}

__global__ __launch_bounds__(256) void final_kernel(
    const float* __restrict__ fusion,
    const float* __restrict__ mow, const float* __restrict__ mob,
    const float* __restrict__ ln1g, const float* __restrict__ ln1b,
    const float* __restrict__ w1, const float* __restrict__ b1,
    const float* __restrict__ w2, const float* __restrict__ b2,
    const float* __restrict__ ln2g, const float* __restrict__ ln2b,
    float* __restrict__ out)
{
    __shared__ float a0[D], t1[D], h1[2 * D];
    __shared__ float red[8];
    int tid = threadIdx.x;
    a0[tid] = g_a0[tid] / g_Z0[tid >> 5];
    __syncthreads();
    float y = mob[tid];
    for (int j = 0; j < D; j++) y += a0[j] * mow[(size_t)tid * D + j];
    float tv = fusion[tid] + y;
    float m = blockSum256(tv, red) * (1.0f / D);
    float d = tv - m;
    float var = blockSum256(d * d, red) * (1.0f / D);
    float t = d * rsqrtf(var + 1e-5f) * ln1g[tid] + ln1b[tid];
    t1[tid] = t;
    __syncthreads();
    float hh[2];
#pragma unroll
    for (int r2 = 0; r2 < 2; r2++) {
        int jj = tid + r2 * 256;
        float a = b1[jj];
        for (int c = 0; c < D; c++) a += t1[c] * w1[(size_t)jj * D + c];
        hh[r2] = a * 0.5f * (1.f + erff(a * 0.70710678118654752f));
    }
    h1[tid] = hh[0];
    h1[tid + 256] = hh[1];
    __syncthreads();
    float o = b2[tid];
    for (int j = 0; j < 512; j++) o += h1[j] * w2[(size_t)tid * 512 + j];
    // residual is the LN1 OUTPUT (tokens was reassigned before the FFN)
    float t2v = t1[tid] + o;
    float m2 = blockSum256(t2v, red) * (1.0f / D);
    float d2 = t2v - m2;
    float v2 = blockSum256(d2 * d2, red) * (1.0f / D);
    out[tid] = d2 * rsqrtf(v2 + 1e-5f) * ln2g[tid] + ln2b[tid];
}

// ---------------- launcher ----------------
extern "C" void kernel_launch(void* const* d_in, const int* in_sizes, int n_in,
                              void* d_out, int out_size)
{
    const float* H_S     = (const float*)d_in[0];
    const float* H_C     = (const float*)d_in[1];
    const float* H_G     = (const float*)d_in[2];
    const float* G_glyph = (const float*)d_in[3];
    const float* Ws      = (const float*)d_in[4];
    const float* bs      = (const float*)d_in[5];
    const float* Wb      = (const float*)d_in[6];
    const float* bb      = (const float*)d_in[7];
    const float* Wg      = (const float*)d_in[8];
    const float* bg      = (const float*)d_in[9];
    const float* WQ      = (const float*)d_in[10];
    const float* WK      = (const float*)d_in[11];
    const float* WV      = (const float*)d_in[12];
    const float* WO      = (const float*)d_in[13];
    const float* bO      = (const float*)d_in[14];
    const float* ln_ca_g = (const float*)d_in[15];
    const float* ln_ca_b = (const float*)d_in[16];
    const float* fusion  = (const float*)d_in[17];
    const float* mha_in_w  = (const float*)d_in[18];
    const float* mha_in_b  = (const float*)d_in[19];
    const float* mha_out_w = (const float*)d_in[20];
    const float* mha_out_b = (const float*)d_in[21];
    const float* ln1_g   = (const float*)d_in[22];
    const float* ln1_b   = (const float*)d_in[23];
    const float* ln2_g   = (const float*)d_in[24];
    const float* ln2_b   = (const float*)d_in[25];
    const float* ffn_w1  = (const float*)d_in[26];
    const float* ffn_b1  = (const float*)d_in[27];
    const float* ffn_w2  = (const float*)d_in[28];
    const float* ffn_b2  = (const float*)d_in[29];

    float* out = (float*)d_out;
    float* z_fused  = out;        // 256
    float* attn_map = out + D;    // 2048 * 4096

    float *pHS, *pHC, *pQ, *pK, *pV, *pHnew, *pTmp, *pTok, *pk2, *pv2;
    cudaGetSymbolAddress((void**)&pHS,  g_HS);
    cudaGetSymbolAddress((void**)&pHC,  g_HC);
    cudaGetSymbolAddress((void**)&pQ,   g_Q);
    cudaGetSymbolAddress((void**)&pK,   g_K);
    cudaGetSymbolAddress((void**)&pV,   g_V);
    cudaGetSymbolAddress((void**)&pHnew,g_Hnew);
    cudaGetSymbolAddress((void**)&pTmp, g_tmp);
    cudaGetSymbolAddress((void**)&pTok, g_tok);
    cudaGetSymbolAddress((void**)&pk2,  g_k2);
    cudaGetSymbolAddress((void**)&pv2,  g_v2);

    zero_kernel<<<64, 256>>>();

    // input projections
    gemm_bias_kernel<<<dim3(4, 32), 256>>>(H_S, Ws, bs, pHS, NS, D, 128);
    gemm_bias_kernel<<<dim3(4, 64), 256>>>(H_C, Wb, bb, pHC, NC, D, 256);
    gemm_bias_kernel<<<dim3(4, 32), 256>>>(H_G, Wg, bg, pTok + (size_t)(1 + NS) * D, NG, D, 64);

    // Q/K/V
    gemm_bias_kernel<<<dim3(4, 32), 256>>>(pHS, WQ, nullptr, pQ, NS, D, 256);
    gemm_bias_kernel<<<dim3(4, 64), 256>>>(pHC, WK, nullptr, pK, NC, D, 256);
    gemm_bias_kernel<<<dim3(4, 64), 256>>>(pHC, WV, nullptr, pV, NC, D, 256);

    // cross attention
    pass_a_kernel<<<dim3(NC / 64, NS / 32), 256>>>(G_glyph);
    pass_b_kernel<<<NS / 16, 256>>>(attn_map);

    // O projection + residual LN -> tokens
    gemm_bias_kernel<<<dim3(4, 32), 256>>>(pHnew, WO, bO, pTmp, NS, D, 256);
    ln_ca_kernel<<<NS / 8, 256>>>(ln_ca_g, ln_ca_b, fusion);

    // self-attn K/V over tokens
    gemm_bias_kernel<<<dim3(4, 65), 256>>>(pTok, mha_in_w + 256 * 256, mha_in_b + 256, pk2, TT, D, 256);
    gemm_bias_kernel<<<dim3(4, 65), 256>>>(pTok, mha_in_w + 512 * 256, mha_in_b + 512, pv2, TT, D, 256);

    // token-0 attention + head
    q0_kernel<<<1, 256>>>(fusion, mha_in_w, mha_in_b);
    score0_kernel<<<32, 256>>>();
    av0_kernel<<<16, 256>>>();
    final_kernel<<<1, 256>>>(fusion, mha_out_w, mha_out_b, ln1_g, ln1_b,
                             ffn_w1, ffn_b1, ffn_w2, ffn_b2, ln2_g, ln2_b, z_fused);
}

// round 3
// speedup vs baseline: 1.4005x; 1.4005x over previous
#include <cuda_runtime.h>
#include <cuda_fp16.h>

#define NS 2048
#define NC 4096
#define NG 2048
#define D  256
#define NH 8
#define TT 4097   // 1 + NS + NG

// ---------------- device scratch (static globals; no runtime alloc) ----------------
__device__ float  g_HS[NS * D];
__device__ float  g_HC[NC * D];
__device__ __half g_Qh[NS * D];
__device__ __half g_Kh[NC * D];
__device__ __half g_Vh[NC * D];
__device__ __half g_P16[(size_t)NS * NH * NC];   // 128MB un-normalized exp scores
__device__ float  g_Z[NS * NH];                  // softmax denominators
__device__ float  g_Hnew[NS * D];                // normalized attn @ V
__device__ float  g_tmp[NS * D];                 // O-proj output
__device__ float  g_tok[TT * D];                 // [fusion; HSu; HG]
__device__ float  g_k2[TT * D];
__device__ float  g_v2[TT * D];
__device__ float  g_q0[D];
__device__ float  g_p0[TT * NH];
__device__ float  g_Z0[NH];
__device__ float  g_a0[D];

__device__ __forceinline__ float warpSum(float v) {
#pragma unroll
    for (int o = 16; o; o >>= 1) v += __shfl_xor_sync(0xffffffffu, v, o);
    return v;
}

__device__ __forceinline__ void mma16816(float* c, const unsigned* a, const unsigned* b) {
    asm volatile(
        "mma.sync.aligned.m16n8k16.row.col.f32.f16.f16.f32 "
        "{%0,%1,%2,%3}, {%4,%5,%6,%7}, {%8,%9}, {%0,%1,%2,%3};\n"
        : "+f"(c[0]), "+f"(c[1]), "+f"(c[2]), "+f"(c[3])
        : "r"(a[0]), "r"(a[1]), "r"(a[2]), "r"(a[3]), "r"(b[0]), "r"(b[1]));
}

// ---------------- zero accumulators ----------------
__global__ void zero_kernel() {
    int i = blockIdx.x * blockDim.x + threadIdx.x;
    if (i < NH) g_Z0[i] = 0.f;
    if (i < D) g_a0[i] = 0.f;
}

// ---------------- generic GEMM (fp32 out): C[m,n] = sum_k A[m,k]*W[n,k] + bias[n] ----------------
__global__ __launch_bounds__(256) void gemm_bias_kernel(
    const float* __restrict__ A, const float* __restrict__ W,
    const float* __restrict__ bias, float* __restrict__ C,
    int M, int N, int K)
{
    __shared__ float As[64][16];
    __shared__ float Bs[64][17];
    int bm = blockIdx.y * 64, bn = blockIdx.x * 64;
    int tid = threadIdx.x;
    int tx = tid & 15, ty = tid >> 4;
    float acc[4][4] = {};
    for (int k0 = 0; k0 < K; k0 += 16) {
#pragma unroll
        for (int t = 0; t < 4; t++) {
            int idx = tid + t * 256;
            int r = idx >> 4, c = idx & 15;
            int gm = bm + r;
            As[r][c] = (gm < M) ? A[(size_t)gm * K + k0 + c] : 0.f;
        }
#pragma unroll
        for (int t = 0; t < 4; t++) {
            int idx = tid + t * 256;
            int r = idx >> 4, c = idx & 15;
            Bs[r][c] = W[(size_t)(bn + r) * K + k0 + c];
        }
        __syncthreads();
#pragma unroll
        for (int kk = 0; kk < 16; kk++) {
            float a[4], b[4];
#pragma unroll
            for (int i = 0; i < 4; i++) a[i] = As[ty * 4 + i][kk];
#pragma unroll
            for (int j = 0; j < 4; j++) b[j] = Bs[tx * 4 + j][kk];
#pragma unroll
            for (int i = 0; i < 4; i++)
#pragma unroll
                for (int j = 0; j < 4; j++) acc[i][j] += a[i] * b[j];
        }
        __syncthreads();
    }
#pragma unroll
    for (int i = 0; i < 4; i++) {
        int gm = bm + ty * 4 + i;
        if (gm >= M) continue;
#pragma unroll
        for (int j = 0; j < 4; j++) {
            int gn = bn + tx * 4 + j;
            float bv = bias ? bias[gn] : 0.f;
            C[(size_t)gm * N + gn] = acc[i][j] + bv;
        }
    }
}

// ---------------- same GEMM but __half output (for Q/K/V) ----------------
__global__ __launch_bounds__(256) void gemm_h_kernel(
    const float* __restrict__ A, const float* __restrict__ W,
    __half* __restrict__ C, int M, int N, int K)
{
    __shared__ float As[64][16];
    __shared__ float Bs[64][17];
    int bm = blockIdx.y * 64, bn = blockIdx.x * 64;
    int tid = threadIdx.x;
    int tx = tid & 15, ty = tid >> 4;
    float acc[4][4] = {};
    for (int k0 = 0; k0 < K; k0 += 16) {
#pragma unroll
        for (int t = 0; t < 4; t++) {
            int idx = tid + t * 256;
            int r = idx >> 4, c = idx & 15;
            As[r][c] = A[(size_t)(bm + r) * K + k0 + c];
        }
#pragma unroll
        for (int t = 0; t < 4; t++) {
            int idx = tid + t * 256;
            int r = idx >> 4, c = idx & 15;
            Bs[r][c] = W[(size_t)(bn + r) * K + k0 + c];
        }
        __syncthreads();
#pragma unroll
        for (int kk = 0; kk < 16; kk++) {
            float a[4], b[4];
#pragma unroll
            for (int i = 0; i < 4; i++) a[i] = As[ty * 4 + i][kk];
#pragma unroll
            for (int j = 0; j < 4; j++) b[j] = Bs[tx * 4 + j][kk];
#pragma unroll
            for (int i = 0; i < 4; i++)
#pragma unroll
                for (int j = 0; j < 4; j++) acc[i][j] += a[i] * b[j];
        }
        __syncthreads();
    }
#pragma unroll
    for (int i = 0; i < 4; i++)
#pragma unroll
        for (int j = 0; j < 4; j++)
            C[(size_t)(bm + ty * 4 + i) * N + bn + tx * 4 + j] = __float2half(acc[i][j]);
}

// ---------------- fused gated cross-attention (flash-style, HMMA) ----------------
// grid = NS/16 blocks of 256 threads. Per block: 16 s-rows, loop h outer, c inner.
// Warp w owns c-subrange [w*32, w*32+32) of each 256-wide c tile.
__global__ __launch_bounds__(256) void ca_fused_kernel(const float* __restrict__ G)
{
    __shared__ __half Ks[256 * 40];   // [c][k0..31], stride 40 halves (16B aligned, conflict-free)
    __shared__ __half Vs[32 * 264];   // transposed [d][c], stride 264
    __shared__ __half Qs[16 * 40];
    __shared__ float  Hs[16 * 32];
    __shared__ float  Zs[16];

    const int s0 = blockIdx.x * 16;
    const int tid = threadIdx.x;
    const int w = tid >> 5, lane = tid & 31;
    const int gr = lane >> 2, cc = lane & 3;
    const int cw = w * 32;
    const float isq = 0.17677669529663687f;

    for (int h = 0; h < NH; h++) {
        // load Q tile (16 x 32 halves)
        {
            int row = tid >> 4, c2 = (tid & 15) * 2;
            *(unsigned*)&Qs[row * 40 + c2] =
                *(const unsigned*)&g_Qh[(size_t)(s0 + row) * D + h * 32 + c2];
        }
        Hs[tid] = 0.f;
        Hs[tid + 256] = 0.f;
        if (tid < 16) Zs[tid] = 0.f;

        float hacc[4][4] = {};
        float zacc0 = 0.f, zacc1 = 0.f;

        for (int ci = 0; ci < 16; ci++) {
            int c0 = ci * 256;
            __syncthreads();   // prev iter's mma reads / head init done before overwrite
            // cooperative K,V tile load (256 c rows x 32 halves)
            {
                int pr = tid >> 2, pp = tid & 3;
#pragma unroll
                for (int rr = 0; rr < 4; rr++) {
                    int row = rr * 64 + pr;
                    size_t src = (size_t)(c0 + row) * D + h * 32 + pp * 8;
                    *(int4*)&Ks[row * 40 + pp * 8] = *(const int4*)&g_Kh[src];
                    int4 v = *(const int4*)&g_Vh[src];
                    const __half* vh = (const __half*)&v;
#pragma unroll
                    for (int j = 0; j < 8; j++) Vs[(pp * 8 + j) * 264 + row] = vh[j];
                }
            }
            __syncthreads();

            // Q A-fragments (2 k-steps)
            unsigned qa[2][4];
#pragma unroll
            for (int ks = 0; ks < 2; ks++) {
                qa[ks][0] = *(unsigned*)&Qs[gr * 40 + ks * 16 + 2 * cc];
                qa[ks][1] = *(unsigned*)&Qs[(gr + 8) * 40 + ks * 16 + 2 * cc];
                qa[ks][2] = *(unsigned*)&Qs[gr * 40 + ks * 16 + 2 * cc + 8];
                qa[ks][3] = *(unsigned*)&Qs[(gr + 8) * 40 + ks * 16 + 2 * cc + 8];
            }

            unsigned pa[2][4];   // P A-fragments for the PV mma
#pragma unroll
            for (int nt = 0; nt < 4; nt++) {
                float S[4] = {0.f, 0.f, 0.f, 0.f};
#pragma unroll
                for (int ks = 0; ks < 2; ks++) {
                    unsigned b[2];
                    int nrow = cw + nt * 8 + gr;
                    b[0] = *(unsigned*)&Ks[nrow * 40 + ks * 16 + 2 * cc];
                    b[1] = *(unsigned*)&Ks[nrow * 40 + ks * 16 + 2 * cc + 8];
                    mma16816(S, qa[ks], b);
                }
                // epilogue: gate, exp, Z, fp16 P store
                int gcol = c0 + cw + nt * 8 + 2 * cc;
                float2 gA = __ldg((const float2*)&G[(size_t)(s0 + gr) * NC + gcol]);
                float2 gB = __ldg((const float2*)&G[(size_t)(s0 + gr + 8) * NC + gcol]);
                float p0 = __expf(S[0] * isq * gA.x);
                float p1 = __expf(S[1] * isq * gA.y);
                float p2 = __expf(S[2] * isq * gB.x);
                float p3 = __expf(S[3] * isq * gB.y);
                zacc0 += p0 + p1;
                zacc1 += p2 + p3;
                __half2 h01 = __floats2half2_rn(p0, p1);
                __half2 h23 = __floats2half2_rn(p2, p3);
                *(__half2*)&g_P16[((size_t)(s0 + gr) * NH + h) * NC + gcol] = h01;
                *(__half2*)&g_P16[((size_t)(s0 + gr + 8) * NH + h) * NC + gcol] = h23;
                unsigned u01 = *(unsigned*)&h01, u23 = *(unsigned*)&h23;
                if ((nt & 1) == 0) { pa[nt >> 1][0] = u01; pa[nt >> 1][1] = u23; }
                else               { pa[nt >> 1][2] = u01; pa[nt >> 1][3] = u23; }
            }

            // P @ V  (accumulate across c)
#pragma unroll
            for (int nt2 = 0; nt2 < 4; nt2++) {
#pragma unroll
                for (int ks2 = 0; ks2 < 2; ks2++) {
                    unsigned b[2];
                    int d = nt2 * 8 + gr;
                    b[0] = *(unsigned*)&Vs[d * 264 + cw + ks2 * 16 + 2 * cc];
                    b[1] = *(unsigned*)&Vs[d * 264 + cw + ks2 * 16 + 2 * cc + 8];
                    mma16816(hacc[nt2], pa[ks2], b);
                }
            }
        }

        // Z: reduce over quad lanes, then shared atomics across warps
#pragma unroll
        for (int o = 1; o < 4; o <<= 1) {
            zacc0 += __shfl_xor_sync(0xffffffffu, zacc0, o);
            zacc1 += __shfl_xor_sync(0xffffffffu, zacc1, o);
        }
        if (cc == 0) {
            atomicAdd(&Zs[gr], zacc0);
            atomicAdd(&Zs[gr + 8], zacc1);
        }
        // Hnew partials across warps
#pragma unroll
        for (int nt2 = 0; nt2 < 4; nt2++) {
            atomicAdd(&Hs[gr * 32 + nt2 * 8 + 2 * cc],           hacc[nt2][0]);
            atomicAdd(&Hs[gr * 32 + nt2 * 8 + 2 * cc + 1],       hacc[nt2][1]);
            atomicAdd(&Hs[(gr + 8) * 32 + nt2 * 8 + 2 * cc],     hacc[nt2][2]);
            atomicAdd(&Hs[(gr + 8) * 32 + nt2 * 8 + 2 * cc + 1], hacc[nt2][3]);
        }
        __syncthreads();
        if (tid < 16) g_Z[(s0 + tid) * NH + h] = Zs[tid];
#pragma unroll
        for (int k = 0; k < 2; k++) {
            int idx = k * 256 + tid;
            int row = idx >> 5, d = idx & 31;
            g_Hnew[(size_t)(s0 + row) * D + h * 32 + d] = Hs[idx] / Zs[row];
        }
        __syncthreads();
    }
}

// ---------------- attn_map = mean_h P/Z ----------------
__global__ __launch_bounds__(256) void attn_map_kernel(float* __restrict__ AM)
{
    int s = blockIdx.y;
    int c = (blockIdx.x * 256 + threadIdx.x) * 2;
    float a0 = 0.f, a1 = 0.f;
#pragma unroll
    for (int h = 0; h < NH; h++) {
        float iz = 0.125f / g_Z[s * NH + h];
        __half2 p = *(const __half2*)&g_P16[((size_t)s * NH + h) * NC + c];
        float2 pf = __half22float2(p);
        a0 += pf.x * iz;
        a1 += pf.y * iz;
    }
    *(float2*)&AM[(size_t)s * NC + c] = make_float2(a0, a1);
}

// ---------------- cross-attn epilogue LN ----------------
__global__ __launch_bounds__(256) void ln_ca_kernel(
    const float* __restrict__ g, const float* __restrict__ b, const float* __restrict__ fusion)
{
    int tid = threadIdx.x;
    if (blockIdx.x == 0 && tid < D) g_tok[tid] = fusion[tid];
    int warp = tid >> 5, lane = tid & 31;
    int row = blockIdx.x * 8 + warp;
    float x[8];
    float s = 0.f;
#pragma unroll
    for (int j = 0; j < 8; j++) {
        int c = lane + 32 * j;
        x[j] = g_tmp[(size_t)row * D + c] + g_HS[(size_t)row * D + c];
        s += x[j];
    }
    s = warpSum(s);
    float m = s * (1.0f / D);
    float vs = 0.f;
#pragma unroll
    for (int j = 0; j < 8; j++) { float d = x[j] - m; vs += d * d; }
    vs = warpSum(vs);
    float r = rsqrtf(vs * (1.0f / D) + 1e-5f);
#pragma unroll
    for (int j = 0; j < 8; j++) {
        int c = lane + 32 * j;
        g_tok[(size_t)(1 + row) * D + c] = (x[j] - m) * r * g[c] + b[c];
    }
}

// ---------------- q0 = fusion @ Wq.T + bq ----------------
__global__ void q0_kernel(const float* __restrict__ fusion,
                          const float* __restrict__ w, const float* __restrict__ bqkv)
{
    __shared__ float fs[D];
    int tid = threadIdx.x;
    fs[tid] = fusion[tid];
    __syncthreads();
    float a = bqkv[tid];
    for (int c = 0; c < D; c++) a += fs[c] * w[(size_t)tid * D + c];
    g_q0[tid] = a;
}

// ---------------- row-0 scores over tokens ----------------
__global__ __launch_bounds__(256) void score0_kernel()
{
    __shared__ float q0s[D];
    __shared__ float zpart[NH];
    int tid = threadIdx.x;
    if (tid < D) q0s[tid] = g_q0[tid];
    if (tid < NH) zpart[tid] = 0.f;
    __syncthreads();
    int warp = tid >> 5, lane = tid & 31;
    int wtotal = gridDim.x * 8;
    const float isq = 0.17677669529663687f;
    for (int u = blockIdx.x * 8 + warp; u < TT; u += wtotal) {
        float mine = 0.f;
#pragma unroll
        for (int j = 0; j < 8; j++) {
            int c = lane + 32 * j;
            float v = q0s[c] * g_k2[(size_t)u * D + c];
            v = warpSum(v);
            if (lane == j) mine = v;
        }
        if (lane < 8) {
            float p = __expf(mine * isq);
            g_p0[u * NH + lane] = p;
            atomicAdd(&zpart[lane], p);
        }
    }
    __syncthreads();
    if (tid < NH) atomicAdd(&g_Z0[tid], zpart[tid]);
}

// ---------------- row-0 AV ----------------
__global__ __launch_bounds__(256) void av0_kernel()
{
    int col = threadIdx.x;
    int h = col >> 5;
    int u0 = blockIdx.x * 257;
    int u1 = u0 + 257; if (u1 > TT) u1 = TT;
    float acc = 0.f;
    for (int u = u0; u < u1; u++)
        acc += g_p0[u * NH + h] * g_v2[(size_t)u * D + col];
    atomicAdd(&g_a0[col], acc);
}

// ---------------- final head ----------------
__device__ __forceinline__ float blockSum256(float v, volatile float* red) {
    int lane = threadIdx.x & 31, w = threadIdx.x >> 5;
    v = warpSum(v);
    __syncthreads();
    if (lane == 0) red[w] = v;
    __syncthreads();
    float s = 0.f;
#pragma unroll
    for (int i = 0; i < 8; i++) s += red[i];
    return s;
}

__global__ __launch_bounds__(256) void final_kernel(
    const float* __restrict__ fusion,
    const float* __restrict__ mow, const float* __restrict__ mob,
    const float* __restrict__ ln1g, const float* __restrict__ ln1b,
    const float* __restrict__ w1, const float* __restrict__ b1,
    const float* __restrict__ w2, const float* __restrict__ b2,
    const float* __restrict__ ln2g, const float* __restrict__ ln2b,
    float* __restrict__ out)
{
    __shared__ float a0[D], t1[D], h1[2 * D];
    __shared__ float red[8];
    int tid = threadIdx.x;
    a0[tid] = g_a0[tid] / g_Z0[tid >> 5];
    __syncthreads();
    float y = mob[tid];
    for (int j = 0; j < D; j++) y += a0[j] * mow[(size_t)tid * D + j];
    float tv = fusion[tid] + y;
    float m = blockSum256(tv, red) * (1.0f / D);
    float d = tv - m;
    float var = blockSum256(d * d, red) * (1.0f / D);
    float t = d * rsqrtf(var + 1e-5f) * ln1g[tid] + ln1b[tid];
    t1[tid] = t;
    __syncthreads();
    float hh[2];
#pragma unroll
    for (int r2 = 0; r2 < 2; r2++) {
        int jj = tid + r2 * 256;
        float a = b1[jj];
        for (int c = 0; c < D; c++) a += t1[c] * w1[(size_t)jj * D + c];
        hh[r2] = a * 0.5f * (1.f + erff(a * 0.70710678118654752f));
    }
    h1[tid] = hh[0];
    h1[tid + 256] = hh[1];
    __syncthreads();
    float o = b2[tid];
    for (int j = 0; j < 512; j++) o += h1[j] * w2[(size_t)tid * 512 + j];
    float t2v = t1[tid] + o;   // residual = LN1 output
    float m2 = blockSum256(t2v, red) * (1.0f / D);
    float d2 = t2v - m2;
    float v2 = blockSum256(d2 * d2, red) * (1.0f / D);
    out[tid] = d2 * rsqrtf(v2 + 1e-5f) * ln2g[tid] + ln2b[tid];
}

// ---------------- launcher ----------------
extern "C" void kernel_launch(void* const* d_in, const int* in_sizes, int n_in,
                              void* d_out, int out_size)
{
    const float* H_S     = (const float*)d_in[0];
    const float* H_C     = (const float*)d_in[1];
    const float* H_G     = (const float*)d_in[2];
    const float* G_glyph = (const float*)d_in[3];
    const float* Ws      = (const float*)d_in[4];
    const float* bs      = (const float*)d_in[5];
    const float* Wb      = (const float*)d_in[6];
    const float* bb      = (const float*)d_in[7];
    const float* Wg      = (const float*)d_in[8];
    const float* bg      = (const float*)d_in[9];
    const float* WQ      = (const float*)d_in[10];
    const float* WK      = (const float*)d_in[11];
    const float* WV      = (const float*)d_in[12];
    const float* WO      = (const float*)d_in[13];
    const float* bO      = (const float*)d_in[14];
    const float* ln_ca_g = (const float*)d_in[15];
    const float* ln_ca_b = (const float*)d_in[16];
    const float* fusion  = (const float*)d_in[17];
    const float* mha_in_w  = (const float*)d_in[18];
    const float* mha_in_b  = (const float*)d_in[19];
    const float* mha_out_w = (const float*)d_in[20];
    const float* mha_out_b = (const float*)d_in[21];
    const float* ln1_g   = (const float*)d_in[22];
    const float* ln1_b   = (const float*)d_in[23];
    const float* ln2_g   = (const float*)d_in[24];
    const float* ln2_b   = (const float*)d_in[25];
    const float* ffn_w1  = (const float*)d_in[26];
    const float* ffn_b1  = (const float*)d_in[27];
    const float* ffn_w2  = (const float*)d_in[28];
    const float* ffn_b2  = (const float*)d_in[29];

    float* out = (float*)d_out;
    float* z_fused  = out;        // 256
    float* attn_map = out + D;    // 2048 * 4096

    float *pHS, *pHC, *pHnew, *pTmp, *pTok, *pk2, *pv2;
    __half *pQh, *pKh, *pVh;
    cudaGetSymbolAddress((void**)&pHS,  g_HS);
    cudaGetSymbolAddress((void**)&pHC,  g_HC);
    cudaGetSymbolAddress((void**)&pQh,  g_Qh);
    cudaGetSymbolAddress((void**)&pKh,  g_Kh);
    cudaGetSymbolAddress((void**)&pVh,  g_Vh);
    cudaGetSymbolAddress((void**)&pHnew,g_Hnew);
    cudaGetSymbolAddress((void**)&pTmp, g_tmp);
    cudaGetSymbolAddress((void**)&pTok, g_tok);
    cudaGetSymbolAddress((void**)&pk2,  g_k2);
    cudaGetSymbolAddress((void**)&pv2,  g_v2);

    zero_kernel<<<1, 256>>>();

    // input projections
    gemm_bias_kernel<<<dim3(4, 32), 256>>>(H_S, Ws, bs, pHS, NS, D, 128);
    gemm_bias_kernel<<<dim3(4, 64), 256>>>(H_C, Wb, bb, pHC, NC, D, 256);
    gemm_bias_kernel<<<dim3(4, 32), 256>>>(H_G, Wg, bg, pTok + (size_t)(1 + NS) * D, NG, D, 64);

    // Q/K/V (fp16 outputs for tensor-core attention)
    gemm_h_kernel<<<dim3(4, 32), 256>>>(pHS, WQ, pQh, NS, D, 256);
    gemm_h_kernel<<<dim3(4, 64), 256>>>(pHC, WK, pKh, NC, D, 256);
    gemm_h_kernel<<<dim3(4, 64), 256>>>(pHC, WV, pVh, NC, D, 256);

    // fused gated cross attention (Z, Hnew, fp16 P) + attn_map
    ca_fused_kernel<<<NS / 16, 256>>>(G_glyph);
    attn_map_kernel<<<dim3(NC / 512, NS), 256>>>(attn_map);

    // O projection + residual LN -> tokens
    gemm_bias_kernel<<<dim3(4, 32), 256>>>(pHnew, WO, bO, pTmp, NS, D, 256);
    ln_ca_kernel<<<NS / 8, 256>>>(ln_ca_g, ln_ca_b, fusion);

    // self-attn K/V over tokens
    gemm_bias_kernel<<<dim3(4, 65), 256>>>(pTok, mha_in_w + 256 * 256, mha_in_b + 256, pk2, TT, D, 256);
    gemm_bias_kernel<<<dim3(4, 65), 256>>>(pTok, mha_in_w + 512 * 256, mha_in_b + 512, pv2, TT, D, 256);

    // token-0 attention + head
    q0_kernel<<<1, 256>>>(fusion, mha_in_w, mha_in_b);
    score0_kernel<<<32, 256>>>();
    av0_kernel<<<16, 256>>>();
    final_kernel<<<1, 256>>>(fusion, mha_out_w, mha_out_b, ln1_g, ln1_b,
                             ffn_w1, ffn_b1, ffn_w2, ffn_b2, ln2_g, ln2_b, z_fused);
}

// round 4
// speedup vs baseline: 1.6206x; 1.1571x over previous
#include <cuda_runtime.h>
#include <cuda_fp16.h>

#define NS 2048
#define NC 4096
#define NG 2048
#define D  256
#define NH 8
#define TT 4097   // 1 + NS + NG

// ---------------- device scratch (static globals; no runtime alloc) ----------------
__device__ float  g_HS[NS * D];
__device__ float  g_HC[NC * D];
__device__ __half g_Qh[NS * D];
__device__ __half g_Kh[NC * D];
__device__ __half g_Vh[NC * D];
__device__ __half g_P16[(size_t)NS * NH * NC];   // 128MB un-normalized exp scores
__device__ float  g_Z[NS * NH];                  // softmax denominators
__device__ float  g_Hnew[NS * D];                // normalized attn @ V
__device__ float  g_tmp[NS * D];                 // O-proj output
__device__ float  g_tok[TT * D];                 // [fusion; HSu; HG]
__device__ float  g_k2[TT * D];
__device__ float  g_v2[TT * D];
__device__ float  g_q0[D];
__device__ float  g_p0[TT * NH];
__device__ float  g_Z0[NH];
__device__ float  g_a0[D];

__device__ __forceinline__ float warpSum(float v) {
#pragma unroll
    for (int o = 16; o; o >>= 1) v += __shfl_xor_sync(0xffffffffu, v, o);
    return v;
}

__device__ __forceinline__ void mma16816(float* c, const unsigned* a, const unsigned* b) {
    asm volatile(
        "mma.sync.aligned.m16n8k16.row.col.f32.f16.f16.f32 "
        "{%0,%1,%2,%3}, {%4,%5,%6,%7}, {%8,%9}, {%0,%1,%2,%3};\n"
        : "+f"(c[0]), "+f"(c[1]), "+f"(c[2]), "+f"(c[3])
        : "r"(a[0]), "r"(a[1]), "r"(a[2]), "r"(a[3]), "r"(b[0]), "r"(b[1]));
}

__device__ __forceinline__ unsigned smaddr(const void* p) {
    return (unsigned)__cvta_generic_to_shared(p);
}
__device__ __forceinline__ void ldm_x2(unsigned& r0, unsigned& r1, unsigned a) {
    asm volatile("ldmatrix.sync.aligned.m8n8.x2.shared.b16 {%0,%1}, [%2];"
                 : "=r"(r0), "=r"(r1) : "r"(a));
}
__device__ __forceinline__ void ldm_x2_t(unsigned& r0, unsigned& r1, unsigned a) {
    asm volatile("ldmatrix.sync.aligned.m8n8.x2.trans.shared.b16 {%0,%1}, [%2];"
                 : "=r"(r0), "=r"(r1) : "r"(a));
}
__device__ __forceinline__ void ldm_x4(unsigned* r, unsigned a) {
    asm volatile("ldmatrix.sync.aligned.m8n8.x4.shared.b16 {%0,%1,%2,%3}, [%4];"
                 : "=r"(r[0]), "=r"(r[1]), "=r"(r[2]), "=r"(r[3]) : "r"(a));
}

// ---------------- zero accumulators ----------------
__global__ void zero_kernel() {
    int i = blockIdx.x * blockDim.x + threadIdx.x;
    if (i < NH) g_Z0[i] = 0.f;
    if (i < D) g_a0[i] = 0.f;
}

// ---------------- generic GEMM (fp32 out): C[m,n] = sum_k A[m,k]*W[n,k] + bias[n] ----------------
__global__ __launch_bounds__(256) void gemm_bias_kernel(
    const float* __restrict__ A, const float* __restrict__ W,
    const float* __restrict__ bias, float* __restrict__ C,
    int M, int N, int K)
{
    __shared__ float As[64][16];
    __shared__ float Bs[64][17];
    int bm = blockIdx.y * 64, bn = blockIdx.x * 64;
    int tid = threadIdx.x;
    int tx = tid & 15, ty = tid >> 4;
    float acc[4][4] = {};
    for (int k0 = 0; k0 < K; k0 += 16) {
#pragma unroll
        for (int t = 0; t < 4; t++) {
            int idx = tid + t * 256;
            int r = idx >> 4, c = idx & 15;
            int gm = bm + r;
            As[r][c] = (gm < M) ? A[(size_t)gm * K + k0 + c] : 0.f;
        }
#pragma unroll
        for (int t = 0; t < 4; t++) {
            int idx = tid + t * 256;
            int r = idx >> 4, c = idx & 15;
            Bs[r][c] = W[(size_t)(bn + r) * K + k0 + c];
        }
        __syncthreads();
#pragma unroll
        for (int kk = 0; kk < 16; kk++) {
            float a[4], b[4];
#pragma unroll
            for (int i = 0; i < 4; i++) a[i] = As[ty * 4 + i][kk];
#pragma unroll
            for (int j = 0; j < 4; j++) b[j] = Bs[tx * 4 + j][kk];
#pragma unroll
            for (int i = 0; i < 4; i++)
#pragma unroll
                for (int j = 0; j < 4; j++) acc[i][j] += a[i] * b[j];
        }
        __syncthreads();
    }
#pragma unroll
    for (int i = 0; i < 4; i++) {
        int gm = bm + ty * 4 + i;
        if (gm >= M) continue;
#pragma unroll
        for (int j = 0; j < 4; j++) {
            int gn = bn + tx * 4 + j;
            float bv = bias ? bias[gn] : 0.f;
            C[(size_t)gm * N + gn] = acc[i][j] + bv;
        }
    }
}

// ---------------- same GEMM but __half output (for Q/K/V) ----------------
__global__ __launch_bounds__(256) void gemm_h_kernel(
    const float* __restrict__ A, const float* __restrict__ W,
    __half* __restrict__ C, int M, int N, int K)
{
    __shared__ float As[64][16];
    __shared__ float Bs[64][17];
    int bm = blockIdx.y * 64, bn = blockIdx.x * 64;
    int tid = threadIdx.x;
    int tx = tid & 15, ty = tid >> 4;
    float acc[4][4] = {};
    for (int k0 = 0; k0 < K; k0 += 16) {
#pragma unroll
        for (int t = 0; t < 4; t++) {
            int idx = tid + t * 256;
            int r = idx >> 4, c = idx & 15;
            As[r][c] = A[(size_t)(bm + r) * K + k0 + c];
        }
#pragma unroll
        for (int t = 0; t < 4; t++) {
            int idx = tid + t * 256;
            int r = idx >> 4, c = idx & 15;
            Bs[r][c] = W[(size_t)(bn + r) * K + k0 + c];
        }
        __syncthreads();
#pragma unroll
        for (int kk = 0; kk < 16; kk++) {
            float a[4], b[4];
#pragma unroll
            for (int i = 0; i < 4; i++) a[i] = As[ty * 4 + i][kk];
#pragma unroll
            for (int j = 0; j < 4; j++) b[j] = Bs[tx * 4 + j][kk];
#pragma unroll
            for (int i = 0; i < 4; i++)
#pragma unroll
                for (int j = 0; j < 4; j++) acc[i][j] += a[i] * b[j];
        }
        __syncthreads();
    }
#pragma unroll
    for (int i = 0; i < 4; i++)
#pragma unroll
        for (int j = 0; j < 4; j++)
            C[(size_t)(bm + ty * 4 + i) * N + bn + tx * 4 + j] = __float2half(acc[i][j]);
}

// ---------------- fused gated cross-attention (flash-style, HMMA + ldmatrix) ----------------
// grid = (NH, NS/16). Per block: one head, 16 s-rows, full c loop. 256 threads.
// Warp w owns c-subrange [w*32, w*32+32) of each 256-wide c tile.
__global__ __launch_bounds__(256) void ca_fused_kernel(const float* __restrict__ G)
{
    __shared__ __half Ks[256 * 40];   // [c][d], stride 40 halves (80B, ldmatrix conflict-free)
    __shared__ __half Vs[256 * 40];   // [c][d], row-major (ldmatrix.trans for B frags)
    __shared__ __half Qs[16 * 40];
    __shared__ float  Hs[16 * 32];
    __shared__ float  Zs[16];

    const int h = blockIdx.x;
    const int s0 = blockIdx.y * 16;
    const int tid = threadIdx.x;
    const int w = tid >> 5, lane = tid & 31;
    const int gr = lane >> 2, cc = lane & 3;
    const int cw = w * 32;
    const int l4 = lane & 15;
    const float isq = 0.17677669529663687f;

    // load Q tile (16 x 32 halves)
    {
        int row = tid >> 4, c2 = (tid & 15) * 2;
        *(unsigned*)&Qs[row * 40 + c2] =
            *(const unsigned*)&g_Qh[(size_t)(s0 + row) * D + h * 32 + c2];
    }
    Hs[tid] = 0.f;
    Hs[tid + 256] = 0.f;
    if (tid < 16) Zs[tid] = 0.f;
    __syncthreads();

    // Q A-fragments via ldmatrix.x4 (2 k-steps of 16)
    unsigned qa[2][4];
    {
        int qrow = lane & 15;
        int qcol = (lane >> 4) * 8;
#pragma unroll
        for (int ks = 0; ks < 2; ks++)
            ldm_x4(qa[ks], smaddr(&Qs[qrow * 40 + ks * 16 + qcol]));
    }

    float hacc[4][4] = {};
    float zacc0 = 0.f, zacc1 = 0.f;

    for (int ci = 0; ci < 16; ci++) {
        int c0 = ci * 256;
        __syncthreads();   // previous tile's fragment reads complete
        // cooperative K,V tile load (256 c rows x 32 halves), row-major, vectorized
        {
            int pr = tid >> 2, pp = tid & 3;
#pragma unroll
            for (int rr = 0; rr < 4; rr++) {
                int row = rr * 64 + pr;
                size_t src = (size_t)(c0 + row) * D + h * 32 + pp * 8;
                *(int4*)&Ks[row * 40 + pp * 8] = *(const int4*)&g_Kh[src];
                *(int4*)&Vs[row * 40 + pp * 8] = *(const int4*)&g_Vh[src];
            }
        }
        // prefetch gate values for this tile (overlaps with smem fill + mma)
        float2 gA[4], gB[4];
#pragma unroll
        for (int nt = 0; nt < 4; nt++) {
            int gcol = c0 + cw + nt * 8 + 2 * cc;
            gA[nt] = __ldg((const float2*)&G[(size_t)(s0 + gr) * NC + gcol]);
            gB[nt] = __ldg((const float2*)&G[(size_t)(s0 + gr + 8) * NC + gcol]);
        }
        __syncthreads();

        unsigned pa[2][4];   // P A-fragments for the PV mma
#pragma unroll
        for (int nt = 0; nt < 4; nt++) {
            float S[4] = {0.f, 0.f, 0.f, 0.f};
#pragma unroll
            for (int ks = 0; ks < 2; ks++) {
                unsigned b[2];
                ldm_x2(b[0], b[1],
                       smaddr(&Ks[(cw + nt * 8 + (l4 & 7)) * 40 + ks * 16 + (l4 >> 3) * 8]));
                mma16816(S, qa[ks], b);
            }
            // epilogue: gate, exp, Z, fp16 P store
            int gcol = c0 + cw + nt * 8 + 2 * cc;
            float p0 = __expf(S[0] * isq * gA[nt].x);
            float p1 = __expf(S[1] * isq * gA[nt].y);
            float p2 = __expf(S[2] * isq * gB[nt].x);
            float p3 = __expf(S[3] * isq * gB[nt].y);
            zacc0 += p0 + p1;
            zacc1 += p2 + p3;
            __half2 h01 = __floats2half2_rn(p0, p1);
            __half2 h23 = __floats2half2_rn(p2, p3);
            *(__half2*)&g_P16[((size_t)(s0 + gr) * NH + h) * NC + gcol] = h01;
            *(__half2*)&g_P16[((size_t)(s0 + gr + 8) * NH + h) * NC + gcol] = h23;
            unsigned u01 = *(unsigned*)&h01, u23 = *(unsigned*)&h23;
            if ((nt & 1) == 0) { pa[nt >> 1][0] = u01; pa[nt >> 1][1] = u23; }
            else               { pa[nt >> 1][2] = u01; pa[nt >> 1][3] = u23; }
        }

        // P @ V  (accumulate across c) — B frags via ldmatrix.trans on row-major V
#pragma unroll
        for (int nt2 = 0; nt2 < 4; nt2++) {
#pragma unroll
            for (int ks2 = 0; ks2 < 2; ks2++) {
                unsigned b[2];
                ldm_x2_t(b[0], b[1],
                         smaddr(&Vs[(cw + ks2 * 16 + l4) * 40 + nt2 * 8]));
                mma16816(hacc[nt2], pa[ks2], b);
            }
        }
    }

    // Z: reduce over quad lanes, then shared atomics across warps
#pragma unroll
    for (int o = 1; o < 4; o <<= 1) {
        zacc0 += __shfl_xor_sync(0xffffffffu, zacc0, o);
        zacc1 += __shfl_xor_sync(0xffffffffu, zacc1, o);
    }
    if (cc == 0) {
        atomicAdd(&Zs[gr], zacc0);
        atomicAdd(&Zs[gr + 8], zacc1);
    }
    // Hnew partials across warps
#pragma unroll
    for (int nt2 = 0; nt2 < 4; nt2++) {
        atomicAdd(&Hs[gr * 32 + nt2 * 8 + 2 * cc],           hacc[nt2][0]);
        atomicAdd(&Hs[gr * 32 + nt2 * 8 + 2 * cc + 1],       hacc[nt2][1]);
        atomicAdd(&Hs[(gr + 8) * 32 + nt2 * 8 + 2 * cc],     hacc[nt2][2]);
        atomicAdd(&Hs[(gr + 8) * 32 + nt2 * 8 + 2 * cc + 1], hacc[nt2][3]);
    }
    __syncthreads();
    if (tid < 16) g_Z[(s0 + tid) * NH + h] = Zs[tid];
#pragma unroll
    for (int k = 0; k < 2; k++) {
        int idx = k * 256 + tid;
        int row = idx >> 5, d = idx & 31;
        g_Hnew[(size_t)(s0 + row) * D + h * 32 + d] = Hs[idx] / Zs[row];
    }
}

// ---------------- attn_map = mean_h P/Z ----------------
__global__ __launch_bounds__(256) void attn_map_kernel(float* __restrict__ AM)
{
    int s = blockIdx.y;
    int c = (blockIdx.x * 256 + threadIdx.x) * 2;
    float a0 = 0.f, a1 = 0.f;
#pragma unroll
    for (int h = 0; h < NH; h++) {
        float iz = 0.125f / g_Z[s * NH + h];
        __half2 p = *(const __half2*)&g_P16[((size_t)s * NH + h) * NC + c];
        float2 pf = __half22float2(p);
        a0 += pf.x * iz;
        a1 += pf.y * iz;
    }
    *(float2*)&AM[(size_t)s * NC + c] = make_float2(a0, a1);
}

// ---------------- cross-attn epilogue LN ----------------
__global__ __launch_bounds__(256) void ln_ca_kernel(
    const float* __restrict__ g, const float* __restrict__ b, const float* __restrict__ fusion)
{
    int tid = threadIdx.x;
    if (blockIdx.x == 0 && tid < D) g_tok[tid] = fusion[tid];
    int warp = tid >> 5, lane = tid & 31;
    int row = blockIdx.x * 8 + warp;
    float x[8];
    float s = 0.f;
#pragma unroll
    for (int j = 0; j < 8; j++) {
        int c = lane + 32 * j;
        x[j] = g_tmp[(size_t)row * D + c] + g_HS[(size_t)row * D + c];
        s += x[j];
    }
    s = warpSum(s);
    float m = s * (1.0f / D);
    float vs = 0.f;
#pragma unroll
    for (int j = 0; j < 8; j++) { float d = x[j] - m; vs += d * d; }
    vs = warpSum(vs);
    float r = rsqrtf(vs * (1.0f / D) + 1e-5f);
#pragma unroll
    for (int j = 0; j < 8; j++) {
        int c = lane + 32 * j;
        g_tok[(size_t)(1 + row) * D + c] = (x[j] - m) * r * g[c] + b[c];
    }
}

// ---------------- q0 = fusion @ Wq.T + bq ----------------
__global__ void q0_kernel(const float* __restrict__ fusion,
                          const float* __restrict__ w, const float* __restrict__ bqkv)
{
    __shared__ float fs[D];
    int tid = threadIdx.x;
    fs[tid] = fusion[tid];
    __syncthreads();
    float a = bqkv[tid];
    for (int c = 0; c < D; c++) a += fs[c] * w[(size_t)tid * D + c];
    g_q0[tid] = a;
}

// ---------------- row-0 scores over tokens ----------------
__global__ __launch_bounds__(256) void score0_kernel()
{
    __shared__ float q0s[D];
    __shared__ float zpart[NH];
    int tid = threadIdx.x;
    if (tid < D) q0s[tid] = g_q0[tid];
    if (tid < NH) zpart[tid] = 0.f;
    __syncthreads();
    int warp = tid >> 5, lane = tid & 31;
    int wtotal = gridDim.x * 8;
    const float isq = 0.17677669529663687f;
    for (int u = blockIdx.x * 8 + warp; u < TT; u += wtotal) {
        float mine = 0.f;
#pragma unroll
        for (int j = 0; j < 8; j++) {
            int c = lane + 32 * j;
            float v = q0s[c] * g_k2[(size_t)u * D + c];
            v = warpSum(v);
            if (lane == j) mine = v;
        }
        if (lane < 8) {
            float p = __expf(mine * isq);
            g_p0[u * NH + lane] = p;
            atomicAdd(&zpart[lane], p);
        }
    }
    __syncthreads();
    if (tid < NH) atomicAdd(&g_Z0[tid], zpart[tid]);
}

// ---------------- row-0 AV ----------------
__global__ __launch_bounds__(256) void av0_kernel()
{
    int col = threadIdx.x;
    int h = col >> 5;
    int u0 = blockIdx.x * 257;
    int u1 = u0 + 257; if (u1 > TT) u1 = TT;
    float acc = 0.f;
    for (int u = u0; u < u1; u++)
        acc += g_p0[u * NH + h] * g_v2[(size_t)u * D + col];
    atomicAdd(&g_a0[col], acc);
}

// ---------------- final head ----------------
__device__ __forceinline__ float blockSum256(float v, volatile float* red) {
    int lane = threadIdx.x & 31, w = threadIdx.x >> 5;
    v = warpSum(v);
    __syncthreads();
    if (lane == 0) red[w] = v;
    __syncthreads();
    float s = 0.f;
#pragma unroll
    for (int i = 0; i < 8; i++) s += red[i];
    return s;
}

__global__ __launch_bounds__(256) void final_kernel(
    const float* __restrict__ fusion,
    const float* __restrict__ mow, const float* __restrict__ mob,
    const float* __restrict__ ln1g, const float* __restrict__ ln1b,
    const float* __restrict__ w1, const float* __restrict__ b1,
    const float* __restrict__ w2, const float* __restrict__ b2,
    const float* __restrict__ ln2g, const float* __restrict__ ln2b,
    float* __restrict__ out)
{
    __shared__ float a0[D], t1[D], h1[2 * D];
    __shared__ float red[8];
    int tid = threadIdx.x;
    a0[tid] = g_a0[tid] / g_Z0[tid >> 5];
    __syncthreads();
    float y = mob[tid];
    for (int j = 0; j < D; j++) y += a0[j] * mow[(size_t)tid * D + j];
    float tv = fusion[tid] + y;
    float m = blockSum256(tv, red) * (1.0f / D);
    float d = tv - m;
    float var = blockSum256(d * d, red) * (1.0f / D);
    float t = d * rsqrtf(var + 1e-5f) * ln1g[tid] + ln1b[tid];
    t1[tid] = t;
    __syncthreads();
    float hh[2];
#pragma unroll
    for (int r2 = 0; r2 < 2; r2++) {
        int jj = tid + r2 * 256;
        float a = b1[jj];
        for (int c = 0; c < D; c++) a += t1[c] * w1[(size_t)jj * D + c];
        hh[r2] = a * 0.5f * (1.f + erff(a * 0.70710678118654752f));
    }
    h1[tid] = hh[0];
    h1[tid + 256] = hh[1];
    __syncthreads();
    float o = b2[tid];
    for (int j = 0; j < 512; j++) o += h1[j] * w2[(size_t)tid * 512 + j];
    float t2v = t1[tid] + o;   // residual = LN1 output
    float m2 = blockSum256(t2v, red) * (1.0f / D);
    float d2 = t2v - m2;
    float v2 = blockSum256(d2 * d2, red) * (1.0f / D);
    out[tid] = d2 * rsqrtf(v2 + 1e-5f) * ln2g[tid] + ln2b[tid];
}

// ---------------- launcher ----------------
extern "C" void kernel_launch(void* const* d_in, const int* in_sizes, int n_in,
                              void* d_out, int out_size)
{
    const float* H_S     = (const float*)d_in[0];
    const float* H_C     = (const float*)d_in[1];
    const float* H_G     = (const float*)d_in[2];
    const float* G_glyph = (const float*)d_in[3];
    const float* Ws      = (const float*)d_in[4];
    const float* bs      = (const float*)d_in[5];
    const float* Wb      = (const float*)d_in[6];
    const float* bb      = (const float*)d_in[7];
    const float* Wg      = (const float*)d_in[8];
    const float* bg      = (const float*)d_in[9];
    const float* WQ      = (const float*)d_in[10];
    const float* WK      = (const float*)d_in[11];
    const float* WV      = (const float*)d_in[12];
    const float* WO      = (const float*)d_in[13];
    const float* bO      = (const float*)d_in[14];
    const float* ln_ca_g = (const float*)d_in[15];
    const float* ln_ca_b = (const float*)d_in[16];
    const float* fusion  = (const float*)d_in[17];
    const float* mha_in_w  = (const float*)d_in[18];
    const float* mha_in_b  = (const float*)d_in[19];
    const float* mha_out_w = (const float*)d_in[20];
    const float* mha_out_b = (const float*)d_in[21];
    const float* ln1_g   = (const float*)d_in[22];
    const float* ln1_b   = (const float*)d_in[23];
    const float* ln2_g   = (const float*)d_in[24];
    const float* ln2_b   = (const float*)d_in[25];
    const float* ffn_w1  = (const float*)d_in[26];
    const float* ffn_b1  = (const float*)d_in[27];
    const float* ffn_w2  = (const float*)d_in[28];
    const float* ffn_b2  = (const float*)d_in[29];

    float* out = (float*)d_out;
    float* z_fused  = out;        // 256
    float* attn_map = out + D;    // 2048 * 4096

    float *pHS, *pHC, *pHnew, *pTmp, *pTok, *pk2, *pv2;
    __half *pQh, *pKh, *pVh;
    cudaGetSymbolAddress((void**)&pHS,  g_HS);
    cudaGetSymbolAddress((void**)&pHC,  g_HC);
    cudaGetSymbolAddress((void**)&pQh,  g_Qh);
    cudaGetSymbolAddress((void**)&pKh,  g_Kh);
    cudaGetSymbolAddress((void**)&pVh,  g_Vh);
    cudaGetSymbolAddress((void**)&pHnew,g_Hnew);
    cudaGetSymbolAddress((void**)&pTmp, g_tmp);
    cudaGetSymbolAddress((void**)&pTok, g_tok);
    cudaGetSymbolAddress((void**)&pk2,  g_k2);
    cudaGetSymbolAddress((void**)&pv2,  g_v2);

    zero_kernel<<<1, 256>>>();

    // input projections
    gemm_bias_kernel<<<dim3(4, 32), 256>>>(H_S, Ws, bs, pHS, NS, D, 128);
    gemm_bias_kernel<<<dim3(4, 64), 256>>>(H_C, Wb, bb, pHC, NC, D, 256);
    gemm_bias_kernel<<<dim3(4, 32), 256>>>(H_G, Wg, bg, pTok + (size_t)(1 + NS) * D, NG, D, 64);

    // Q/K/V (fp16 outputs for tensor-core attention)
    gemm_h_kernel<<<dim3(4, 32), 256>>>(pHS, WQ, pQh, NS, D, 256);
    gemm_h_kernel<<<dim3(4, 64), 256>>>(pHC, WK, pKh, NC, D, 256);
    gemm_h_kernel<<<dim3(4, 64), 256>>>(pHC, WV, pVh, NC, D, 256);

    // fused gated cross attention (Z, Hnew, fp16 P) + attn_map
    ca_fused_kernel<<<dim3(NH, NS / 16), 256>>>(G_glyph);
    attn_map_kernel<<<dim3(NC / 512, NS), 256>>>(attn_map);

    // O projection + residual LN -> tokens
    gemm_bias_kernel<<<dim3(4, 32), 256>>>(pHnew, WO, bO, pTmp, NS, D, 256);
    ln_ca_kernel<<<NS / 8, 256>>>(ln_ca_g, ln_ca_b, fusion);

    // self-attn K/V over tokens
    gemm_bias_kernel<<<dim3(4, 65), 256>>>(pTok, mha_in_w + 256 * 256, mha_in_b + 256, pk2, TT, D, 256);
    gemm_bias_kernel<<<dim3(4, 65), 256>>>(pTok, mha_in_w + 512 * 256, mha_in_b + 512, pv2, TT, D, 256);

    // token-0 attention + head
    q0_kernel<<<1, 256>>>(fusion, mha_in_w, mha_in_b);
    score0_kernel<<<32, 256>>>();
    av0_kernel<<<16, 256>>>();
    final_kernel<<<1, 256>>>(fusion, mha_out_w, mha_out_b, ln1_g, ln1_b,
                             ffn_w1, ffn_b1, ffn_w2, ffn_b2, ln2_g, ln2_b, z_fused);
}

// round 5
// speedup vs baseline: 1.7915x; 1.1055x over previous
#include <cuda_runtime.h>
#include <cuda_fp16.h>

#define NS 2048
#define NC 4096
#define NG 2048
#define D  256
#define NH 8
#define TT 4097   // 1 + NS + NG

// ---------------- device scratch (static globals; no runtime alloc) ----------------
__device__ float  g_HS[NS * D];
__device__ float  g_HC[NC * D];
__device__ __half g_Qh[NS * D];
__device__ __half g_Kh[NC * D];
__device__ __half g_Vh[NC * D];
__device__ __half g_P16[(size_t)NS * NH * NC];   // 128MB un-normalized exp scores
__device__ float  g_Z[NS * NH];                  // softmax denominators
__device__ float  g_Hnew[NS * D];                // normalized attn @ V
__device__ float  g_tmp[NS * D];                 // O-proj output
__device__ float  g_tok[TT * D];                 // [fusion; HSu; HG]
__device__ float  g_k2[TT * D];
__device__ float  g_v2[TT * D];
__device__ float  g_q0[D];
__device__ float  g_p0[TT * NH];
__device__ float  g_Z0[NH];
__device__ float  g_a0[D];

__device__ __forceinline__ float warpSum(float v) {
#pragma unroll
    for (int o = 16; o; o >>= 1) v += __shfl_xor_sync(0xffffffffu, v, o);
    return v;
}

__device__ __forceinline__ void mma16816(float* c, const unsigned* a, const unsigned* b) {
    asm volatile(
        "mma.sync.aligned.m16n8k16.row.col.f32.f16.f16.f32 "
        "{%0,%1,%2,%3}, {%4,%5,%6,%7}, {%8,%9}, {%0,%1,%2,%3};\n"
        : "+f"(c[0]), "+f"(c[1]), "+f"(c[2]), "+f"(c[3])
        : "r"(a[0]), "r"(a[1]), "r"(a[2]), "r"(a[3]), "r"(b[0]), "r"(b[1]));
}

__device__ __forceinline__ void mma1688_tf32(float* c, const unsigned* a, const unsigned* b) {
    asm volatile(
        "mma.sync.aligned.m16n8k8.row.col.f32.tf32.tf32.f32 "
        "{%0,%1,%2,%3}, {%4,%5,%6,%7}, {%8,%9}, {%0,%1,%2,%3};\n"
        : "+f"(c[0]), "+f"(c[1]), "+f"(c[2]), "+f"(c[3])
        : "r"(a[0]), "r"(a[1]), "r"(a[2]), "r"(a[3]), "r"(b[0]), "r"(b[1]));
}

__device__ __forceinline__ unsigned f2tf32(float x) {
    unsigned u;
    asm("cvt.rna.tf32.f32 %0, %1;" : "=r"(u) : "f"(x));
    return u;
}

__device__ __forceinline__ unsigned smaddr(const void* p) {
    return (unsigned)__cvta_generic_to_shared(p);
}
__device__ __forceinline__ void ldm_x2(unsigned& r0, unsigned& r1, unsigned a) {
    asm volatile("ldmatrix.sync.aligned.m8n8.x2.shared.b16 {%0,%1}, [%2];"
                 : "=r"(r0), "=r"(r1) : "r"(a));
}
__device__ __forceinline__ void ldm_x2_t(unsigned& r0, unsigned& r1, unsigned a) {
    asm volatile("ldmatrix.sync.aligned.m8n8.x2.trans.shared.b16 {%0,%1}, [%2];"
                 : "=r"(r0), "=r"(r1) : "r"(a));
}
__device__ __forceinline__ void ldm_x4(unsigned* r, unsigned a) {
    asm volatile("ldmatrix.sync.aligned.m8n8.x4.shared.b16 {%0,%1,%2,%3}, [%4];"
                 : "=r"(r[0]), "=r"(r[1]), "=r"(r[2]), "=r"(r[3]) : "r"(a));
}
__device__ __forceinline__ void cpa16(void* smem, const void* gmem) {
    asm volatile("cp.async.cg.shared.global [%0], [%1], 16;"
                 :: "r"(smaddr(smem)), "l"(gmem));
}

// ---------------- zero accumulators ----------------
__global__ void zero_kernel() {
    int i = blockIdx.x * blockDim.x + threadIdx.x;
    if (i < NH) g_Z0[i] = 0.f;
    if (i < D) g_a0[i] = 0.f;
}

// ---------------- tf32 tensor-core GEMM: C[m,n] = sum_k A[m,k]*W[n,k] + bias[n] ----------------
// tile 64x64, 8 warps (4x2), warp tile 16x32. K % 32 == 0, N % 64 == 0. M guarded.
template<bool HALF_OUT>
__global__ __launch_bounds__(256) void gemm_tf32_kernel(
    const float* __restrict__ A, const float* __restrict__ W,
    const float* __restrict__ bias,
    float* __restrict__ Cf, __half* __restrict__ Ch,
    int M, int N, int K)
{
    __shared__ unsigned As[64][33];
    __shared__ unsigned Bs[64][33];
    const int bm = blockIdx.y * 64, bn = blockIdx.x * 64;
    const int tid = threadIdx.x;
    const int w = tid >> 5, lane = tid & 31;
    const int wr = w >> 1, wc = w & 1;      // warp grid 4x2
    const int gr = lane >> 2, cc = lane & 3;

    float acc[4][4] = {};

    const int nChunks = K >> 5;
    for (int ch = 0; ch < nChunks; ch++) {
        int k0 = ch << 5;
        __syncthreads();
#pragma unroll
        for (int t = 0; t < 2; t++) {
            int linear = t * 256 + tid;     // 0..511
            int r = linear >> 3;
            int c4 = (linear & 7) * 4;
            float4 av = make_float4(0.f, 0.f, 0.f, 0.f);
            if (bm + r < M)
                av = *(const float4*)&A[(size_t)(bm + r) * K + k0 + c4];
            As[r][c4 + 0] = f2tf32(av.x);
            As[r][c4 + 1] = f2tf32(av.y);
            As[r][c4 + 2] = f2tf32(av.z);
            As[r][c4 + 3] = f2tf32(av.w);
            float4 bv = *(const float4*)&W[(size_t)(bn + r) * K + k0 + c4];
            Bs[r][c4 + 0] = f2tf32(bv.x);
            Bs[r][c4 + 1] = f2tf32(bv.y);
            Bs[r][c4 + 2] = f2tf32(bv.z);
            Bs[r][c4 + 3] = f2tf32(bv.w);
        }
        __syncthreads();
#pragma unroll
        for (int k8 = 0; k8 < 4; k8++) {
            int kk = k8 * 8;
            unsigned a[4];
            a[0] = As[wr * 16 + gr][kk + cc];
            a[1] = As[wr * 16 + gr + 8][kk + cc];
            a[2] = As[wr * 16 + gr][kk + cc + 4];
            a[3] = As[wr * 16 + gr + 8][kk + cc + 4];
#pragma unroll
            for (int nt = 0; nt < 4; nt++) {
                unsigned b[2];
                b[0] = Bs[wc * 32 + nt * 8 + gr][kk + cc];
                b[1] = Bs[wc * 32 + nt * 8 + gr][kk + cc + 4];
                mma1688_tf32(acc[nt], a, b);
            }
        }
    }

    // epilogue
#pragma unroll
    for (int nt = 0; nt < 4; nt++) {
        int col = bn + wc * 32 + nt * 8 + 2 * cc;
        float b0 = bias ? bias[col] : 0.f;
        float b1 = bias ? bias[col + 1] : 0.f;
        int row0 = bm + wr * 16 + gr;
        int row1 = row0 + 8;
        if (row0 < M) {
            if (HALF_OUT) {
                Ch[(size_t)row0 * N + col]     = __float2half(acc[nt][0] + b0);
                Ch[(size_t)row0 * N + col + 1] = __float2half(acc[nt][1] + b1);
            } else {
                Cf[(size_t)row0 * N + col]     = acc[nt][0] + b0;
                Cf[(size_t)row0 * N + col + 1] = acc[nt][1] + b1;
            }
        }
        if (row1 < M) {
            if (HALF_OUT) {
                Ch[(size_t)row1 * N + col]     = __float2half(acc[nt][2] + b0);
                Ch[(size_t)row1 * N + col + 1] = __float2half(acc[nt][3] + b1);
            } else {
                Cf[(size_t)row1 * N + col]     = acc[nt][2] + b0;
                Cf[(size_t)row1 * N + col + 1] = acc[nt][3] + b1;
            }
        }
    }
}

// ---------------- fused gated cross-attention (flash-style, HMMA + ldmatrix + cp.async) ----------------
// grid = (NH, NS/16). Per block: one head, 16 s-rows, c loop with double-buffered tiles.
// dynamic smem layout (bytes):
//   Ks: 2 * 256*40*2 = 40960
//   Vs: 2 * 256*40*2 = 40960   @40960
//   Qs: 16*40*2      = 1280    @81920
//   Hs: 512*4        = 2048    @83200
//   Zs: 16*4         = 64      @85248
#define CA_SMEM 85312
__global__ __launch_bounds__(256) void ca_fused_kernel(const float* __restrict__ G)
{
    extern __shared__ __align__(16) char smraw[];
    __half* Ks = (__half*)smraw;
    __half* Vs = (__half*)(smraw + 40960);
    __half* Qs = (__half*)(smraw + 81920);
    float*  Hs = (float*)(smraw + 83200);
    float*  Zs = (float*)(smraw + 85248);

    const int h = blockIdx.x;
    const int s0 = blockIdx.y * 16;
    const int tid = threadIdx.x;
    const int w = tid >> 5, lane = tid & 31;
    const int gr = lane >> 2, cc = lane & 3;
    const int cw = w * 32;
    const int l4 = lane & 15;
    const float isq = 0.17677669529663687f;

    auto issue_tile = [&](int ci) {
        int buf = (ci & 1) * 10240;
        int c0 = ci * 256;
        int pr = tid >> 2, pp = tid & 3;
#pragma unroll
        for (int rr = 0; rr < 4; rr++) {
            int row = rr * 64 + pr;
            size_t src = (size_t)(c0 + row) * D + h * 32 + pp * 8;
            cpa16(&Ks[buf + row * 40 + pp * 8], &g_Kh[src]);
            cpa16(&Vs[buf + row * 40 + pp * 8], &g_Vh[src]);
        }
        asm volatile("cp.async.commit_group;");
    };

    // load Q tile (16 x 32 halves)
    {
        int row = tid >> 4, c2 = (tid & 15) * 2;
        *(unsigned*)&Qs[row * 40 + c2] =
            *(const unsigned*)&g_Qh[(size_t)(s0 + row) * D + h * 32 + c2];
    }
    Hs[tid] = 0.f;
    Hs[tid + 256] = 0.f;
    if (tid < 16) Zs[tid] = 0.f;

    issue_tile(0);
    __syncthreads();

    // Q A-fragments via ldmatrix.x4 (2 k-steps of 16)
    unsigned qa[2][4];
    {
        int qrow = lane & 15;
        int qcol = (lane >> 4) * 8;
#pragma unroll
        for (int ks = 0; ks < 2; ks++)
            ldm_x4(qa[ks], smaddr(&Qs[qrow * 40 + ks * 16 + qcol]));
    }

    float hacc[4][4] = {};
    float zacc0 = 0.f, zacc1 = 0.f;

    for (int ci = 0; ci < 16; ci++) {
        int c0 = ci * 256;
        int buf = (ci & 1) * 10240;
        if (ci < 15) issue_tile(ci + 1);

        // prefetch gate values for this tile into registers
        float2 gA[4], gB[4];
#pragma unroll
        for (int nt = 0; nt < 4; nt++) {
            int gcol = c0 + cw + nt * 8 + 2 * cc;
            gA[nt] = __ldg((const float2*)&G[(size_t)(s0 + gr) * NC + gcol]);
            gB[nt] = __ldg((const float2*)&G[(size_t)(s0 + gr + 8) * NC + gcol]);
        }

        if (ci < 15) asm volatile("cp.async.wait_group 1;" ::: "memory");
        else         asm volatile("cp.async.wait_group 0;" ::: "memory");
        __syncthreads();

        unsigned pa[2][4];   // P A-fragments for the PV mma
#pragma unroll
        for (int nt = 0; nt < 4; nt++) {
            float S[4] = {0.f, 0.f, 0.f, 0.f};
#pragma unroll
            for (int ks = 0; ks < 2; ks++) {
                unsigned b[2];
                ldm_x2(b[0], b[1],
                       smaddr(&Ks[buf + (cw + nt * 8 + (l4 & 7)) * 40 + ks * 16 + (l4 >> 3) * 8]));
                mma16816(S, qa[ks], b);
            }
            // epilogue: gate, exp, Z, fp16 P store
            int gcol = c0 + cw + nt * 8 + 2 * cc;
            float p0 = __expf(S[0] * isq * gA[nt].x);
            float p1 = __expf(S[1] * isq * gA[nt].y);
            float p2 = __expf(S[2] * isq * gB[nt].x);
            float p3 = __expf(S[3] * isq * gB[nt].y);
            zacc0 += p0 + p1;
            zacc1 += p2 + p3;
            __half2 h01 = __floats2half2_rn(p0, p1);
            __half2 h23 = __floats2half2_rn(p2, p3);
            *(__half2*)&g_P16[((size_t)(s0 + gr) * NH + h) * NC + gcol] = h01;
            *(__half2*)&g_P16[((size_t)(s0 + gr + 8) * NH + h) * NC + gcol] = h23;
            unsigned u01 = *(unsigned*)&h01, u23 = *(unsigned*)&h23;
            if ((nt & 1) == 0) { pa[nt >> 1][0] = u01; pa[nt >> 1][1] = u23; }
            else               { pa[nt >> 1][2] = u01; pa[nt >> 1][3] = u23; }
        }

        // P @ V  (accumulate across c) — B frags via ldmatrix.trans on row-major V
#pragma unroll
        for (int nt2 = 0; nt2 < 4; nt2++) {
#pragma unroll
            for (int ks2 = 0; ks2 < 2; ks2++) {
                unsigned b[2];
                ldm_x2_t(b[0], b[1],
                         smaddr(&Vs[buf + (cw + ks2 * 16 + l4) * 40 + nt2 * 8]));
                mma16816(hacc[nt2], pa[ks2], b);
            }
        }
        __syncthreads();
    }

    // Z: reduce over quad lanes, then shared atomics across warps
#pragma unroll
    for (int o = 1; o < 4; o <<= 1) {
        zacc0 += __shfl_xor_sync(0xffffffffu, zacc0, o);
        zacc1 += __shfl_xor_sync(0xffffffffu, zacc1, o);
    }
    if (cc == 0) {
        atomicAdd(&Zs[gr], zacc0);
        atomicAdd(&Zs[gr + 8], zacc1);
    }
    // Hnew partials across warps
#pragma unroll
    for (int nt2 = 0; nt2 < 4; nt2++) {
        atomicAdd(&Hs[gr * 32 + nt2 * 8 + 2 * cc],           hacc[nt2][0]);
        atomicAdd(&Hs[gr * 32 + nt2 * 8 + 2 * cc + 1],       hacc[nt2][1]);
        atomicAdd(&Hs[(gr + 8) * 32 + nt2 * 8 + 2 * cc],     hacc[nt2][2]);
        atomicAdd(&Hs[(gr + 8) * 32 + nt2 * 8 + 2 * cc + 1], hacc[nt2][3]);
    }
    __syncthreads();
    if (tid < 16) g_Z[(s0 + tid) * NH + h] = Zs[tid];
#pragma unroll
    for (int k = 0; k < 2; k++) {
        int idx = k * 256 + tid;
        int row = idx >> 5, d = idx & 31;
        g_Hnew[(size_t)(s0 + row) * D + h * 32 + d] = Hs[idx] / Zs[row];
    }
}

// ---------------- attn_map = mean_h P/Z ----------------
__global__ __launch_bounds__(256) void attn_map_kernel(float* __restrict__ AM)
{
    int s = blockIdx.y;
    int c = (blockIdx.x * 256 + threadIdx.x) * 2;
    float a0 = 0.f, a1 = 0.f;
#pragma unroll
    for (int h = 0; h < NH; h++) {
        float iz = 0.125f / g_Z[s * NH + h];
        __half2 p = *(const __half2*)&g_P16[((size_t)s * NH + h) * NC + c];
        float2 pf = __half22float2(p);
        a0 += pf.x * iz;
        a1 += pf.y * iz;
    }
    *(float2*)&AM[(size_t)s * NC + c] = make_float2(a0, a1);
}

// ---------------- cross-attn epilogue LN ----------------
__global__ __launch_bounds__(256) void ln_ca_kernel(
    const float* __restrict__ g, const float* __restrict__ b, const float* __restrict__ fusion)
{
    int tid = threadIdx.x;
    if (blockIdx.x == 0 && tid < D) g_tok[tid] = fusion[tid];
    int warp = tid >> 5, lane = tid & 31;
    int row = blockIdx.x * 8 + warp;
    float x[8];
    float s = 0.f;
#pragma unroll
    for (int j = 0; j < 8; j++) {
        int c = lane + 32 * j;
        x[j] = g_tmp[(size_t)row * D + c] + g_HS[(size_t)row * D + c];
        s += x[j];
    }
    s = warpSum(s);
    float m = s * (1.0f / D);
    float vs = 0.f;
#pragma unroll
    for (int j = 0; j < 8; j++) { float d = x[j] - m; vs += d * d; }
    vs = warpSum(vs);
    float r = rsqrtf(vs * (1.0f / D) + 1e-5f);
#pragma unroll
    for (int j = 0; j < 8; j++) {
        int c = lane + 32 * j;
        g_tok[(size_t)(1 + row) * D + c] = (x[j] - m) * r * g[c] + b[c];
    }
}

// ---------------- q0 = fusion @ Wq.T + bq ----------------
__global__ void q0_kernel(const float* __restrict__ fusion,
                          const float* __restrict__ w, const float* __restrict__ bqkv)
{
    __shared__ float fs[D];
    int tid = threadIdx.x;
    fs[tid] = fusion[tid];
    __syncthreads();
    float a = bqkv[tid];
    for (int c = 0; c < D; c++) a += fs[c] * w[(size_t)tid * D + c];
    g_q0[tid] = a;
}

// ---------------- row-0 scores over tokens ----------------
__global__ __launch_bounds__(256) void score0_kernel()
{
    __shared__ float q0s[D];
    __shared__ float zpart[NH];
    int tid = threadIdx.x;
    if (tid < D) q0s[tid] = g_q0[tid];
    if (tid < NH) zpart[tid] = 0.f;
    __syncthreads();
    int warp = tid >> 5, lane = tid & 31;
    int wtotal = gridDim.x * 8;
    const float isq = 0.17677669529663687f;
    for (int u = blockIdx.x * 8 + warp; u < TT; u += wtotal) {
        float mine = 0.f;
#pragma unroll
        for (int j = 0; j < 8; j++) {
            int c = lane + 32 * j;
            float v = q0s[c] * g_k2[(size_t)u * D + c];
            v = warpSum(v);
            if (lane == j) mine = v;
        }
        if (lane < 8) {
            float p = __expf(mine * isq);
            g_p0[u * NH + lane] = p;
            atomicAdd(&zpart[lane], p);
        }
    }
    __syncthreads();
    if (tid < NH) atomicAdd(&g_Z0[tid], zpart[tid]);
}

// ---------------- row-0 AV ----------------
__global__ __launch_bounds__(256) void av0_kernel()
{
    int col = threadIdx.x;
    int h = col >> 5;
    int u0 = blockIdx.x * 257;
    int u1 = u0 + 257; if (u1 > TT) u1 = TT;
    float acc = 0.f;
    for (int u = u0; u < u1; u++)
        acc += g_p0[u * NH + h] * g_v2[(size_t)u * D + col];
    atomicAdd(&g_a0[col], acc);
}

// ---------------- final head ----------------
__device__ __forceinline__ float blockSum256(float v, volatile float* red) {
    int lane = threadIdx.x & 31, w = threadIdx.x >> 5;
    v = warpSum(v);
    __syncthreads();
    if (lane == 0) red[w] = v;
    __syncthreads();
    float s = 0.f;
#pragma unroll
    for (int i = 0; i < 8; i++) s += red[i];
    return s;
}

__global__ __launch_bounds__(256) void final_kernel(
    const float* __restrict__ fusion,
    const float* __restrict__ mow, const float* __restrict__ mob,
    const float* __restrict__ ln1g, const float* __restrict__ ln1b,
    const float* __restrict__ w1, const float* __restrict__ b1,
    const float* __restrict__ w2, const float* __restrict__ b2,
    const float* __restrict__ ln2g, const float* __restrict__ ln2b,
    float* __restrict__ out)
{
    __shared__ float a0[D], t1[D], h1[2 * D];
    __shared__ float red[8];
    int tid = threadIdx.x;
    a0[tid] = g_a0[tid] / g_Z0[tid >> 5];
    __syncthreads();
    float y = mob[tid];
    for (int j = 0; j < D; j++) y += a0[j] * mow[(size_t)tid * D + j];
    float tv = fusion[tid] + y;
    float m = blockSum256(tv, red) * (1.0f / D);
    float d = tv - m;
    float var = blockSum256(d * d, red) * (1.0f / D);
    float t = d * rsqrtf(var + 1e-5f) * ln1g[tid] + ln1b[tid];
    t1[tid] = t;
    __syncthreads();
    float hh[2];
#pragma unroll
    for (int r2 = 0; r2 < 2; r2++) {
        int jj = tid + r2 * 256;
        float a = b1[jj];
        for (int c = 0; c < D; c++) a += t1[c] * w1[(size_t)jj * D + c];
        hh[r2] = a * 0.5f * (1.f + erff(a * 0.70710678118654752f));
    }
    h1[tid] = hh[0];
    h1[tid + 256] = hh[1];
    __syncthreads();
    float o = b2[tid];
    for (int j = 0; j < 512; j++) o += h1[j] * w2[(size_t)tid * 512 + j];
    float t2v = t1[tid] + o;   // residual = LN1 output
    float m2 = blockSum256(t2v, red) * (1.0f / D);
    float d2 = t2v - m2;
    float v2 = blockSum256(d2 * d2, red) * (1.0f / D);
    out[tid] = d2 * rsqrtf(v2 + 1e-5f) * ln2g[tid] + ln2b[tid];
}

// ---------------- launcher ----------------
extern "C" void kernel_launch(void* const* d_in, const int* in_sizes, int n_in,
                              void* d_out, int out_size)
{
    const float* H_S     = (const float*)d_in[0];
    const float* H_C     = (const float*)d_in[1];
    const float* H_G     = (const float*)d_in[2];
    const float* G_glyph = (const float*)d_in[3];
    const float* Ws      = (const float*)d_in[4];
    const float* bs      = (const float*)d_in[5];
    const float* Wb      = (const float*)d_in[6];
    const float* bb      = (const float*)d_in[7];
    const float* Wg      = (const float*)d_in[8];
    const float* bg      = (const float*)d_in[9];
    const float* WQ      = (const float*)d_in[10];
    const float* WK      = (const float*)d_in[11];
    const float* WV      = (const float*)d_in[12];
    const float* WO      = (const float*)d_in[13];
    const float* bO      = (const float*)d_in[14];
    const float* ln_ca_g = (const float*)d_in[15];
    const float* ln_ca_b = (const float*)d_in[16];
    const float* fusion  = (const float*)d_in[17];
    const float* mha_in_w  = (const float*)d_in[18];
    const float* mha_in_b  = (const float*)d_in[19];
    const float* mha_out_w = (const float*)d_in[20];
    const float* mha_out_b = (const float*)d_in[21];
    const float* ln1_g   = (const float*)d_in[22];
    const float* ln1_b   = (const float*)d_in[23];
    const float* ln2_g   = (const float*)d_in[24];
    const float* ln2_b   = (const float*)d_in[25];
    const float* ffn_w1  = (const float*)d_in[26];
    const float* ffn_b1  = (const float*)d_in[27];
    const float* ffn_w2  = (const float*)d_in[28];
    const float* ffn_b2  = (const float*)d_in[29];

    float* out = (float*)d_out;
    float* z_fused  = out;        // 256
    float* attn_map = out + D;    // 2048 * 4096

    float *pHS, *pHC, *pHnew, *pTmp, *pTok, *pk2, *pv2;
    __half *pQh, *pKh, *pVh;
    cudaGetSymbolAddress((void**)&pHS,  g_HS);
    cudaGetSymbolAddress((void**)&pHC,  g_HC);
    cudaGetSymbolAddress((void**)&pQh,  g_Qh);
    cudaGetSymbolAddress((void**)&pKh,  g_Kh);
    cudaGetSymbolAddress((void**)&pVh,  g_Vh);
    cudaGetSymbolAddress((void**)&pHnew,g_Hnew);
    cudaGetSymbolAddress((void**)&pTmp, g_tmp);
    cudaGetSymbolAddress((void**)&pTok, g_tok);
    cudaGetSymbolAddress((void**)&pk2,  g_k2);
    cudaGetSymbolAddress((void**)&pv2,  g_v2);

    static bool attrSet = false;
    if (!attrSet) {
        cudaFuncSetAttribute(ca_fused_kernel,
                             cudaFuncAttributeMaxDynamicSharedMemorySize, CA_SMEM);
        attrSet = true;
    }

    zero_kernel<<<1, 256>>>();

    // input projections (tf32 tensor cores)
    gemm_tf32_kernel<false><<<dim3(4, 32), 256>>>(H_S, Ws, bs, pHS, nullptr, NS, D, 128);
    gemm_tf32_kernel<false><<<dim3(4, 64), 256>>>(H_C, Wb, bb, pHC, nullptr, NC, D, 256);
    gemm_tf32_kernel<false><<<dim3(4, 32), 256>>>(H_G, Wg, bg, pTok + (size_t)(1 + NS) * D, nullptr, NG, D, 64);

    // Q/K/V (fp16 outputs for tensor-core attention)
    gemm_tf32_kernel<true><<<dim3(4, 32), 256>>>(pHS, WQ, nullptr, nullptr, pQh, NS, D, 256);
    gemm_tf32_kernel<true><<<dim3(4, 64), 256>>>(pHC, WK, nullptr, nullptr, pKh, NC, D, 256);
    gemm_tf32_kernel<true><<<dim3(4, 64), 256>>>(pHC, WV, nullptr, nullptr, pVh, NC, D, 256);

    // fused gated cross attention (Z, Hnew, fp16 P) + attn_map
    ca_fused_kernel<<<dim3(NH, NS / 16), 256, CA_SMEM>>>(G_glyph);
    attn_map_kernel<<<dim3(NC / 512, NS), 256>>>(attn_map);

    // O projection + residual LN -> tokens
    gemm_tf32_kernel<false><<<dim3(4, 32), 256>>>(pHnew, WO, bO, pTmp, nullptr, NS, D, 256);
    ln_ca_kernel<<<NS / 8, 256>>>(ln_ca_g, ln_ca_b, fusion);

    // self-attn K/V over tokens
    gemm_tf32_kernel<false><<<dim3(4, 65), 256>>>(pTok, mha_in_w + 256 * 256, mha_in_b + 256, pk2, nullptr, TT, D, 256);
    gemm_tf32_kernel<false><<<dim3(4, 65), 256>>>(pTok, mha_in_w + 512 * 256, mha_in_b + 512, pv2, nullptr, TT, D, 256);

    // token-0 attention + head
    q0_kernel<<<1, 256>>>(fusion, mha_in_w, mha_in_b);
    score0_kernel<<<32, 256>>>();
    av0_kernel<<<16, 256>>>();
    final_kernel<<<1, 256>>>(fusion, mha_out_w, mha_out_b, ln1_g, ln1_b,
                             ffn_w1, ffn_b1, ffn_w2, ffn_b2, ln2_g, ln2_b, z_fused);
}

// round 6
// speedup vs baseline: 1.9678x; 1.0984x over previous
#include <cuda_runtime.h>
#include <cuda_fp16.h>

#define NS 2048
#define NC 4096
#define NG 2048
#define D  256
#define NH 8
#define TT 4097   // 1 + NS + NG

// ---------------- device scratch (static globals; no runtime alloc) ----------------
__device__ float  g_HS[NS * D];
__device__ float  g_HC[NC * D];
__device__ __half g_Qh[NS * D];
__device__ __half g_Kh[NC * D];
__device__ __half g_Vh[NC * D];
__device__ float  g_Z[NS * NH];                  // softmax denominators
__device__ float  g_Hnew[NS * D];                // normalized attn @ V
__device__ float  g_tmp[NS * D];                 // O-proj output
__device__ float  g_tok[TT * D];                 // [fusion; HSu; HG]
__device__ float  g_k2[TT * D];
__device__ float  g_v2[TT * D];
__device__ float  g_q0[D];
__device__ float  g_p0[TT * NH];
__device__ float  g_Z0[NH];
__device__ float  g_a0[D];

__device__ __forceinline__ float warpSum(float v) {
#pragma unroll
    for (int o = 16; o; o >>= 1) v += __shfl_xor_sync(0xffffffffu, v, o);
    return v;
}

__device__ __forceinline__ void mma16816(float* c, const unsigned* a, const unsigned* b) {
    asm volatile(
        "mma.sync.aligned.m16n8k16.row.col.f32.f16.f16.f32 "
        "{%0,%1,%2,%3}, {%4,%5,%6,%7}, {%8,%9}, {%0,%1,%2,%3};\n"
        : "+f"(c[0]), "+f"(c[1]), "+f"(c[2]), "+f"(c[3])
        : "r"(a[0]), "r"(a[1]), "r"(a[2]), "r"(a[3]), "r"(b[0]), "r"(b[1]));
}

__device__ __forceinline__ void mma1688_tf32(float* c, const unsigned* a, const unsigned* b) {
    asm volatile(
        "mma.sync.aligned.m16n8k8.row.col.f32.tf32.tf32.f32 "
        "{%0,%1,%2,%3}, {%4,%5,%6,%7}, {%8,%9}, {%0,%1,%2,%3};\n"
        : "+f"(c[0]), "+f"(c[1]), "+f"(c[2]), "+f"(c[3])
        : "r"(a[0]), "r"(a[1]), "r"(a[2]), "r"(a[3]), "r"(b[0]), "r"(b[1]));
}

__device__ __forceinline__ unsigned f2tf32(float x) {
    unsigned u;
    asm("cvt.rna.tf32.f32 %0, %1;" : "=r"(u) : "f"(x));
    return u;
}

__device__ __forceinline__ unsigned smaddr(const void* p) {
    return (unsigned)__cvta_generic_to_shared(p);
}
__device__ __forceinline__ void ldm_x2(unsigned& r0, unsigned& r1, unsigned a) {
    asm volatile("ldmatrix.sync.aligned.m8n8.x2.shared.b16 {%0,%1}, [%2];"
                 : "=r"(r0), "=r"(r1) : "r"(a));
}
__device__ __forceinline__ void ldm_x2_t(unsigned& r0, unsigned& r1, unsigned a) {
    asm volatile("ldmatrix.sync.aligned.m8n8.x2.trans.shared.b16 {%0,%1}, [%2];"
                 : "=r"(r0), "=r"(r1) : "r"(a));
}
__device__ __forceinline__ void ldm_x4(unsigned* r, unsigned a) {
    asm volatile("ldmatrix.sync.aligned.m8n8.x4.shared.b16 {%0,%1,%2,%3}, [%4];"
                 : "=r"(r[0]), "=r"(r[1]), "=r"(r[2]), "=r"(r[3]) : "r"(a));
}
__device__ __forceinline__ void cpa16(void* smem, const void* gmem) {
    asm volatile("cp.async.cg.shared.global [%0], [%1], 16;"
                 :: "r"(smaddr(smem)), "l"(gmem));
}

// ---------------- zero accumulators ----------------
__global__ void zero_kernel() {
    int i = blockIdx.x * blockDim.x + threadIdx.x;
    if (i < NH) g_Z0[i] = 0.f;
    if (i < D) g_a0[i] = 0.f;
}

// ---------------- tf32 tensor-core GEMM (optionally dual via blockIdx.z) ----------------
// C[m,n] = sum_k A[m,k]*W[n,k] + bias[n]; tile 64x64, 8 warps. K%32==0, N%64==0, M guarded.
template<bool HALF_OUT>
__global__ __launch_bounds__(256) void gemm_tf32_kernel(
    const float* __restrict__ A,
    const float* __restrict__ W0, const float* __restrict__ bias0,
    float* __restrict__ Cf0, __half* __restrict__ Ch0,
    const float* __restrict__ W1, const float* __restrict__ bias1,
    float* __restrict__ Cf1, __half* __restrict__ Ch1,
    int M, int N, int K)
{
    const float* W   = blockIdx.z ? W1 : W0;
    const float* bias= blockIdx.z ? bias1 : bias0;
    float* Cf        = blockIdx.z ? Cf1 : Cf0;
    __half* Ch       = blockIdx.z ? Ch1 : Ch0;

    __shared__ unsigned As[64][33];
    __shared__ unsigned Bs[64][33];
    const int bm = blockIdx.y * 64, bn = blockIdx.x * 64;
    const int tid = threadIdx.x;
    const int w = tid >> 5, lane = tid & 31;
    const int wr = w >> 1, wc = w & 1;
    const int gr = lane >> 2, cc = lane & 3;

    float acc[4][4] = {};

    const int nChunks = K >> 5;
    for (int ch = 0; ch < nChunks; ch++) {
        int k0 = ch << 5;
        __syncthreads();
#pragma unroll
        for (int t = 0; t < 2; t++) {
            int linear = t * 256 + tid;
            int r = linear >> 3;
            int c4 = (linear & 7) * 4;
            float4 av = make_float4(0.f, 0.f, 0.f, 0.f);
            if (bm + r < M)
                av = *(const float4*)&A[(size_t)(bm + r) * K + k0 + c4];
            As[r][c4 + 0] = f2tf32(av.x);
            As[r][c4 + 1] = f2tf32(av.y);
            As[r][c4 + 2] = f2tf32(av.z);
            As[r][c4 + 3] = f2tf32(av.w);
            float4 bv = *(const float4*)&W[(size_t)(bn + r) * K + k0 + c4];
            Bs[r][c4 + 0] = f2tf32(bv.x);
            Bs[r][c4 + 1] = f2tf32(bv.y);
            Bs[r][c4 + 2] = f2tf32(bv.z);
            Bs[r][c4 + 3] = f2tf32(bv.w);
        }
        __syncthreads();
#pragma unroll
        for (int k8 = 0; k8 < 4; k8++) {
            int kk = k8 * 8;
            unsigned a[4];
            a[0] = As[wr * 16 + gr][kk + cc];
            a[1] = As[wr * 16 + gr + 8][kk + cc];
            a[2] = As[wr * 16 + gr][kk + cc + 4];
            a[3] = As[wr * 16 + gr + 8][kk + cc + 4];
#pragma unroll
            for (int nt = 0; nt < 4; nt++) {
                unsigned b[2];
                b[0] = Bs[wc * 32 + nt * 8 + gr][kk + cc];
                b[1] = Bs[wc * 32 + nt * 8 + gr][kk + cc + 4];
                mma1688_tf32(acc[nt], a, b);
            }
        }
    }

#pragma unroll
    for (int nt = 0; nt < 4; nt++) {
        int col = bn + wc * 32 + nt * 8 + 2 * cc;
        float b0 = bias ? bias[col] : 0.f;
        float b1 = bias ? bias[col + 1] : 0.f;
        int row0 = bm + wr * 16 + gr;
        int row1 = row0 + 8;
        if (row0 < M) {
            if (HALF_OUT) {
                Ch[(size_t)row0 * N + col]     = __float2half(acc[nt][0] + b0);
                Ch[(size_t)row0 * N + col + 1] = __float2half(acc[nt][1] + b1);
            } else {
                Cf[(size_t)row0 * N + col]     = acc[nt][0] + b0;
                Cf[(size_t)row0 * N + col + 1] = acc[nt][1] + b1;
            }
        }
        if (row1 < M) {
            if (HALF_OUT) {
                Ch[(size_t)row1 * N + col]     = __float2half(acc[nt][2] + b0);
                Ch[(size_t)row1 * N + col + 1] = __float2half(acc[nt][3] + b1);
            } else {
                Cf[(size_t)row1 * N + col]     = acc[nt][2] + b0;
                Cf[(size_t)row1 * N + col + 1] = acc[nt][3] + b1;
            }
        }
    }
}

// ---------------- fused gated cross-attention: Z + softmax@V only (no P store) ----------------
// grid = (NH, NS/16). smem: Ks 2x10240h, Vs 2x10240h, Qs 640h, Hs 512f, Zs 16f
#define CA_SMEM 85312
__global__ __launch_bounds__(256) void ca_fused_kernel(const float* __restrict__ G)
{
    extern __shared__ __align__(16) char smraw[];
    __half* Ks = (__half*)smraw;
    __half* Vs = (__half*)(smraw + 40960);
    __half* Qs = (__half*)(smraw + 81920);
    float*  Hs = (float*)(smraw + 83200);
    float*  Zs = (float*)(smraw + 85248);

    const int h = blockIdx.x;
    const int s0 = blockIdx.y * 16;
    const int tid = threadIdx.x;
    const int w = tid >> 5, lane = tid & 31;
    const int gr = lane >> 2, cc = lane & 3;
    const int cw = w * 32;
    const int l4 = lane & 15;
    const float isq = 0.17677669529663687f;

    auto issue_tile = [&](int ci) {
        int buf = (ci & 1) * 10240;
        int c0 = ci * 256;
        int pr = tid >> 2, pp = tid & 3;
#pragma unroll
        for (int rr = 0; rr < 4; rr++) {
            int row = rr * 64 + pr;
            size_t src = (size_t)(c0 + row) * D + h * 32 + pp * 8;
            cpa16(&Ks[buf + row * 40 + pp * 8], &g_Kh[src]);
            cpa16(&Vs[buf + row * 40 + pp * 8], &g_Vh[src]);
        }
        asm volatile("cp.async.commit_group;");
    };

    {
        int row = tid >> 4, c2 = (tid & 15) * 2;
        *(unsigned*)&Qs[row * 40 + c2] =
            *(const unsigned*)&g_Qh[(size_t)(s0 + row) * D + h * 32 + c2];
    }
    Hs[tid] = 0.f;
    Hs[tid + 256] = 0.f;
    if (tid < 16) Zs[tid] = 0.f;

    issue_tile(0);
    __syncthreads();

    unsigned qa[2][4];
    {
        int qrow = lane & 15;
        int qcol = (lane >> 4) * 8;
#pragma unroll
        for (int ks = 0; ks < 2; ks++)
            ldm_x4(qa[ks], smaddr(&Qs[qrow * 40 + ks * 16 + qcol]));
    }

    float hacc[4][4] = {};
    float zacc0 = 0.f, zacc1 = 0.f;

    for (int ci = 0; ci < 16; ci++) {
        int c0 = ci * 256;
        int buf = (ci & 1) * 10240;
        if (ci < 15) issue_tile(ci + 1);

        float2 gA[4], gB[4];
#pragma unroll
        for (int nt = 0; nt < 4; nt++) {
            int gcol = c0 + cw + nt * 8 + 2 * cc;
            gA[nt] = __ldg((const float2*)&G[(size_t)(s0 + gr) * NC + gcol]);
            gB[nt] = __ldg((const float2*)&G[(size_t)(s0 + gr + 8) * NC + gcol]);
        }

        if (ci < 15) asm volatile("cp.async.wait_group 1;" ::: "memory");
        else         asm volatile("cp.async.wait_group 0;" ::: "memory");
        __syncthreads();

        unsigned pa[2][4];
#pragma unroll
        for (int nt = 0; nt < 4; nt++) {
            float S[4] = {0.f, 0.f, 0.f, 0.f};
#pragma unroll
            for (int ks = 0; ks < 2; ks++) {
                unsigned b[2];
                ldm_x2(b[0], b[1],
                       smaddr(&Ks[buf + (cw + nt * 8 + (l4 & 7)) * 40 + ks * 16 + (l4 >> 3) * 8]));
                mma16816(S, qa[ks], b);
            }
            float p0 = __expf(S[0] * isq * gA[nt].x);
            float p1 = __expf(S[1] * isq * gA[nt].y);
            float p2 = __expf(S[2] * isq * gB[nt].x);
            float p3 = __expf(S[3] * isq * gB[nt].y);
            zacc0 += p0 + p1;
            zacc1 += p2 + p3;
            __half2 h01 = __floats2half2_rn(p0, p1);
            __half2 h23 = __floats2half2_rn(p2, p3);
            unsigned u01 = *(unsigned*)&h01, u23 = *(unsigned*)&h23;
            if ((nt & 1) == 0) { pa[nt >> 1][0] = u01; pa[nt >> 1][1] = u23; }
            else               { pa[nt >> 1][2] = u01; pa[nt >> 1][3] = u23; }
        }

#pragma unroll
        for (int nt2 = 0; nt2 < 4; nt2++) {
#pragma unroll
            for (int ks2 = 0; ks2 < 2; ks2++) {
                unsigned b[2];
                ldm_x2_t(b[0], b[1],
                         smaddr(&Vs[buf + (cw + ks2 * 16 + l4) * 40 + nt2 * 8]));
                mma16816(hacc[nt2], pa[ks2], b);
            }
        }
        __syncthreads();
    }

#pragma unroll
    for (int o = 1; o < 4; o <<= 1) {
        zacc0 += __shfl_xor_sync(0xffffffffu, zacc0, o);
        zacc1 += __shfl_xor_sync(0xffffffffu, zacc1, o);
    }
    if (cc == 0) {
        atomicAdd(&Zs[gr], zacc0);
        atomicAdd(&Zs[gr + 8], zacc1);
    }
#pragma unroll
    for (int nt2 = 0; nt2 < 4; nt2++) {
        atomicAdd(&Hs[gr * 32 + nt2 * 8 + 2 * cc],           hacc[nt2][0]);
        atomicAdd(&Hs[gr * 32 + nt2 * 8 + 2 * cc + 1],       hacc[nt2][1]);
        atomicAdd(&Hs[(gr + 8) * 32 + nt2 * 8 + 2 * cc],     hacc[nt2][2]);
        atomicAdd(&Hs[(gr + 8) * 32 + nt2 * 8 + 2 * cc + 1], hacc[nt2][3]);
    }
    __syncthreads();
    if (tid < 16) g_Z[(s0 + tid) * NH + h] = Zs[tid];
#pragma unroll
    for (int k = 0; k < 2; k++) {
        int idx = k * 256 + tid;
        int row = idx >> 5, d = idx & 31;
        g_Hnew[(size_t)(s0 + row) * D + h * 32 + d] = Hs[idx] / Zs[row];
    }
}

// ---------------- attn_map by QK recompute: AM[s][c] = (1/8) sum_h exp(...)/Z ----------------
// grid (NC/128, NS/16), 256 thr. Warp w owns c-sub [w*16,w*16+16), loops h in registers.
// smem: Ks[128][264]h @0, Qs[16][264]h @67584, Gs[16][128]f @76032, AMs[16][132]f @84224, iZ[128]f @92672
#define AT_SMEM 93184
__global__ __launch_bounds__(256) void attn_recompute_kernel(
    const float* __restrict__ G, float* __restrict__ AM)
{
    extern __shared__ __align__(16) char smraw[];
    __half* Ks = (__half*)smraw;
    __half* Qs = (__half*)(smraw + 67584);
    float*  Gs = (float*)(smraw + 76032);
    float*  AMs = (float*)(smraw + 84224);
    float*  iZ = (float*)(smraw + 92672);

    const int c0 = blockIdx.x * 128;
    const int s0 = blockIdx.y * 16;
    const int tid = threadIdx.x;
    const int w = tid >> 5, lane = tid & 31;
    const int gr = lane >> 2, cc = lane & 3;
    const int l4 = lane & 15;
    const int cw16 = w * 16;
    const float isq = 0.17677669529663687f;

    // K tile: 128 rows x 256 halves
#pragma unroll
    for (int t = 0; t < 16; t++) {
        int idx = t * 256 + tid;
        int r = idx >> 5, pp = idx & 31;
        cpa16(&Ks[r * 264 + pp * 8], &g_Kh[(size_t)(c0 + r) * D + pp * 8]);
    }
    // Q tile: 16 rows x 256 halves
#pragma unroll
    for (int t = 0; t < 2; t++) {
        int idx = t * 256 + tid;
        int r = idx >> 5, pp = idx & 31;
        cpa16(&Qs[r * 264 + pp * 8], &g_Qh[(size_t)(s0 + r) * D + pp * 8]);
    }
    // G tile: 16 rows x 128 floats
#pragma unroll
    for (int t = 0; t < 2; t++) {
        int idx = t * 256 + tid;
        int r = idx >> 5, p4 = idx & 31;
        cpa16(&Gs[r * 128 + p4 * 4], &G[(size_t)(s0 + r) * NC + c0 + p4 * 4]);
    }
    asm volatile("cp.async.commit_group;");
    if (tid < 128) {
        int s = tid >> 3, hh = tid & 7;
        iZ[tid] = 0.125f / g_Z[(s0 + s) * NH + hh];
    }
    asm volatile("cp.async.wait_group 0;" ::: "memory");
    __syncthreads();

    // gate values for this warp's 16x16 tile (from smem, fixed across heads)
    float2 gA[2], gB[2];
#pragma unroll
    for (int nt = 0; nt < 2; nt++) {
        int col = cw16 + nt * 8 + 2 * cc;
        gA[nt] = *(const float2*)&Gs[gr * 128 + col];
        gB[nt] = *(const float2*)&Gs[(gr + 8) * 128 + col];
    }

    float acc[2][4] = {};
#pragma unroll
    for (int h = 0; h < NH; h++) {
        unsigned qa[2][4];
#pragma unroll
        for (int ks = 0; ks < 2; ks++)
            ldm_x4(qa[ks], smaddr(&Qs[l4 * 264 + h * 32 + ks * 16 + (lane >> 4) * 8]));
        float izA = iZ[gr * 8 + h];
        float izB = iZ[(gr + 8) * 8 + h];
#pragma unroll
        for (int nt = 0; nt < 2; nt++) {
            float S[4] = {0.f, 0.f, 0.f, 0.f};
#pragma unroll
            for (int ks = 0; ks < 2; ks++) {
                unsigned b[2];
                ldm_x2(b[0], b[1],
                       smaddr(&Ks[(cw16 + nt * 8 + (l4 & 7)) * 264 + h * 32 + ks * 16 + (l4 >> 3) * 8]));
                mma16816(S, qa[ks], b);
            }
            acc[nt][0] += __expf(S[0] * isq * gA[nt].x) * izA;
            acc[nt][1] += __expf(S[1] * isq * gA[nt].y) * izA;
            acc[nt][2] += __expf(S[2] * isq * gB[nt].x) * izB;
            acc[nt][3] += __expf(S[3] * isq * gB[nt].y) * izB;
        }
    }

    // stage to smem, then coalesced global write
#pragma unroll
    for (int nt = 0; nt < 2; nt++) {
        int col = cw16 + nt * 8 + 2 * cc;
        *(float2*)&AMs[gr * 132 + col]       = make_float2(acc[nt][0], acc[nt][1]);
        *(float2*)&AMs[(gr + 8) * 132 + col] = make_float2(acc[nt][2], acc[nt][3]);
    }
    __syncthreads();
#pragma unroll
    for (int t = 0; t < 2; t++) {
        int idx = t * 256 + tid;
        int r = idx >> 5, p4 = idx & 31;
        *(float4*)&AM[(size_t)(s0 + r) * NC + c0 + p4 * 4] = *(const float4*)&AMs[r * 132 + p4 * 4];
    }
}

// ---------------- cross-attn epilogue LN ----------------
__global__ __launch_bounds__(256) void ln_ca_kernel(
    const float* __restrict__ g, const float* __restrict__ b, const float* __restrict__ fusion)
{
    int tid = threadIdx.x;
    if (blockIdx.x == 0 && tid < D) g_tok[tid] = fusion[tid];
    int warp = tid >> 5, lane = tid & 31;
    int row = blockIdx.x * 8 + warp;
    float x[8];
    float s = 0.f;
#pragma unroll
    for (int j = 0; j < 8; j++) {
        int c = lane + 32 * j;
        x[j] = g_tmp[(size_t)row * D + c] + g_HS[(size_t)row * D + c];
        s += x[j];
    }
    s = warpSum(s);
    float m = s * (1.0f / D);
    float vs = 0.f;
#pragma unroll
    for (int j = 0; j < 8; j++) { float d = x[j] - m; vs += d * d; }
    vs = warpSum(vs);
    float r = rsqrtf(vs * (1.0f / D) + 1e-5f);
#pragma unroll
    for (int j = 0; j < 8; j++) {
        int c = lane + 32 * j;
        g_tok[(size_t)(1 + row) * D + c] = (x[j] - m) * r * g[c] + b[c];
    }
}

// ---------------- q0 = fusion @ Wq.T + bq ----------------
__global__ void q0_kernel(const float* __restrict__ fusion,
                          const float* __restrict__ w, const float* __restrict__ bqkv)
{
    __shared__ float fs[D];
    int tid = threadIdx.x;
    fs[tid] = fusion[tid];
    __syncthreads();
    float a = bqkv[tid];
    for (int c = 0; c < D; c++) a += fs[c] * w[(size_t)tid * D + c];
    g_q0[tid] = a;
}

// ---------------- row-0 scores over tokens ----------------
__global__ __launch_bounds__(256) void score0_kernel()
{
    __shared__ float q0s[D];
    __shared__ float zpart[NH];
    int tid = threadIdx.x;
    if (tid < D) q0s[tid] = g_q0[tid];
    if (tid < NH) zpart[tid] = 0.f;
    __syncthreads();
    int warp = tid >> 5, lane = tid & 31;
    int wtotal = gridDim.x * 8;
    const float isq = 0.17677669529663687f;
    for (int u = blockIdx.x * 8 + warp; u < TT; u += wtotal) {
        float mine = 0.f;
#pragma unroll
        for (int j = 0; j < 8; j++) {
            int c = lane + 32 * j;
            float v = q0s[c] * g_k2[(size_t)u * D + c];
            v = warpSum(v);
            if (lane == j) mine = v;
        }
        if (lane < 8) {
            float p = __expf(mine * isq);
            g_p0[u * NH + lane] = p;
            atomicAdd(&zpart[lane], p);
        }
    }
    __syncthreads();
    if (tid < NH) atomicAdd(&g_Z0[tid], zpart[tid]);
}

// ---------------- row-0 AV ----------------
__global__ __launch_bounds__(256) void av0_kernel()
{
    int col = threadIdx.x;
    int h = col >> 5;
    int u0 = blockIdx.x * 257;
    int u1 = u0 + 257; if (u1 > TT) u1 = TT;
    float acc = 0.f;
    for (int u = u0; u < u1; u++)
        acc += g_p0[u * NH + h] * g_v2[(size_t)u * D + col];
    atomicAdd(&g_a0[col], acc);
}

// ---------------- final head ----------------
__device__ __forceinline__ float blockSum256(float v, volatile float* red) {
    int lane = threadIdx.x & 31, w = threadIdx.x >> 5;
    v = warpSum(v);
    __syncthreads();
    if (lane == 0) red[w] = v;
    __syncthreads();
    float s = 0.f;
#pragma unroll
    for (int i = 0; i < 8; i++) s += red[i];
    return s;
}

__global__ __launch_bounds__(256) void final_kernel(
    const float* __restrict__ fusion,
    const float* __restrict__ mow, const float* __restrict__ mob,
    const float* __restrict__ ln1g, const float* __restrict__ ln1b,
    const float* __restrict__ w1, const float* __restrict__ b1,
    const float* __restrict__ w2, const float* __restrict__ b2,
    const float* __restrict__ ln2g, const float* __restrict__ ln2b,
    float* __restrict__ out)
{
    __shared__ float a0[D], t1[D], h1[2 * D];
    __shared__ float red[8];
    int tid = threadIdx.x;
    a0[tid] = g_a0[tid] / g_Z0[tid >> 5];
    __syncthreads();
    float y = mob[tid];
    for (int j = 0; j < D; j++) y += a0[j] * mow[(size_t)tid * D + j];
    float tv = fusion[tid] + y;
    float m = blockSum256(tv, red) * (1.0f / D);
    float d = tv - m;
    float var = blockSum256(d * d, red) * (1.0f / D);
    float t = d * rsqrtf(var + 1e-5f) * ln1g[tid] + ln1b[tid];
    t1[tid] = t;
    __syncthreads();
    float hh[2];
#pragma unroll
    for (int r2 = 0; r2 < 2; r2++) {
        int jj = tid + r2 * 256;
        float a = b1[jj];
        for (int c = 0; c < D; c++) a += t1[c] * w1[(size_t)jj * D + c];
        hh[r2] = a * 0.5f * (1.f + erff(a * 0.70710678118654752f));
    }
    h1[tid] = hh[0];
    h1[tid + 256] = hh[1];
    __syncthreads();
    float o = b2[tid];
    for (int j = 0; j < 512; j++) o += h1[j] * w2[(size_t)tid * 512 + j];
    float t2v = t1[tid] + o;   // residual = LN1 output
    float m2 = blockSum256(t2v, red) * (1.0f / D);
    float d2 = t2v - m2;
    float v2 = blockSum256(d2 * d2, red) * (1.0f / D);
    out[tid] = d2 * rsqrtf(v2 + 1e-5f) * ln2g[tid] + ln2b[tid];
}

// ---------------- launcher ----------------
extern "C" void kernel_launch(void* const* d_in, const int* in_sizes, int n_in,
                              void* d_out, int out_size)
{
    const float* H_S     = (const float*)d_in[0];
    const float* H_C     = (const float*)d_in[1];
    const float* H_G     = (const float*)d_in[2];
    const float* G_glyph = (const float*)d_in[3];
    const float* Ws      = (const float*)d_in[4];
    const float* bs      = (const float*)d_in[5];
    const float* Wb      = (const float*)d_in[6];
    const float* bb      = (const float*)d_in[7];
    const float* Wg      = (const float*)d_in[8];
    const float* bg      = (const float*)d_in[9];
    const float* WQ      = (const float*)d_in[10];
    const float* WK      = (const float*)d_in[11];
    const float* WV      = (const float*)d_in[12];
    const float* WO      = (const float*)d_in[13];
    const float* bO      = (const float*)d_in[14];
    const float* ln_ca_g = (const float*)d_in[15];
    const float* ln_ca_b = (const float*)d_in[16];
    const float* fusion  = (const float*)d_in[17];
    const float* mha_in_w  = (const float*)d_in[18];
    const float* mha_in_b  = (const float*)d_in[19];
    const float* mha_out_w = (const float*)d_in[20];
    const float* mha_out_b = (const float*)d_in[21];
    const float* ln1_g   = (const float*)d_in[22];
    const float* ln1_b   = (const float*)d_in[23];
    const float* ln2_g   = (const float*)d_in[24];
    const float* ln2_b   = (const float*)d_in[25];
    const float* ffn_w1  = (const float*)d_in[26];
    const float* ffn_b1  = (const float*)d_in[27];
    const float* ffn_w2  = (const float*)d_in[28];
    const float* ffn_b2  = (const float*)d_in[29];

    float* out = (float*)d_out;
    float* z_fused  = out;        // 256
    float* attn_map = out + D;    // 2048 * 4096

    float *pHS, *pHC, *pHnew, *pTmp, *pTok, *pk2, *pv2;
    __half *pQh, *pKh, *pVh;
    cudaGetSymbolAddress((void**)&pHS,  g_HS);
    cudaGetSymbolAddress((void**)&pHC,  g_HC);
    cudaGetSymbolAddress((void**)&pQh,  g_Qh);
    cudaGetSymbolAddress((void**)&pKh,  g_Kh);
    cudaGetSymbolAddress((void**)&pVh,  g_Vh);
    cudaGetSymbolAddress((void**)&pHnew,g_Hnew);
    cudaGetSymbolAddress((void**)&pTmp, g_tmp);
    cudaGetSymbolAddress((void**)&pTok, g_tok);
    cudaGetSymbolAddress((void**)&pk2,  g_k2);
    cudaGetSymbolAddress((void**)&pv2,  g_v2);

    static bool attrSet = false;
    if (!attrSet) {
        cudaFuncSetAttribute(ca_fused_kernel,
                             cudaFuncAttributeMaxDynamicSharedMemorySize, CA_SMEM);
        cudaFuncSetAttribute(attn_recompute_kernel,
                             cudaFuncAttributeMaxDynamicSharedMemorySize, AT_SMEM);
        attrSet = true;
    }

    // launches 1-5 (ca_fused is #6 for ncu -s 5 -c 1)
    gemm_tf32_kernel<false><<<dim3(4, 32), 256>>>(H_S, Ws, bs, pHS, nullptr,
                                                  nullptr, nullptr, nullptr, nullptr, NS, D, 128);
    gemm_tf32_kernel<false><<<dim3(4, 64), 256>>>(H_C, Wb, bb, pHC, nullptr,
                                                  nullptr, nullptr, nullptr, nullptr, NC, D, 256);
    gemm_tf32_kernel<true><<<dim3(4, 32), 256>>>(pHS, WQ, nullptr, nullptr, pQh,
                                                 nullptr, nullptr, nullptr, nullptr, NS, D, 256);
    gemm_tf32_kernel<true><<<dim3(4, 64, 2), 256>>>(pHC, WK, nullptr, nullptr, pKh,
                                                    WV, nullptr, nullptr, pVh, NC, D, 256);
    gemm_tf32_kernel<false><<<dim3(4, 32), 256>>>(H_G, Wg, bg, pTok + (size_t)(1 + NS) * D, nullptr,
                                                  nullptr, nullptr, nullptr, nullptr, NG, D, 64);

    // fused gated cross attention (Z + Hnew)
    ca_fused_kernel<<<dim3(NH, NS / 16), 256, CA_SMEM>>>(G_glyph);
    // attn_map via QK recompute (needs g_Z)
    attn_recompute_kernel<<<dim3(NC / 128, NS / 16), 256, AT_SMEM>>>(G_glyph, attn_map);

    // O projection + residual LN -> tokens
    gemm_tf32_kernel<false><<<dim3(4, 32), 256>>>(pHnew, WO, bO, pTmp, nullptr,
                                                  nullptr, nullptr, nullptr, nullptr, NS, D, 256);
    ln_ca_kernel<<<NS / 8, 256>>>(ln_ca_g, ln_ca_b, fusion);

    // self-attn K/V over tokens (dual)
    gemm_tf32_kernel<false><<<dim3(4, 65, 2), 256>>>(pTok,
        mha_in_w + 256 * 256, mha_in_b + 256, pk2, nullptr,
        mha_in_w + 512 * 256, mha_in_b + 512, pv2, nullptr, TT, D, 256);

    // token-0 attention + head
    zero_kernel<<<1, 256>>>();
    q0_kernel<<<1, 256>>>(fusion, mha_in_w, mha_in_b);
    score0_kernel<<<32, 256>>>();
    av0_kernel<<<16, 256>>>();
    final_kernel<<<1, 256>>>(fusion, mha_out_w, mha_out_b, ln1_g, ln1_b,
                             ffn_w1, ffn_b1, ffn_w2, ffn_b2, ln2_g, ln2_b, z_fused);
}

// round 7
// speedup vs baseline: 2.2911x; 1.1643x over previous
#include <cuda_runtime.h>
#include <cuda_fp16.h>

#define NS 2048
#define NC 4096
#define NG 2048
#define D  256
#define NH 8
#define TT 4097   // 1 + NS + NG

// ---------------- device scratch ----------------
__device__ float  g_HS[NS * D];
__device__ float  g_HC[NC * D];
__device__ __half g_Qh[NS * D];
__device__ __half g_Kh[NC * D];
__device__ __half g_Vh[NC * D];
__device__ float  g_Z[NS * NH];
__device__ float  g_Hnew[NS * D];
__device__ float  g_tmp[NS * D];
__device__ float  g_tok[TT * D];
__device__ float  g_k2[TT * D];
__device__ float  g_v2[TT * D];
__device__ float  g_q0[D];
__device__ float  g_p0[TT * NH];
__device__ float  g_Z0[NH];
__device__ float  g_a0[D];

__device__ __forceinline__ float warpSum(float v) {
#pragma unroll
    for (int o = 16; o; o >>= 1) v += __shfl_xor_sync(0xffffffffu, v, o);
    return v;
}

__device__ __forceinline__ void mma16816(float* c, const unsigned* a, const unsigned* b) {
    asm volatile(
        "mma.sync.aligned.m16n8k16.row.col.f32.f16.f16.f32 "
        "{%0,%1,%2,%3}, {%4,%5,%6,%7}, {%8,%9}, {%0,%1,%2,%3};\n"
        : "+f"(c[0]), "+f"(c[1]), "+f"(c[2]), "+f"(c[3])
        : "r"(a[0]), "r"(a[1]), "r"(a[2]), "r"(a[3]), "r"(b[0]), "r"(b[1]));
}

__device__ __forceinline__ unsigned smaddr(const void* p) {
    return (unsigned)__cvta_generic_to_shared(p);
}
__device__ __forceinline__ void ldm_x2(unsigned& r0, unsigned& r1, unsigned a) {
    asm volatile("ldmatrix.sync.aligned.m8n8.x2.shared.b16 {%0,%1}, [%2];"
                 : "=r"(r0), "=r"(r1) : "r"(a));
}
__device__ __forceinline__ void ldm_x2_t(unsigned& r0, unsigned& r1, unsigned a) {
    asm volatile("ldmatrix.sync.aligned.m8n8.x2.trans.shared.b16 {%0,%1}, [%2];"
                 : "=r"(r0), "=r"(r1) : "r"(a));
}
__device__ __forceinline__ void ldm_x4(unsigned* r, unsigned a) {
    asm volatile("ldmatrix.sync.aligned.m8n8.x4.shared.b16 {%0,%1,%2,%3}, [%4];"
                 : "=r"(r[0]), "=r"(r[1]), "=r"(r[2]), "=r"(r[3]) : "r"(a));
}
__device__ __forceinline__ void cpa16(void* smem, const void* gmem) {
    asm volatile("cp.async.cg.shared.global [%0], [%1], 16;"
                 :: "r"(smaddr(smem)), "l"(gmem));
}
__device__ __forceinline__ __half2 h2ex2(__half2 x) {
    unsigned r, xi = *(unsigned*)&x;
    asm("ex2.approx.f16x2 %0, %1;" : "=r"(r) : "r"(xi));
    return *(__half2*)&r;
}

#define CE 0.25506382f   // (1/sqrt(32)) * log2(e)

// ---------------- zero accumulators ----------------
__global__ void zero_kernel() {
    int i = blockIdx.x * blockDim.x + threadIdx.x;
    if (i < NH) g_Z0[i] = 0.f;
    if (i < D) g_a0[i] = 0.f;
}

// ---------------- fp16 tensor-core GEMM (up to 3 problems via blockIdx.z) ----------------
// C[m,n] = sum_k A[m,k]*W[n,k] + bias[n]; block tile 64x64, 8 warps (4x2).
// K%32==0, N%64==0, M guarded. OM: 0 fp32 out, 1 fp16 out.
template<int OM>
__global__ __launch_bounds__(256) void gemm16_kernel(
    const float* __restrict__ A0, const float* __restrict__ W0, const float* __restrict__ bs0,
    float* __restrict__ Cf0, __half* __restrict__ Ch0, int M0,
    const float* __restrict__ A1, const float* __restrict__ W1, const float* __restrict__ bs1,
    float* __restrict__ Cf1, __half* __restrict__ Ch1, int M1,
    const float* __restrict__ A2, const float* __restrict__ W2, const float* __restrict__ bs2,
    float* __restrict__ Cf2, __half* __restrict__ Ch2, int M2,
    int N, int K)
{
    const int z = blockIdx.z;
    const float* A    = z == 0 ? A0  : (z == 1 ? A1  : A2);
    const float* W    = z == 0 ? W0  : (z == 1 ? W1  : W2);
    const float* bias = z == 0 ? bs0 : (z == 1 ? bs1 : bs2);
    float* Cf         = z == 0 ? Cf0 : (z == 1 ? Cf1 : Cf2);
    __half* Ch        = z == 0 ? Ch0 : (z == 1 ? Ch1 : Ch2);
    const int M       = z == 0 ? M0  : (z == 1 ? M1  : M2);

    const int bm = blockIdx.y * 64, bn = blockIdx.x * 64;
    if (bm >= M) return;

    __shared__ __half Ah[64 * 40];
    __shared__ __half Bh[64 * 40];

    const int tid = threadIdx.x;
    const int w = tid >> 5, lane = tid & 31;
    const int wr = w >> 1, wc = w & 1;
    const int gr = lane >> 2, cc = lane & 3;
    const int fr = tid >> 2, fc8 = (tid & 3) * 8;
    const int l4 = lane & 15;
    const int hi8 = (lane >> 4) * 8;

    float acc[4][4] = {};

    for (int k0 = 0; k0 < K; k0 += 32) {
        __syncthreads();
        // fill A (guarded) and B, converting fp32 -> fp16, vectorized
        {
            float4 a0v = make_float4(0.f, 0.f, 0.f, 0.f), a1v = a0v;
            if (bm + fr < M) {
                const float* ap = &A[(size_t)(bm + fr) * K + k0 + fc8];
                a0v = *(const float4*)ap;
                a1v = *(const float4*)(ap + 4);
            }
            __half2 h0 = __floats2half2_rn(a0v.x, a0v.y);
            __half2 h1 = __floats2half2_rn(a0v.z, a0v.w);
            __half2 h2 = __floats2half2_rn(a1v.x, a1v.y);
            __half2 h3 = __floats2half2_rn(a1v.z, a1v.w);
            int4 pk = make_int4(*(int*)&h0, *(int*)&h1, *(int*)&h2, *(int*)&h3);
            *(int4*)&Ah[fr * 40 + fc8] = pk;

            const float* wp = &W[(size_t)(bn + fr) * K + k0 + fc8];
            float4 b0v = *(const float4*)wp;
            float4 b1v = *(const float4*)(wp + 4);
            __half2 g0 = __floats2half2_rn(b0v.x, b0v.y);
            __half2 g1 = __floats2half2_rn(b0v.z, b0v.w);
            __half2 g2 = __floats2half2_rn(b1v.x, b1v.y);
            __half2 g3 = __floats2half2_rn(b1v.z, b1v.w);
            int4 pk2 = make_int4(*(int*)&g0, *(int*)&g1, *(int*)&g2, *(int*)&g3);
            *(int4*)&Bh[fr * 40 + fc8] = pk2;
        }
        __syncthreads();

#pragma unroll
        for (int ks = 0; ks < 2; ks++) {
            unsigned af[4];
            ldm_x4(af, smaddr(&Ah[(wr * 16 + l4) * 40 + ks * 16 + hi8]));
            unsigned bf[2][4];
#pragma unroll
            for (int p = 0; p < 2; p++)
                ldm_x4(bf[p], smaddr(&Bh[(wc * 32 + p * 16 + l4) * 40 + ks * 16 + hi8]));
#pragma unroll
            for (int nt = 0; nt < 4; nt++) {
                unsigned bb[2];
                bb[0] = bf[nt >> 1][(nt & 1)];
                bb[1] = bf[nt >> 1][(nt & 1) + 2];
                mma16816(acc[nt], af, bb);
            }
        }
    }

#pragma unroll
    for (int nt = 0; nt < 4; nt++) {
        int col = bn + wc * 32 + nt * 8 + 2 * cc;
        float b0 = bias ? bias[col] : 0.f;
        float b1 = bias ? bias[col + 1] : 0.f;
        int row0 = bm + wr * 16 + gr;
        int row1 = row0 + 8;
        if (row0 < M) {
            if (OM == 1) {
                Ch[(size_t)row0 * N + col]     = __float2half(acc[nt][0] + b0);
                Ch[(size_t)row0 * N + col + 1] = __float2half(acc[nt][1] + b1);
            } else {
                Cf[(size_t)row0 * N + col]     = acc[nt][0] + b0;
                Cf[(size_t)row0 * N + col + 1] = acc[nt][1] + b1;
            }
        }
        if (row1 < M) {
            if (OM == 1) {
                Ch[(size_t)row1 * N + col]     = __float2half(acc[nt][2] + b0);
                Ch[(size_t)row1 * N + col + 1] = __float2half(acc[nt][3] + b1);
            } else {
                Cf[(size_t)row1 * N + col]     = acc[nt][2] + b0;
                Cf[(size_t)row1 * N + col + 1] = acc[nt][3] + b1;
            }
        }
    }
}

// ---------------- fused gated cross-attention: Z + softmax@V (no P store) ----------------
// grid = (NH, NS/16). smem: Ks 2x10240h, Vs 2x10240h, Qs 640h, Hs 512f, Zs 16f
#define CA_SMEM 85312
__global__ __launch_bounds__(256) void ca_fused_kernel(const float* __restrict__ G)
{
    extern __shared__ __align__(16) char smraw[];
    __half* Ks = (__half*)smraw;
    __half* Vs = (__half*)(smraw + 40960);
    __half* Qs = (__half*)(smraw + 81920);
    float*  Hs = (float*)(smraw + 83200);
    float*  Zs = (float*)(smraw + 85248);

    const int h = blockIdx.x;
    const int s0 = blockIdx.y * 16;
    const int tid = threadIdx.x;
    const int w = tid >> 5, lane = tid & 31;
    const int gr = lane >> 2, cc = lane & 3;
    const int cw = w * 32;
    const int l4 = lane & 15;

    auto issue_tile = [&](int ci) {
        int buf = (ci & 1) * 10240;
        int c0 = ci * 256;
        int pr = tid >> 2, pp = tid & 3;
#pragma unroll
        for (int rr = 0; rr < 4; rr++) {
            int row = rr * 64 + pr;
            size_t src = (size_t)(c0 + row) * D + h * 32 + pp * 8;
            cpa16(&Ks[buf + row * 40 + pp * 8], &g_Kh[src]);
            cpa16(&Vs[buf + row * 40 + pp * 8], &g_Vh[src]);
        }
        asm volatile("cp.async.commit_group;");
    };

    {
        int row = tid >> 4, c2 = (tid & 15) * 2;
        *(unsigned*)&Qs[row * 40 + c2] =
            *(const unsigned*)&g_Qh[(size_t)(s0 + row) * D + h * 32 + c2];
    }
    Hs[tid] = 0.f;
    Hs[tid + 256] = 0.f;
    if (tid < 16) Zs[tid] = 0.f;

    issue_tile(0);
    __syncthreads();

    unsigned qa[2][4];
    {
        int qrow = lane & 15;
        int qcol = (lane >> 4) * 8;
#pragma unroll
        for (int ks = 0; ks < 2; ks++)
            ldm_x4(qa[ks], smaddr(&Qs[qrow * 40 + ks * 16 + qcol]));
    }

    float hacc[4][4] = {};
    float zacc0 = 0.f, zacc1 = 0.f;

    for (int ci = 0; ci < 16; ci++) {
        int c0 = ci * 256;
        int buf = (ci & 1) * 10240;
        if (ci < 15) issue_tile(ci + 1);

        // gate values pre-scaled by isq*log2e
        float2 gA[4], gB[4];
#pragma unroll
        for (int nt = 0; nt < 4; nt++) {
            int gcol = c0 + cw + nt * 8 + 2 * cc;
            gA[nt] = __ldg((const float2*)&G[(size_t)(s0 + gr) * NC + gcol]);
            gB[nt] = __ldg((const float2*)&G[(size_t)(s0 + gr + 8) * NC + gcol]);
            gA[nt].x *= CE; gA[nt].y *= CE;
            gB[nt].x *= CE; gB[nt].y *= CE;
        }

        if (ci < 15) asm volatile("cp.async.wait_group 1;" ::: "memory");
        else         asm volatile("cp.async.wait_group 0;" ::: "memory");
        __syncthreads();

        unsigned pa[2][4];
#pragma unroll
        for (int nt = 0; nt < 4; nt++) {
            float S[4] = {0.f, 0.f, 0.f, 0.f};
#pragma unroll
            for (int ks = 0; ks < 2; ks++) {
                unsigned b[2];
                ldm_x2(b[0], b[1],
                       smaddr(&Ks[buf + (cw + nt * 8 + (l4 & 7)) * 40 + ks * 16 + (l4 >> 3) * 8]));
                mma16816(S, qa[ks], b);
            }
            // exp2 in fp16x2
            __half2 x01 = __floats2half2_rn(S[0] * gA[nt].x, S[1] * gA[nt].y);
            __half2 x23 = __floats2half2_rn(S[2] * gB[nt].x, S[3] * gB[nt].y);
            __half2 p01 = h2ex2(x01);
            __half2 p23 = h2ex2(x23);
            float2 f01 = __half22float2(p01);
            float2 f23 = __half22float2(p23);
            zacc0 += f01.x + f01.y;
            zacc1 += f23.x + f23.y;
            unsigned u01 = *(unsigned*)&p01, u23 = *(unsigned*)&p23;
            if ((nt & 1) == 0) { pa[nt >> 1][0] = u01; pa[nt >> 1][1] = u23; }
            else               { pa[nt >> 1][2] = u01; pa[nt >> 1][3] = u23; }
        }

#pragma unroll
        for (int nt2 = 0; nt2 < 4; nt2++) {
#pragma unroll
            for (int ks2 = 0; ks2 < 2; ks2++) {
                unsigned b[2];
                ldm_x2_t(b[0], b[1],
                         smaddr(&Vs[buf + (cw + ks2 * 16 + l4) * 40 + nt2 * 8]));
                mma16816(hacc[nt2], pa[ks2], b);
            }
        }
        __syncthreads();
    }

#pragma unroll
    for (int o = 1; o < 4; o <<= 1) {
        zacc0 += __shfl_xor_sync(0xffffffffu, zacc0, o);
        zacc1 += __shfl_xor_sync(0xffffffffu, zacc1, o);
    }
    if (cc == 0) {
        atomicAdd(&Zs[gr], zacc0);
        atomicAdd(&Zs[gr + 8], zacc1);
    }
#pragma unroll
    for (int nt2 = 0; nt2 < 4; nt2++) {
        atomicAdd(&Hs[gr * 32 + nt2 * 8 + 2 * cc],           hacc[nt2][0]);
        atomicAdd(&Hs[gr * 32 + nt2 * 8 + 2 * cc + 1],       hacc[nt2][1]);
        atomicAdd(&Hs[(gr + 8) * 32 + nt2 * 8 + 2 * cc],     hacc[nt2][2]);
        atomicAdd(&Hs[(gr + 8) * 32 + nt2 * 8 + 2 * cc + 1], hacc[nt2][3]);
    }
    __syncthreads();
    if (tid < 16) g_Z[(s0 + tid) * NH + h] = Zs[tid];
#pragma unroll
    for (int k = 0; k < 2; k++) {
        int idx = k * 256 + tid;
        int row = idx >> 5, d = idx & 31;
        g_Hnew[(size_t)(s0 + row) * D + h * 32 + d] = Hs[idx] / Zs[row];
    }
}

// ---------------- attn_map by QK recompute ----------------
#define AT_SMEM 93184
__global__ __launch_bounds__(256) void attn_recompute_kernel(
    const float* __restrict__ G, float* __restrict__ AM)
{
    extern __shared__ __align__(16) char smraw[];
    __half* Ks = (__half*)smraw;
    __half* Qs = (__half*)(smraw + 67584);
    float*  Gs = (float*)(smraw + 76032);
    float*  AMs = (float*)(smraw + 84224);
    float*  iZ = (float*)(smraw + 92672);

    const int c0 = blockIdx.x * 128;
    const int s0 = blockIdx.y * 16;
    const int tid = threadIdx.x;
    const int w = tid >> 5, lane = tid & 31;
    const int gr = lane >> 2, cc = lane & 3;
    const int l4 = lane & 15;
    const int hi8 = (lane >> 4) * 8;
    const int cw16 = w * 16;

#pragma unroll
    for (int t = 0; t < 16; t++) {
        int idx = t * 256 + tid;
        int r = idx >> 5, pp = idx & 31;
        cpa16(&Ks[r * 264 + pp * 8], &g_Kh[(size_t)(c0 + r) * D + pp * 8]);
    }
#pragma unroll
    for (int t = 0; t < 2; t++) {
        int idx = t * 256 + tid;
        int r = idx >> 5, pp = idx & 31;
        cpa16(&Qs[r * 264 + pp * 8], &g_Qh[(size_t)(s0 + r) * D + pp * 8]);
    }
#pragma unroll
    for (int t = 0; t < 2; t++) {
        int idx = t * 256 + tid;
        int r = idx >> 5, p4 = idx & 31;
        cpa16(&Gs[r * 128 + p4 * 4], &G[(size_t)(s0 + r) * NC + c0 + p4 * 4]);
    }
    asm volatile("cp.async.commit_group;");
    if (tid < 128) {
        int s = tid >> 3, hh = tid & 7;
        iZ[tid] = 0.125f / g_Z[(s0 + s) * NH + hh];
    }
    asm volatile("cp.async.wait_group 0;" ::: "memory");
    __syncthreads();

    float2 gA[2], gB[2];
#pragma unroll
    for (int nt = 0; nt < 2; nt++) {
        int col = cw16 + nt * 8 + 2 * cc;
        gA[nt] = *(const float2*)&Gs[gr * 128 + col];
        gB[nt] = *(const float2*)&Gs[(gr + 8) * 128 + col];
        gA[nt].x *= CE; gA[nt].y *= CE;
        gB[nt].x *= CE; gB[nt].y *= CE;
    }

    float acc[2][4] = {};
#pragma unroll
    for (int h = 0; h < NH; h++) {
        unsigned qa[2][4];
#pragma unroll
        for (int ks = 0; ks < 2; ks++)
            ldm_x4(qa[ks], smaddr(&Qs[l4 * 264 + h * 32 + ks * 16 + hi8]));
        unsigned kb[2][4];
#pragma unroll
        for (int ks = 0; ks < 2; ks++)
            ldm_x4(kb[ks], smaddr(&Ks[(cw16 + l4) * 264 + h * 32 + ks * 16 + hi8]));
        float izA = iZ[gr * 8 + h];
        float izB = iZ[(gr + 8) * 8 + h];
#pragma unroll
        for (int nt = 0; nt < 2; nt++) {
            float S[4] = {0.f, 0.f, 0.f, 0.f};
#pragma unroll
            for (int ks = 0; ks < 2; ks++) {
                unsigned bb[2];
                bb[0] = kb[ks][nt];
                bb[1] = kb[ks][nt + 2];
                mma16816(S, qa[ks], bb);
            }
            __half2 x01 = __floats2half2_rn(S[0] * gA[nt].x, S[1] * gA[nt].y);
            __half2 x23 = __floats2half2_rn(S[2] * gB[nt].x, S[3] * gB[nt].y);
            float2 f01 = __half22float2(h2ex2(x01));
            float2 f23 = __half22float2(h2ex2(x23));
            acc[nt][0] += f01.x * izA;
            acc[nt][1] += f01.y * izA;
            acc[nt][2] += f23.x * izB;
            acc[nt][3] += f23.y * izB;
        }
    }

#pragma unroll
    for (int nt = 0; nt < 2; nt++) {
        int col = cw16 + nt * 8 + 2 * cc;
        *(float2*)&AMs[gr * 132 + col]       = make_float2(acc[nt][0], acc[nt][1]);
        *(float2*)&AMs[(gr + 8) * 132 + col] = make_float2(acc[nt][2], acc[nt][3]);
    }
    __syncthreads();
#pragma unroll
    for (int t = 0; t < 2; t++) {
        int idx = t * 256 + tid;
        int r = idx >> 5, p4 = idx & 31;
        *(float4*)&AM[(size_t)(s0 + r) * NC + c0 + p4 * 4] = *(const float4*)&AMs[r * 132 + p4 * 4];
    }
}

// ---------------- cross-attn epilogue LN ----------------
__global__ __launch_bounds__(256) void ln_ca_kernel(
    const float* __restrict__ g, const float* __restrict__ b, const float* __restrict__ fusion)
{
    int tid = threadIdx.x;
    if (blockIdx.x == 0 && tid < D) g_tok[tid] = fusion[tid];
    int warp = tid >> 5, lane = tid & 31;
    int row = blockIdx.x * 8 + warp;
    float x[8];
    float s = 0.f;
#pragma unroll
    for (int j = 0; j < 8; j++) {
        int c = lane + 32 * j;
        x[j] = g_tmp[(size_t)row * D + c] + g_HS[(size_t)row * D + c];
        s += x[j];
    }
    s = warpSum(s);
    float m = s * (1.0f / D);
    float vs = 0.f;
#pragma unroll
    for (int j = 0; j < 8; j++) { float d = x[j] - m; vs += d * d; }
    vs = warpSum(vs);
    float r = rsqrtf(vs * (1.0f / D) + 1e-5f);
#pragma unroll
    for (int j = 0; j < 8; j++) {
        int c = lane + 32 * j;
        g_tok[(size_t)(1 + row) * D + c] = (x[j] - m) * r * g[c] + b[c];
    }
}

// ---------------- q0 = fusion @ Wq.T + bq ----------------
__global__ void q0_kernel(const float* __restrict__ fusion,
                          const float* __restrict__ w, const float* __restrict__ bqkv)
{
    __shared__ float fs[D];
    int tid = threadIdx.x;
    fs[tid] = fusion[tid];
    __syncthreads();
    float a = bqkv[tid];
    for (int c = 0; c < D; c++) a += fs[c] * w[(size_t)tid * D + c];
    g_q0[tid] = a;
}

// ---------------- row-0 scores over tokens ----------------
__global__ __launch_bounds__(256) void score0_kernel()
{
    __shared__ float q0s[D];
    __shared__ float zpart[NH];
    int tid = threadIdx.x;
    if (tid < D) q0s[tid] = g_q0[tid];
    if (tid < NH) zpart[tid] = 0.f;
    __syncthreads();
    int warp = tid >> 5, lane = tid & 31;
    int wtotal = gridDim.x * 8;
    const float isq = 0.17677669529663687f;
    for (int u = blockIdx.x * 8 + warp; u < TT; u += wtotal) {
        float mine = 0.f;
#pragma unroll
        for (int j = 0; j < 8; j++) {
            int c = lane + 32 * j;
            float v = q0s[c] * g_k2[(size_t)u * D + c];
            v = warpSum(v);
            if (lane == j) mine = v;
        }
        if (lane < 8) {
            float p = __expf(mine * isq);
            g_p0[u * NH + lane] = p;
            atomicAdd(&zpart[lane], p);
        }
    }
    __syncthreads();
    if (tid < NH) atomicAdd(&g_Z0[tid], zpart[tid]);
}

// ---------------- row-0 AV ----------------
__global__ __launch_bounds__(256) void av0_kernel()
{
    int col = threadIdx.x;
    int h = col >> 5;
    int u0 = blockIdx.x * 257;
    int u1 = u0 + 257; if (u1 > TT) u1 = TT;
    float acc = 0.f;
    for (int u = u0; u < u1; u++)
        acc += g_p0[u * NH + h] * g_v2[(size_t)u * D + col];
    atomicAdd(&g_a0[col], acc);
}

// ---------------- final head ----------------
__device__ __forceinline__ float blockSum256(float v, volatile float* red) {
    int lane = threadIdx.x & 31, w = threadIdx.x >> 5;
    v = warpSum(v);
    __syncthreads();
    if (lane == 0) red[w] = v;
    __syncthreads();
    float s = 0.f;
#pragma unroll
    for (int i = 0; i < 8; i++) s += red[i];
    return s;
}

__global__ __launch_bounds__(256) void final_kernel(
    const float* __restrict__ fusion,
    const float* __restrict__ mow, const float* __restrict__ mob,
    const float* __restrict__ ln1g, const float* __restrict__ ln1b,
    const float* __restrict__ w1, const float* __restrict__ b1,
    const float* __restrict__ w2, const float* __restrict__ b2,
    const float* __restrict__ ln2g, const float* __restrict__ ln2b,
    float* __restrict__ out)
{
    __shared__ float a0[D], t1[D], h1[2 * D];
    __shared__ float red[8];
    int tid = threadIdx.x;
    a0[tid] = g_a0[tid] / g_Z0[tid >> 5];
    __syncthreads();
    float y = mob[tid];
    for (int j = 0; j < D; j++) y += a0[j] * mow[(size_t)tid * D + j];
    float tv = fusion[tid] + y;
    float m = blockSum256(tv, red) * (1.0f / D);
    float d = tv - m;
    float var = blockSum256(d * d, red) * (1.0f / D);
    float t = d * rsqrtf(var + 1e-5f) * ln1g[tid] + ln1b[tid];
    t1[tid] = t;
    __syncthreads();
    float hh[2];
#pragma unroll
    for (int r2 = 0; r2 < 2; r2++) {
        int jj = tid + r2 * 256;
        float a = b1[jj];
        for (int c = 0; c < D; c++) a += t1[c] * w1[(size_t)jj * D + c];
        hh[r2] = a * 0.5f * (1.f + erff(a * 0.70710678118654752f));
    }
    h1[tid] = hh[0];
    h1[tid + 256] = hh[1];
    __syncthreads();
    float o = b2[tid];
    for (int j = 0; j < 512; j++) o += h1[j] * w2[(size_t)tid * 512 + j];
    float t2v = t1[tid] + o;   // residual = LN1 output
    float m2 = blockSum256(t2v, red) * (1.0f / D);
    float d2 = t2v - m2;
    float v2 = blockSum256(d2 * d2, red) * (1.0f / D);
    out[tid] = d2 * rsqrtf(v2 + 1e-5f) * ln2g[tid] + ln2b[tid];
}

// ---------------- launcher ----------------
extern "C" void kernel_launch(void* const* d_in, const int* in_sizes, int n_in,
                              void* d_out, int out_size)
{
    const float* H_S     = (const float*)d_in[0];
    const float* H_C     = (const float*)d_in[1];
    const float* H_G     = (const float*)d_in[2];
    const float* G_glyph = (const float*)d_in[3];
    const float* Ws      = (const float*)d_in[4];
    const float* bs      = (const float*)d_in[5];
    const float* Wb      = (const float*)d_in[6];
    const float* bb      = (const float*)d_in[7];
    const float* Wg      = (const float*)d_in[8];
    const float* bg      = (const float*)d_in[9];
    const float* WQ      = (const float*)d_in[10];
    const float* WK      = (const float*)d_in[11];
    const float* WV      = (const float*)d_in[12];
    const float* WO      = (const float*)d_in[13];
    const float* bO      = (const float*)d_in[14];
    const float* ln_ca_g = (const float*)d_in[15];
    const float* ln_ca_b = (const float*)d_in[16];
    const float* fusion  = (const float*)d_in[17];
    const float* mha_in_w  = (const float*)d_in[18];
    const float* mha_in_b  = (const float*)d_in[19];
    const float* mha_out_w = (const float*)d_in[20];
    const float* mha_out_b = (const float*)d_in[21];
    const float* ln1_g   = (const float*)d_in[22];
    const float* ln1_b   = (const float*)d_in[23];
    const float* ln2_g   = (const float*)d_in[24];
    const float* ln2_b   = (const float*)d_in[25];
    const float* ffn_w1  = (const float*)d_in[26];
    const float* ffn_b1  = (const float*)d_in[27];
    const float* ffn_w2  = (const float*)d_in[28];
    const float* ffn_b2  = (const float*)d_in[29];

    float* out = (float*)d_out;
    float* z_fused  = out;        // 256
    float* attn_map = out + D;    // 2048 * 4096

    float *pHS, *pHC, *pHnew, *pTmp, *pTok, *pk2, *pv2;
    __half *pQh, *pKh, *pVh;
    cudaGetSymbolAddress((void**)&pHS,  g_HS);
    cudaGetSymbolAddress((void**)&pHC,  g_HC);
    cudaGetSymbolAddress((void**)&pQh,  g_Qh);
    cudaGetSymbolAddress((void**)&pKh,  g_Kh);
    cudaGetSymbolAddress((void**)&pVh,  g_Vh);
    cudaGetSymbolAddress((void**)&pHnew,g_Hnew);
    cudaGetSymbolAddress((void**)&pTmp, g_tmp);
    cudaGetSymbolAddress((void**)&pTok, g_tok);
    cudaGetSymbolAddress((void**)&pk2,  g_k2);
    cudaGetSymbolAddress((void**)&pv2,  g_v2);

    static bool attrSet = false;
    if (!attrSet) {
        cudaFuncSetAttribute(ca_fused_kernel,
                             cudaFuncAttributeMaxDynamicSharedMemorySize, CA_SMEM);
        cudaFuncSetAttribute(attn_recompute_kernel,
                             cudaFuncAttributeMaxDynamicSharedMemorySize, AT_SMEM);
        attrSet = true;
    }

    // #1 HS = H_S @ Ws.T + bs (fp32 out)
    gemm16_kernel<0><<<dim3(4, 32), 256>>>(
        H_S, Ws, bs, pHS, nullptr, NS,
        H_S, Ws, bs, pHS, nullptr, NS,
        H_S, Ws, bs, pHS, nullptr, NS, D, 128);
    // #2 HC = H_C @ Wb.T + bb (fp32 out)
    gemm16_kernel<0><<<dim3(4, 64), 256>>>(
        H_C, Wb, bb, pHC, nullptr, NC,
        H_C, Wb, bb, pHC, nullptr, NC,
        H_C, Wb, bb, pHC, nullptr, NC, D, 256);
    // #3 Q/K/V triple (fp16 out)
    gemm16_kernel<1><<<dim3(4, 64, 3), 256>>>(
        pHS, WQ, nullptr, nullptr, pQh, NS,
        pHC, WK, nullptr, nullptr, pKh, NC,
        pHC, WV, nullptr, nullptr, pVh, NC, D, 256);
    // #4 fused gated cross attention (Z + Hnew)  <-- ncu capture target
    ca_fused_kernel<<<dim3(NH, NS / 16), 256, CA_SMEM>>>(G_glyph);
    // #5 HG projection into token slots
    gemm16_kernel<0><<<dim3(4, 32), 256>>>(
        H_G, Wg, bg, pTok + (size_t)(1 + NS) * D, nullptr, NG,
        H_G, Wg, bg, pTok + (size_t)(1 + NS) * D, nullptr, NG,
        H_G, Wg, bg, pTok + (size_t)(1 + NS) * D, nullptr, NG, D, 64);
    // #6 attn_map via QK recompute (needs g_Z)
    attn_recompute_kernel<<<dim3(NC / 128, NS / 16), 256, AT_SMEM>>>(G_glyph, attn_map);
    // O projection + residual LN -> tokens
    gemm16_kernel<0><<<dim3(4, 32), 256>>>(
        pHnew, WO, bO, pTmp, nullptr, NS,
        pHnew, WO, bO, pTmp, nullptr, NS,
        pHnew, WO, bO, pTmp, nullptr, NS, D, 256);
    ln_ca_kernel<<<NS / 8, 256>>>(ln_ca_g, ln_ca_b, fusion);
    // self-attn K/V over tokens (dual)
    gemm16_kernel<0><<<dim3(4, 65, 2), 256>>>(
        pTok, mha_in_w + 256 * 256, mha_in_b + 256, pk2, nullptr, TT,
        pTok, mha_in_w + 512 * 256, mha_in_b + 512, pv2, nullptr, TT,
        pTok, mha_in_w + 256 * 256, mha_in_b + 256, pk2, nullptr, TT, D, 256);
    // token-0 attention + head
    zero_kernel<<<1, 256>>>();
    q0_kernel<<<1, 256>>>(fusion, mha_in_w, mha_in_b);
    score0_kernel<<<32, 256>>>();
    av0_kernel<<<16, 256>>>();
    final_kernel<<<1, 256>>>(fusion, mha_out_w, mha_out_b, ln1_g, ln1_b,
                             ffn_w1, ffn_b1, ffn_w2, ffn_b2, ln2_g, ln2_b, z_fused);
}

// round 8
// speedup vs baseline: 2.4600x; 1.0737x over previous
#include <cuda_runtime.h>
#include <cuda_fp16.h>

#define NS 2048
#define NC 4096
#define NG 2048
#define D  256
#define NH 8
#define TT 4097   // 1 + NS + NG

// ---------------- device scratch ----------------
__device__ float  g_HS[NS * D];
__device__ float  g_HC[NC * D];
__device__ __half g_Qh[NS * D];
__device__ __half g_Kh[NC * D];
__device__ __half g_Vh[NC * D];
__device__ __half g_Gh[(size_t)NS * NC];   // gate * (isq*log2e), fp16
__device__ float  g_Z[NS * NH];
__device__ float  g_Hnew[NS * D];
__device__ float  g_tmp[NS * D];
__device__ float  g_tok[TT * D];
__device__ float  g_k2[TT * D];
__device__ float  g_v2[TT * D];
__device__ float  g_q0[D];
__device__ float  g_p0[TT * NH];
__device__ float  g_Z0[NH];
__device__ float  g_a0[D];

__device__ __forceinline__ float warpSum(float v) {
#pragma unroll
    for (int o = 16; o; o >>= 1) v += __shfl_xor_sync(0xffffffffu, v, o);
    return v;
}

__device__ __forceinline__ void mma16816(float* c, const unsigned* a, const unsigned* b) {
    asm volatile(
        "mma.sync.aligned.m16n8k16.row.col.f32.f16.f16.f32 "
        "{%0,%1,%2,%3}, {%4,%5,%6,%7}, {%8,%9}, {%0,%1,%2,%3};\n"
        : "+f"(c[0]), "+f"(c[1]), "+f"(c[2]), "+f"(c[3])
        : "r"(a[0]), "r"(a[1]), "r"(a[2]), "r"(a[3]), "r"(b[0]), "r"(b[1]));
}

__device__ __forceinline__ unsigned smaddr(const void* p) {
    return (unsigned)__cvta_generic_to_shared(p);
}
__device__ __forceinline__ void ldm_x2(unsigned& r0, unsigned& r1, unsigned a) {
    asm volatile("ldmatrix.sync.aligned.m8n8.x2.shared.b16 {%0,%1}, [%2];"
                 : "=r"(r0), "=r"(r1) : "r"(a));
}
__device__ __forceinline__ void ldm_x2_t(unsigned& r0, unsigned& r1, unsigned a) {
    asm volatile("ldmatrix.sync.aligned.m8n8.x2.trans.shared.b16 {%0,%1}, [%2];"
                 : "=r"(r0), "=r"(r1) : "r"(a));
}
__device__ __forceinline__ void ldm_x4(unsigned* r, unsigned a) {
    asm volatile("ldmatrix.sync.aligned.m8n8.x4.shared.b16 {%0,%1,%2,%3}, [%4];"
                 : "=r"(r[0]), "=r"(r[1]), "=r"(r[2]), "=r"(r[3]) : "r"(a));
}
__device__ __forceinline__ void cpa16(void* smem, const void* gmem) {
    asm volatile("cp.async.cg.shared.global [%0], [%1], 16;"
                 :: "r"(smaddr(smem)), "l"(gmem));
}
__device__ __forceinline__ __half2 h2ex2(__half2 x) {
    unsigned r, xi = *(unsigned*)&x;
    asm("ex2.approx.f16x2 %0, %1;" : "=r"(r) : "r"(xi));
    return *(__half2*)&r;
}

#define CE 0.25506382f   // (1/sqrt(32)) * log2(e)

// ---------------- zero accumulators ----------------
__global__ void zero_kernel() {
    int i = blockIdx.x * blockDim.x + threadIdx.x;
    if (i < NH) g_Z0[i] = 0.f;
    if (i < D) g_a0[i] = 0.f;
}

// ---------------- fp16 tensor-core GEMM (up to 3 problems via blockIdx.z) ----------------
// Optionally the LAST z-slice converts G fp32 -> fp16*CE instead (gsrc != null).
template<int OM>
__global__ __launch_bounds__(256) void gemm16_kernel(
    const float* __restrict__ A0, const float* __restrict__ W0, const float* __restrict__ bs0,
    float* __restrict__ Cf0, __half* __restrict__ Ch0, int M0,
    const float* __restrict__ A1, const float* __restrict__ W1, const float* __restrict__ bs1,
    float* __restrict__ Cf1, __half* __restrict__ Ch1, int M1,
    const float* __restrict__ A2, const float* __restrict__ W2, const float* __restrict__ bs2,
    float* __restrict__ Cf2, __half* __restrict__ Ch2, int M2,
    int N, int K,
    const float* __restrict__ gsrc, __half* __restrict__ gdst)
{
    if (gsrc != nullptr && blockIdx.z == gridDim.z - 1) {
        // gate conversion path
        int bid = blockIdx.y * gridDim.x + blockIdx.x;
        int t4 = bid * 256 + threadIdx.x;
        const int total4 = (NS * NC) / 4;
        int stride = gridDim.x * gridDim.y * 256;
        for (int i = t4; i < total4; i += stride) {
            float4 v = *(const float4*)&gsrc[(size_t)i * 4];
            __half2 h0 = __floats2half2_rn(v.x * CE, v.y * CE);
            __half2 h1 = __floats2half2_rn(v.z * CE, v.w * CE);
            *(int2*)&gdst[(size_t)i * 4] = make_int2(*(int*)&h0, *(int*)&h1);
        }
        return;
    }

    const int z = blockIdx.z;
    const float* A    = z == 0 ? A0  : (z == 1 ? A1  : A2);
    const float* W    = z == 0 ? W0  : (z == 1 ? W1  : W2);
    const float* bias = z == 0 ? bs0 : (z == 1 ? bs1 : bs2);
    float* Cf         = z == 0 ? Cf0 : (z == 1 ? Cf1 : Cf2);
    __half* Ch        = z == 0 ? Ch0 : (z == 1 ? Ch1 : Ch2);
    const int M       = z == 0 ? M0  : (z == 1 ? M1  : M2);

    const int bm = blockIdx.y * 64, bn = blockIdx.x * 64;
    if (bm >= M) return;

    __shared__ __half Ah[64 * 40];
    __shared__ __half Bh[64 * 40];

    const int tid = threadIdx.x;
    const int w = tid >> 5, lane = tid & 31;
    const int wr = w >> 1, wc = w & 1;
    const int gr = lane >> 2, cc = lane & 3;
    const int fr = tid >> 2, fc8 = (tid & 3) * 8;
    const int l4 = lane & 15;
    const int hi8 = (lane >> 4) * 8;

    float acc[4][4] = {};

    for (int k0 = 0; k0 < K; k0 += 32) {
        __syncthreads();
        {
            float4 a0v = make_float4(0.f, 0.f, 0.f, 0.f), a1v = a0v;
            if (bm + fr < M) {
                const float* ap = &A[(size_t)(bm + fr) * K + k0 + fc8];
                a0v = *(const float4*)ap;
                a1v = *(const float4*)(ap + 4);
            }
            __half2 h0 = __floats2half2_rn(a0v.x, a0v.y);
            __half2 h1 = __floats2half2_rn(a0v.z, a0v.w);
            __half2 h2 = __floats2half2_rn(a1v.x, a1v.y);
            __half2 h3 = __floats2half2_rn(a1v.z, a1v.w);
            int4 pk = make_int4(*(int*)&h0, *(int*)&h1, *(int*)&h2, *(int*)&h3);
            *(int4*)&Ah[fr * 40 + fc8] = pk;

            const float* wp = &W[(size_t)(bn + fr) * K + k0 + fc8];
            float4 b0v = *(const float4*)wp;
            float4 b1v = *(const float4*)(wp + 4);
            __half2 g0 = __floats2half2_rn(b0v.x, b0v.y);
            __half2 g1 = __floats2half2_rn(b0v.z, b0v.w);
            __half2 g2 = __floats2half2_rn(b1v.x, b1v.y);
            __half2 g3 = __floats2half2_rn(b1v.z, b1v.w);
            int4 pk2 = make_int4(*(int*)&g0, *(int*)&g1, *(int*)&g2, *(int*)&g3);
            *(int4*)&Bh[fr * 40 + fc8] = pk2;
        }
        __syncthreads();

#pragma unroll
        for (int ks = 0; ks < 2; ks++) {
            unsigned af[4];
            ldm_x4(af, smaddr(&Ah[(wr * 16 + l4) * 40 + ks * 16 + hi8]));
            unsigned bf[2][4];
#pragma unroll
            for (int p = 0; p < 2; p++)
                ldm_x4(bf[p], smaddr(&Bh[(wc * 32 + p * 16 + l4) * 40 + ks * 16 + hi8]));
#pragma unroll
            for (int nt = 0; nt < 4; nt++) {
                unsigned bb[2];
                bb[0] = bf[nt >> 1][(nt & 1)];
                bb[1] = bf[nt >> 1][(nt & 1) + 2];
                mma16816(acc[nt], af, bb);
            }
        }
    }

#pragma unroll
    for (int nt = 0; nt < 4; nt++) {
        int col = bn + wc * 32 + nt * 8 + 2 * cc;
        float b0 = bias ? bias[col] : 0.f;
        float b1 = bias ? bias[col + 1] : 0.f;
        int row0 = bm + wr * 16 + gr;
        int row1 = row0 + 8;
        if (row0 < M) {
            if (OM == 1) {
                Ch[(size_t)row0 * N + col]     = __float2half(acc[nt][0] + b0);
                Ch[(size_t)row0 * N + col + 1] = __float2half(acc[nt][1] + b1);
            } else {
                Cf[(size_t)row0 * N + col]     = acc[nt][0] + b0;
                Cf[(size_t)row0 * N + col + 1] = acc[nt][1] + b1;
            }
        }
        if (row1 < M) {
            if (OM == 1) {
                Ch[(size_t)row1 * N + col]     = __float2half(acc[nt][2] + b0);
                Ch[(size_t)row1 * N + col + 1] = __float2half(acc[nt][3] + b1);
            } else {
                Cf[(size_t)row1 * N + col]     = acc[nt][2] + b0;
                Cf[(size_t)row1 * N + col + 1] = acc[nt][3] + b1;
            }
        }
    }
}

// ---------------- fused gated cross-attention: Z + softmax@V (no P store) ----------------
// grid = (NH, NS/16). smem bytes:
//   Ks 2x20480 @0, Vs 2x20480 @40960, Ghs 2x8448 @81920, Qs 1280 @98816,
//   Hs 2048 @100096, Zs 64 @102144 -> total 102208
#define CA_SMEM 102208
__global__ __launch_bounds__(256) void ca_fused_kernel()
{
    extern __shared__ __align__(16) char smraw[];
    __half* Ks  = (__half*)smraw;
    __half* Vs  = (__half*)(smraw + 40960);
    __half* Ghs = (__half*)(smraw + 81920);
    __half* Qs  = (__half*)(smraw + 98816);
    float*  Hs  = (float*)(smraw + 100096);
    float*  Zs  = (float*)(smraw + 102144);

    const int h = blockIdx.x;
    const int s0 = blockIdx.y * 16;
    const int tid = threadIdx.x;
    const int w = tid >> 5, lane = tid & 31;
    const int gr = lane >> 2, cc = lane & 3;
    const int cw = w * 32;
    const int l4 = lane & 15;

    auto issue_tile = [&](int ci) {
        int buf = (ci & 1) * 10240;
        int gbuf = (ci & 1) * 4224;
        int c0 = ci * 256;
        int pr = tid >> 2, pp4 = tid & 3;
#pragma unroll
        for (int rr = 0; rr < 4; rr++) {
            int row = rr * 64 + pr;
            size_t src = (size_t)(c0 + row) * D + h * 32 + pp4 * 8;
            cpa16(&Ks[buf + row * 40 + pp4 * 8], &g_Kh[src]);
            cpa16(&Vs[buf + row * 40 + pp4 * 8], &g_Vh[src]);
        }
#pragma unroll
        for (int t = 0; t < 2; t++) {
            int idx = t * 256 + tid;
            int r = idx >> 5, pp = idx & 31;
            cpa16(&Ghs[gbuf + r * 264 + pp * 8], &g_Gh[(size_t)(s0 + r) * NC + c0 + pp * 8]);
        }
        asm volatile("cp.async.commit_group;");
    };

    {
        int row = tid >> 4, c2 = (tid & 15) * 2;
        *(unsigned*)&Qs[row * 40 + c2] =
            *(const unsigned*)&g_Qh[(size_t)(s0 + row) * D + h * 32 + c2];
    }
    Hs[tid] = 0.f;
    Hs[tid + 256] = 0.f;
    if (tid < 16) Zs[tid] = 0.f;

    issue_tile(0);
    __syncthreads();

    unsigned qa[2][4];
    {
        int qrow = lane & 15;
        int qcol = (lane >> 4) * 8;
#pragma unroll
        for (int ks = 0; ks < 2; ks++)
            ldm_x4(qa[ks], smaddr(&Qs[qrow * 40 + ks * 16 + qcol]));
    }

    float hacc[4][4] = {};
    float zacc0 = 0.f, zacc1 = 0.f;

    for (int ci = 0; ci < 16; ci++) {
        int buf = (ci & 1) * 10240;
        int gbuf = (ci & 1) * 4224;
        if (ci < 15) issue_tile(ci + 1);

        if (ci < 15) asm volatile("cp.async.wait_group 1;" ::: "memory");
        else         asm volatile("cp.async.wait_group 0;" ::: "memory");
        __syncthreads();

        unsigned pa[2][4];
#pragma unroll
        for (int nt = 0; nt < 4; nt++) {
            float S[4] = {0.f, 0.f, 0.f, 0.f};
#pragma unroll
            for (int ks = 0; ks < 2; ks++) {
                unsigned b[2];
                ldm_x2(b[0], b[1],
                       smaddr(&Ks[buf + (cw + nt * 8 + (l4 & 7)) * 40 + ks * 16 + (l4 >> 3) * 8]));
                mma16816(S, qa[ks], b);
            }
            // gate fragment via ldmatrix (matches C-fragment layout)
            unsigned gf0, gf1;
            ldm_x2(gf0, gf1, smaddr(&Ghs[gbuf + l4 * 264 + cw + nt * 8]));
            __half2 x01 = __hmul2(__floats2half2_rn(S[0], S[1]), *(__half2*)&gf0);
            __half2 x23 = __hmul2(__floats2half2_rn(S[2], S[3]), *(__half2*)&gf1);
            __half2 p01 = h2ex2(x01);
            __half2 p23 = h2ex2(x23);
            float2 f01 = __half22float2(p01);
            float2 f23 = __half22float2(p23);
            zacc0 += f01.x + f01.y;
            zacc1 += f23.x + f23.y;
            unsigned u01 = *(unsigned*)&p01, u23 = *(unsigned*)&p23;
            if ((nt & 1) == 0) { pa[nt >> 1][0] = u01; pa[nt >> 1][1] = u23; }
            else               { pa[nt >> 1][2] = u01; pa[nt >> 1][3] = u23; }
        }

#pragma unroll
        for (int nt2 = 0; nt2 < 4; nt2++) {
#pragma unroll
            for (int ks2 = 0; ks2 < 2; ks2++) {
                unsigned b[2];
                ldm_x2_t(b[0], b[1],
                         smaddr(&Vs[buf + (cw + ks2 * 16 + l4) * 40 + nt2 * 8]));
                mma16816(hacc[nt2], pa[ks2], b);
            }
        }
        __syncthreads();
    }

#pragma unroll
    for (int o = 1; o < 4; o <<= 1) {
        zacc0 += __shfl_xor_sync(0xffffffffu, zacc0, o);
        zacc1 += __shfl_xor_sync(0xffffffffu, zacc1, o);
    }
    if (cc == 0) {
        atomicAdd(&Zs[gr], zacc0);
        atomicAdd(&Zs[gr + 8], zacc1);
    }
#pragma unroll
    for (int nt2 = 0; nt2 < 4; nt2++) {
        atomicAdd(&Hs[gr * 32 + nt2 * 8 + 2 * cc],           hacc[nt2][0]);
        atomicAdd(&Hs[gr * 32 + nt2 * 8 + 2 * cc + 1],       hacc[nt2][1]);
        atomicAdd(&Hs[(gr + 8) * 32 + nt2 * 8 + 2 * cc],     hacc[nt2][2]);
        atomicAdd(&Hs[(gr + 8) * 32 + nt2 * 8 + 2 * cc + 1], hacc[nt2][3]);
    }
    __syncthreads();
    if (tid < 16) g_Z[(s0 + tid) * NH + h] = Zs[tid];
#pragma unroll
    for (int k = 0; k < 2; k++) {
        int idx = k * 256 + tid;
        int row = idx >> 5, d = idx & 31;
        g_Hnew[(size_t)(s0 + row) * D + h * 32 + d] = Hs[idx] / Zs[row];
    }
}

// ---------------- attn_map by QK recompute ----------------
// smem: Ks 67584 @0, Qs 8448 @67584, Ghs 4352 @76032, AMs 8448 @80384, iZ 512 @88832
#define AT_SMEM 89344
__global__ __launch_bounds__(256) void attn_recompute_kernel(float* __restrict__ AM)
{
    extern __shared__ __align__(16) char smraw[];
    __half* Ks  = (__half*)smraw;
    __half* Qs  = (__half*)(smraw + 67584);
    __half* Ghs = (__half*)(smraw + 76032);
    float*  AMs = (float*)(smraw + 80384);
    float*  iZ  = (float*)(smraw + 88832);

    const int c0 = blockIdx.x * 128;
    const int s0 = blockIdx.y * 16;
    const int tid = threadIdx.x;
    const int w = tid >> 5, lane = tid & 31;
    const int gr = lane >> 2, cc = lane & 3;
    const int l4 = lane & 15;
    const int hi8 = (lane >> 4) * 8;
    const int cw16 = w * 16;

#pragma unroll
    for (int t = 0; t < 16; t++) {
        int idx = t * 256 + tid;
        int r = idx >> 5, pp = idx & 31;
        cpa16(&Ks[r * 264 + pp * 8], &g_Kh[(size_t)(c0 + r) * D + pp * 8]);
    }
#pragma unroll
    for (int t = 0; t < 2; t++) {
        int idx = t * 256 + tid;
        int r = idx >> 5, pp = idx & 31;
        cpa16(&Qs[r * 264 + pp * 8], &g_Qh[(size_t)(s0 + r) * D + pp * 8]);
    }
    {
        int r = tid >> 4, pp = tid & 15;
        cpa16(&Ghs[r * 136 + pp * 8], &g_Gh[(size_t)(s0 + r) * NC + c0 + pp * 8]);
    }
    asm volatile("cp.async.commit_group;");
    if (tid < 128) {
        int s = tid >> 3, hh = tid & 7;
        iZ[tid] = 0.125f / g_Z[(s0 + s) * NH + hh];
    }
    asm volatile("cp.async.wait_group 0;" ::: "memory");
    __syncthreads();

    // gate fragments (constant across heads)
    unsigned gfr[2][2];
#pragma unroll
    for (int nt = 0; nt < 2; nt++)
        ldm_x2(gfr[nt][0], gfr[nt][1], smaddr(&Ghs[l4 * 136 + cw16 + nt * 8]));

    float acc[2][4] = {};
#pragma unroll
    for (int h = 0; h < NH; h++) {
        unsigned qa[2][4];
#pragma unroll
        for (int ks = 0; ks < 2; ks++)
            ldm_x4(qa[ks], smaddr(&Qs[l4 * 264 + h * 32 + ks * 16 + hi8]));
        unsigned kb[2][4];
#pragma unroll
        for (int ks = 0; ks < 2; ks++)
            ldm_x4(kb[ks], smaddr(&Ks[(cw16 + l4) * 264 + h * 32 + ks * 16 + hi8]));
        float izA = iZ[gr * 8 + h];
        float izB = iZ[(gr + 8) * 8 + h];
#pragma unroll
        for (int nt = 0; nt < 2; nt++) {
            float S[4] = {0.f, 0.f, 0.f, 0.f};
#pragma unroll
            for (int ks = 0; ks < 2; ks++) {
                unsigned bb[2];
                bb[0] = kb[ks][nt];
                bb[1] = kb[ks][nt + 2];
                mma16816(S, qa[ks], bb);
            }
            __half2 x01 = __hmul2(__floats2half2_rn(S[0], S[1]), *(__half2*)&gfr[nt][0]);
            __half2 x23 = __hmul2(__floats2half2_rn(S[2], S[3]), *(__half2*)&gfr[nt][1]);
            float2 f01 = __half22float2(h2ex2(x01));
            float2 f23 = __half22float2(h2ex2(x23));
            acc[nt][0] += f01.x * izA;
            acc[nt][1] += f01.y * izA;
            acc[nt][2] += f23.x * izB;
            acc[nt][3] += f23.y * izB;
        }
    }

#pragma unroll
    for (int nt = 0; nt < 2; nt++) {
        int col = cw16 + nt * 8 + 2 * cc;
        *(float2*)&AMs[gr * 132 + col]       = make_float2(acc[nt][0], acc[nt][1]);
        *(float2*)&AMs[(gr + 8) * 132 + col] = make_float2(acc[nt][2], acc[nt][3]);
    }
    __syncthreads();
#pragma unroll
    for (int t = 0; t < 2; t++) {
        int idx = t * 256 + tid;
        int r = idx >> 5, p4 = idx & 31;
        *(float4*)&AM[(size_t)(s0 + r) * NC + c0 + p4 * 4] = *(const float4*)&AMs[r * 132 + p4 * 4];
    }
}

// ---------------- cross-attn epilogue LN ----------------
__global__ __launch_bounds__(256) void ln_ca_kernel(
    const float* __restrict__ g, const float* __restrict__ b, const float* __restrict__ fusion)
{
    int tid = threadIdx.x;
    if (blockIdx.x == 0 && tid < D) g_tok[tid] = fusion[tid];
    int warp = tid >> 5, lane = tid & 31;
    int row = blockIdx.x * 8 + warp;
    float x[8];
    float s = 0.f;
#pragma unroll
    for (int j = 0; j < 8; j++) {
        int c = lane + 32 * j;
        x[j] = g_tmp[(size_t)row * D + c] + g_HS[(size_t)row * D + c];
        s += x[j];
    }
    s = warpSum(s);
    float m = s * (1.0f / D);
    float vs = 0.f;
#pragma unroll
    for (int j = 0; j < 8; j++) { float d = x[j] - m; vs += d * d; }
    vs = warpSum(vs);
    float r = rsqrtf(vs * (1.0f / D) + 1e-5f);
#pragma unroll
    for (int j = 0; j < 8; j++) {
        int c = lane + 32 * j;
        g_tok[(size_t)(1 + row) * D + c] = (x[j] - m) * r * g[c] + b[c];
    }
}

// ---------------- q0 = fusion @ Wq.T + bq ----------------
__global__ void q0_kernel(const float* __restrict__ fusion,
                          const float* __restrict__ w, const float* __restrict__ bqkv)
{
    __shared__ float fs[D];
    int tid = threadIdx.x;
    fs[tid] = fusion[tid];
    __syncthreads();
    float a = bqkv[tid];
    for (int c = 0; c < D; c++) a += fs[c] * w[(size_t)tid * D + c];
    g_q0[tid] = a;
}

// ---------------- row-0 scores over tokens ----------------
__global__ __launch_bounds__(256) void score0_kernel()
{
    __shared__ float q0s[D];
    __shared__ float zpart[NH];
    int tid = threadIdx.x;
    if (tid < D) q0s[tid] = g_q0[tid];
    if (tid < NH) zpart[tid] = 0.f;
    __syncthreads();
    int warp = tid >> 5, lane = tid & 31;
    int wtotal = gridDim.x * 8;
    const float isq = 0.17677669529663687f;
    for (int u = blockIdx.x * 8 + warp; u < TT; u += wtotal) {
        float mine = 0.f;
#pragma unroll
        for (int j = 0; j < 8; j++) {
            int c = lane + 32 * j;
            float v = q0s[c] * g_k2[(size_t)u * D + c];
            v = warpSum(v);
            if (lane == j) mine = v;
        }
        if (lane < 8) {
            float p = __expf(mine * isq);
            g_p0[u * NH + lane] = p;
            atomicAdd(&zpart[lane], p);
        }
    }
    __syncthreads();
    if (tid < NH) atomicAdd(&g_Z0[tid], zpart[tid]);
}

// ---------------- row-0 AV ----------------
__global__ __launch_bounds__(256) void av0_kernel()
{
    int col = threadIdx.x;
    int h = col >> 5;
    int u0 = blockIdx.x * 257;
    int u1 = u0 + 257; if (u1 > TT) u1 = TT;
    float acc = 0.f;
    for (int u = u0; u < u1; u++)
        acc += g_p0[u * NH + h] * g_v2[(size_t)u * D + col];
    atomicAdd(&g_a0[col], acc);
}

// ---------------- final head ----------------
__device__ __forceinline__ float blockSum256(float v, volatile float* red) {
    int lane = threadIdx.x & 31, w = threadIdx.x >> 5;
    v = warpSum(v);
    __syncthreads();
    if (lane == 0) red[w] = v;
    __syncthreads();
    float s = 0.f;
#pragma unroll
    for (int i = 0; i < 8; i++) s += red[i];
    return s;
}

__global__ __launch_bounds__(256) void final_kernel(
    const float* __restrict__ fusion,
    const float* __restrict__ mow, const float* __restrict__ mob,
    const float* __restrict__ ln1g, const float* __restrict__ ln1b,
    const float* __restrict__ w1, const float* __restrict__ b1,
    const float* __restrict__ w2, const float* __restrict__ b2,
    const float* __restrict__ ln2g, const float* __restrict__ ln2b,
    float* __restrict__ out)
{
    __shared__ float a0[D], t1[D], h1[2 * D];
    __shared__ float red[8];
    int tid = threadIdx.x;
    a0[tid] = g_a0[tid] / g_Z0[tid >> 5];
    __syncthreads();
    float y = mob[tid];
    for (int j = 0; j < D; j++) y += a0[j] * mow[(size_t)tid * D + j];
    float tv = fusion[tid] + y;
    float m = blockSum256(tv, red) * (1.0f / D);
    float d = tv - m;
    float var = blockSum256(d * d, red) * (1.0f / D);
    float t = d * rsqrtf(var + 1e-5f) * ln1g[tid] + ln1b[tid];
    t1[tid] = t;
    __syncthreads();
    float hh[2];
#pragma unroll
    for (int r2 = 0; r2 < 2; r2++) {
        int jj = tid + r2 * 256;
        float a = b1[jj];
        for (int c = 0; c < D; c++) a += t1[c] * w1[(size_t)jj * D + c];
        hh[r2] = a * 0.5f * (1.f + erff(a * 0.70710678118654752f));
    }
    h1[tid] = hh[0];
    h1[tid + 256] = hh[1];
    __syncthreads();
    float o = b2[tid];
    for (int j = 0; j < 512; j++) o += h1[j] * w2[(size_t)tid * 512 + j];
    float t2v = t1[tid] + o;   // residual = LN1 output
    float m2 = blockSum256(t2v, red) * (1.0f / D);
    float d2 = t2v - m2;
    float v2 = blockSum256(d2 * d2, red) * (1.0f / D);
    out[tid] = d2 * rsqrtf(v2 + 1e-5f) * ln2g[tid] + ln2b[tid];
}

// ---------------- launcher ----------------
extern "C" void kernel_launch(void* const* d_in, const int* in_sizes, int n_in,
                              void* d_out, int out_size)
{
    const float* H_S     = (const float*)d_in[0];
    const float* H_C     = (const float*)d_in[1];
    const float* H_G     = (const float*)d_in[2];
    const float* G_glyph = (const float*)d_in[3];
    const float* Ws      = (const float*)d_in[4];
    const float* bs      = (const float*)d_in[5];
    const float* Wb      = (const float*)d_in[6];
    const float* bb      = (const float*)d_in[7];
    const float* Wg      = (const float*)d_in[8];
    const float* bg      = (const float*)d_in[9];
    const float* WQ      = (const float*)d_in[10];
    const float* WK      = (const float*)d_in[11];
    const float* WV      = (const float*)d_in[12];
    const float* WO      = (const float*)d_in[13];
    const float* bO      = (const float*)d_in[14];
    const float* ln_ca_g = (const float*)d_in[15];
    const float* ln_ca_b = (const float*)d_in[16];
    const float* fusion  = (const float*)d_in[17];
    const float* mha_in_w  = (const float*)d_in[18];
    const float* mha_in_b  = (const float*)d_in[19];
    const float* mha_out_w = (const float*)d_in[20];
    const float* mha_out_b = (const float*)d_in[21];
    const float* ln1_g   = (const float*)d_in[22];
    const float* ln1_b   = (const float*)d_in[23];
    const float* ln2_g   = (const float*)d_in[24];
    const float* ln2_b   = (const float*)d_in[25];
    const float* ffn_w1  = (const float*)d_in[26];
    const float* ffn_b1  = (const float*)d_in[27];
    const float* ffn_w2  = (const float*)d_in[28];
    const float* ffn_b2  = (const float*)d_in[29];

    float* out = (float*)d_out;
    float* z_fused  = out;        // 256
    float* attn_map = out + D;    // 2048 * 4096

    float *pHS, *pHC, *pHnew, *pTmp, *pTok, *pk2, *pv2;
    __half *pQh, *pKh, *pVh, *pGh;
    cudaGetSymbolAddress((void**)&pHS,  g_HS);
    cudaGetSymbolAddress((void**)&pHC,  g_HC);
    cudaGetSymbolAddress((void**)&pQh,  g_Qh);
    cudaGetSymbolAddress((void**)&pKh,  g_Kh);
    cudaGetSymbolAddress((void**)&pVh,  g_Vh);
    cudaGetSymbolAddress((void**)&pGh,  g_Gh);
    cudaGetSymbolAddress((void**)&pHnew,g_Hnew);
    cudaGetSymbolAddress((void**)&pTmp, g_tmp);
    cudaGetSymbolAddress((void**)&pTok, g_tok);
    cudaGetSymbolAddress((void**)&pk2,  g_k2);
    cudaGetSymbolAddress((void**)&pv2,  g_v2);

    static bool attrSet = false;
    if (!attrSet) {
        cudaFuncSetAttribute(ca_fused_kernel,
                             cudaFuncAttributeMaxDynamicSharedMemorySize, CA_SMEM);
        cudaFuncSetAttribute(attn_recompute_kernel,
                             cudaFuncAttributeMaxDynamicSharedMemorySize, AT_SMEM);
        attrSet = true;
    }

    // #1 HS projection + (z=1 slice) gate fp16 conversion
    gemm16_kernel<0><<<dim3(4, 32, 2), 256>>>(
        H_S, Ws, bs, pHS, nullptr, NS,
        H_S, Ws, bs, pHS, nullptr, NS,
        H_S, Ws, bs, pHS, nullptr, NS, D, 128, G_glyph, pGh);
    // #2 HC projection
    gemm16_kernel<0><<<dim3(4, 64), 256>>>(
        H_C, Wb, bb, pHC, nullptr, NC,
        H_C, Wb, bb, pHC, nullptr, NC,
        H_C, Wb, bb, pHC, nullptr, NC, D, 256, nullptr, nullptr);
    // #3 Q/K/V triple (fp16 out)
    gemm16_kernel<1><<<dim3(4, 64, 3), 256>>>(
        pHS, WQ, nullptr, nullptr, pQh, NS,
        pHC, WK, nullptr, nullptr, pKh, NC,
        pHC, WV, nullptr, nullptr, pVh, NC, D, 256, nullptr, nullptr);
    // #4 fused gated cross attention (Z + Hnew)  <-- ncu capture target
    ca_fused_kernel<<<dim3(NH, NS / 16), 256, CA_SMEM>>>();
    // #5 HG projection into token slots
    gemm16_kernel<0><<<dim3(4, 32), 256>>>(
        H_G, Wg, bg, pTok + (size_t)(1 + NS) * D, nullptr, NG,
        H_G, Wg, bg, pTok + (size_t)(1 + NS) * D, nullptr, NG,
        H_G, Wg, bg, pTok + (size_t)(1 + NS) * D, nullptr, NG, D, 64, nullptr, nullptr);
    // #6 attn_map via QK recompute (needs g_Z)
    attn_recompute_kernel<<<dim3(NC / 128, NS / 16), 256, AT_SMEM>>>(attn_map);
    // O projection + residual LN -> tokens
    gemm16_kernel<0><<<dim3(4, 32), 256>>>(
        pHnew, WO, bO, pTmp, nullptr, NS,
        pHnew, WO, bO, pTmp, nullptr, NS,
        pHnew, WO, bO, pTmp, nullptr, NS, D, 256, nullptr, nullptr);
    ln_ca_kernel<<<NS / 8, 256>>>(ln_ca_g, ln_ca_b, fusion);
    // self-attn K/V over tokens (dual)
    gemm16_kernel<0><<<dim3(4, 65, 2), 256>>>(
        pTok, mha_in_w + 256 * 256, mha_in_b + 256, pk2, nullptr, TT,
        pTok, mha_in_w + 512 * 256, mha_in_b + 512, pv2, nullptr, TT,
        pTok, mha_in_w + 256 * 256, mha_in_b + 256, pk2, nullptr, TT, D, 256, nullptr, nullptr);
    // token-0 attention + head
    zero_kernel<<<1, 256>>>();
    q0_kernel<<<1, 256>>>(fusion, mha_in_w, mha_in_b);
    score0_kernel<<<32, 256>>>();
    av0_kernel<<<16, 256>>>();
    final_kernel<<<1, 256>>>(fusion, mha_out_w, mha_out_b, ln1_g, ln1_b,
                             ffn_w1, ffn_b1, ffn_w2, ffn_b2, ln2_g, ln2_b, z_fused);
}

// round 9
// speedup vs baseline: 2.6131x; 1.0623x over previous
#include <cuda_runtime.h>
#include <cuda_fp16.h>

#define NS 2048
#define NC 4096
#define NG 2048
#define D  256
#define NH 8
#define TT 4097   // 1 + NS + NG

// ---------------- device scratch ----------------
__device__ float  g_HS[NS * D];
__device__ float  g_HC[NC * D];
__device__ __half g_Qh[NS * D];
__device__ __half g_Kh[NC * D];
__device__ __half g_Vh[NC * D];
__device__ __half g_Gh[(size_t)NS * NC];   // gate * (isq*log2e), fp16
__device__ float  g_Z[NS * NH];
__device__ float  g_Hnew[NS * D];
__device__ float  g_tmp[NS * D];
__device__ float  g_tok[TT * D];
__device__ float  g_k2[TT * D];
__device__ float  g_v2[TT * D];
__device__ float  g_q0[D];
__device__ float  g_p0[TT * NH];
__device__ float  g_Z0[NH];
__device__ float  g_a0[D];

__device__ __forceinline__ float warpSum(float v) {
#pragma unroll
    for (int o = 16; o; o >>= 1) v += __shfl_xor_sync(0xffffffffu, v, o);
    return v;
}

__device__ __forceinline__ void mma16816(float* c, const unsigned* a, const unsigned* b) {
    asm volatile(
        "mma.sync.aligned.m16n8k16.row.col.f32.f16.f16.f32 "
        "{%0,%1,%2,%3}, {%4,%5,%6,%7}, {%8,%9}, {%0,%1,%2,%3};\n"
        : "+f"(c[0]), "+f"(c[1]), "+f"(c[2]), "+f"(c[3])
        : "r"(a[0]), "r"(a[1]), "r"(a[2]), "r"(a[3]), "r"(b[0]), "r"(b[1]));
}

__device__ __forceinline__ unsigned smaddr(const void* p) {
    return (unsigned)__cvta_generic_to_shared(p);
}
__device__ __forceinline__ void ldm_x2(unsigned& r0, unsigned& r1, unsigned a) {
    asm volatile("ldmatrix.sync.aligned.m8n8.x2.shared.b16 {%0,%1}, [%2];"
                 : "=r"(r0), "=r"(r1) : "r"(a));
}
__device__ __forceinline__ void ldm_x2_t(unsigned& r0, unsigned& r1, unsigned a) {
    asm volatile("ldmatrix.sync.aligned.m8n8.x2.trans.shared.b16 {%0,%1}, [%2];"
                 : "=r"(r0), "=r"(r1) : "r"(a));
}
__device__ __forceinline__ void ldm_x4(unsigned* r, unsigned a) {
    asm volatile("ldmatrix.sync.aligned.m8n8.x4.shared.b16 {%0,%1,%2,%3}, [%4];"
                 : "=r"(r[0]), "=r"(r[1]), "=r"(r[2]), "=r"(r[3]) : "r"(a));
}
__device__ __forceinline__ void cpa16(void* smem, const void* gmem) {
    asm volatile("cp.async.cg.shared.global [%0], [%1], 16;"
                 :: "r"(smaddr(smem)), "l"(gmem));
}
__device__ __forceinline__ __half2 h2ex2(__half2 x) {
    unsigned r, xi = *(unsigned*)&x;
    asm("ex2.approx.f16x2 %0, %1;" : "=r"(r) : "r"(xi));
    return *(__half2*)&r;
}

#define CE 0.25506382f   // (1/sqrt(32)) * log2(e)

// ---------------- fp16 tensor-core GEMM (up to 3 problems via blockIdx.z) ----------------
// Optionally the LAST z-slice converts G fp32 -> fp16*CE instead (gsrc != null).
template<int OM>
__global__ __launch_bounds__(256) void gemm16_kernel(
    const float* __restrict__ A0, const float* __restrict__ W0, const float* __restrict__ bs0,
    float* __restrict__ Cf0, __half* __restrict__ Ch0, int M0,
    const float* __restrict__ A1, const float* __restrict__ W1, const float* __restrict__ bs1,
    float* __restrict__ Cf1, __half* __restrict__ Ch1, int M1,
    const float* __restrict__ A2, const float* __restrict__ W2, const float* __restrict__ bs2,
    float* __restrict__ Cf2, __half* __restrict__ Ch2, int M2,
    int N, int K,
    const float* __restrict__ gsrc, __half* __restrict__ gdst)
{
    if (gsrc != nullptr && blockIdx.z == gridDim.z - 1) {
        int bid = blockIdx.y * gridDim.x + blockIdx.x;
        int t4 = bid * 256 + threadIdx.x;
        const int total4 = (NS * NC) / 4;
        int stride = gridDim.x * gridDim.y * 256;
        for (int i = t4; i < total4; i += stride) {
            float4 v = *(const float4*)&gsrc[(size_t)i * 4];
            __half2 h0 = __floats2half2_rn(v.x * CE, v.y * CE);
            __half2 h1 = __floats2half2_rn(v.z * CE, v.w * CE);
            *(int2*)&gdst[(size_t)i * 4] = make_int2(*(int*)&h0, *(int*)&h1);
        }
        return;
    }

    const int z = blockIdx.z;
    const float* A    = z == 0 ? A0  : (z == 1 ? A1  : A2);
    const float* W    = z == 0 ? W0  : (z == 1 ? W1  : W2);
    const float* bias = z == 0 ? bs0 : (z == 1 ? bs1 : bs2);
    float* Cf         = z == 0 ? Cf0 : (z == 1 ? Cf1 : Cf2);
    __half* Ch        = z == 0 ? Ch0 : (z == 1 ? Ch1 : Ch2);
    const int M       = z == 0 ? M0  : (z == 1 ? M1  : M2);

    const int bm = blockIdx.y * 64, bn = blockIdx.x * 64;
    if (bm >= M) return;

    __shared__ __half Ah[64 * 40];
    __shared__ __half Bh[64 * 40];

    const int tid = threadIdx.x;
    const int w = tid >> 5, lane = tid & 31;
    const int wr = w >> 1, wc = w & 1;
    const int gr = lane >> 2, cc = lane & 3;
    const int fr = tid >> 2, fc8 = (tid & 3) * 8;
    const int l4 = lane & 15;
    const int hi8 = (lane >> 4) * 8;

    float acc[4][4] = {};

    for (int k0 = 0; k0 < K; k0 += 32) {
        __syncthreads();
        {
            float4 a0v = make_float4(0.f, 0.f, 0.f, 0.f), a1v = a0v;
            if (bm + fr < M) {
                const float* ap = &A[(size_t)(bm + fr) * K + k0 + fc8];
                a0v = *(const float4*)ap;
                a1v = *(const float4*)(ap + 4);
            }
            __half2 h0 = __floats2half2_rn(a0v.x, a0v.y);
            __half2 h1 = __floats2half2_rn(a0v.z, a0v.w);
            __half2 h2 = __floats2half2_rn(a1v.x, a1v.y);
            __half2 h3 = __floats2half2_rn(a1v.z, a1v.w);
            int4 pk = make_int4(*(int*)&h0, *(int*)&h1, *(int*)&h2, *(int*)&h3);
            *(int4*)&Ah[fr * 40 + fc8] = pk;

            const float* wp = &W[(size_t)(bn + fr) * K + k0 + fc8];
            float4 b0v = *(const float4*)wp;
            float4 b1v = *(const float4*)(wp + 4);
            __half2 g0 = __floats2half2_rn(b0v.x, b0v.y);
            __half2 g1 = __floats2half2_rn(b0v.z, b0v.w);
            __half2 g2 = __floats2half2_rn(b1v.x, b1v.y);
            __half2 g3 = __floats2half2_rn(b1v.z, b1v.w);
            int4 pk2 = make_int4(*(int*)&g0, *(int*)&g1, *(int*)&g2, *(int*)&g3);
            *(int4*)&Bh[fr * 40 + fc8] = pk2;
        }
        __syncthreads();

#pragma unroll
        for (int ks = 0; ks < 2; ks++) {
            unsigned af[4];
            ldm_x4(af, smaddr(&Ah[(wr * 16 + l4) * 40 + ks * 16 + hi8]));
            unsigned bf[2][4];
#pragma unroll
            for (int p = 0; p < 2; p++)
                ldm_x4(bf[p], smaddr(&Bh[(wc * 32 + p * 16 + l4) * 40 + ks * 16 + hi8]));
#pragma unroll
            for (int nt = 0; nt < 4; nt++) {
                unsigned bb[2];
                bb[0] = bf[nt >> 1][(nt & 1)];
                bb[1] = bf[nt >> 1][(nt & 1) + 2];
                mma16816(acc[nt], af, bb);
            }
        }
    }

#pragma unroll
    for (int nt = 0; nt < 4; nt++) {
        int col = bn + wc * 32 + nt * 8 + 2 * cc;
        float b0 = bias ? bias[col] : 0.f;
        float b1 = bias ? bias[col + 1] : 0.f;
        int row0 = bm + wr * 16 + gr;
        int row1 = row0 + 8;
        if (row0 < M) {
            if (OM == 1) {
                Ch[(size_t)row0 * N + col]     = __float2half(acc[nt][0] + b0);
                Ch[(size_t)row0 * N + col + 1] = __float2half(acc[nt][1] + b1);
            } else {
                Cf[(size_t)row0 * N + col]     = acc[nt][0] + b0;
                Cf[(size_t)row0 * N + col + 1] = acc[nt][1] + b1;
            }
        }
        if (row1 < M) {
            if (OM == 1) {
                Ch[(size_t)row1 * N + col]     = __float2half(acc[nt][2] + b0);
                Ch[(size_t)row1 * N + col + 1] = __float2half(acc[nt][3] + b1);
            } else {
                Cf[(size_t)row1 * N + col]     = acc[nt][2] + b0;
                Cf[(size_t)row1 * N + col + 1] = acc[nt][3] + b1;
            }
        }
    }
}

// ---------------- fused gated cross-attention: 32 s-rows per block ----------------
// grid = (NH, NS/32). smem bytes:
//   Ks 2x20480 @0, Vs 2x20480 @40960, Ghs 16896 @81920 (single buffer),
//   Qs 2560 @98816, Hs 4096 @101376, Zs 128 @105472 -> total 105600
#define CA_SMEM 105600
__global__ __launch_bounds__(256, 2) void ca_fused_kernel()
{
    extern __shared__ __align__(16) char smraw[];
    __half* Ks  = (__half*)smraw;
    __half* Vs  = (__half*)(smraw + 40960);
    __half* Ghs = (__half*)(smraw + 81920);
    __half* Qs  = (__half*)(smraw + 98816);
    float*  Hs  = (float*)(smraw + 101376);
    float*  Zs  = (float*)(smraw + 105472);

    const int h = blockIdx.x;
    const int s0 = blockIdx.y * 32;
    const int tid = threadIdx.x;
    const int w = tid >> 5, lane = tid & 31;
    const int gr = lane >> 2, cc = lane & 3;
    const int cw = w * 32;
    const int l4 = lane & 15;

    auto issue_tile = [&](int ci) {
        int buf = (ci & 1) * 10240;
        int c0 = ci * 256;
        int pr = tid >> 2, pp4 = tid & 3;
#pragma unroll
        for (int rr = 0; rr < 4; rr++) {
            int row = rr * 64 + pr;
            size_t src = (size_t)(c0 + row) * D + h * 32 + pp4 * 8;
            cpa16(&Ks[buf + row * 40 + pp4 * 8], &g_Kh[src]);
            cpa16(&Vs[buf + row * 40 + pp4 * 8], &g_Vh[src]);
        }
        // gate: 32 rows x 256 halves (single buffer)
#pragma unroll
        for (int t = 0; t < 4; t++) {
            int idx = t * 256 + tid;
            int r = idx >> 5, pp = idx & 31;
            cpa16(&Ghs[r * 264 + pp * 8], &g_Gh[(size_t)(s0 + r) * NC + c0 + pp * 8]);
        }
        asm volatile("cp.async.commit_group;");
    };

    // Q tile: 32 rows x 32 halves
#pragma unroll
    for (int t = 0; t < 2; t++) {
        int idx = t * 256 + tid;
        int row = idx >> 4, c2 = (idx & 15) * 2;
        *(unsigned*)&Qs[row * 40 + c2] =
            *(const unsigned*)&g_Qh[(size_t)(s0 + row) * D + h * 32 + c2];
    }
#pragma unroll
    for (int k = 0; k < 4; k++) Hs[k * 256 + tid] = 0.f;
    if (tid < 32) Zs[tid] = 0.f;

    issue_tile(0);
    __syncthreads();

    unsigned qa[2][2][4];
#pragma unroll
    for (int sh = 0; sh < 2; sh++)
#pragma unroll
        for (int ks = 0; ks < 2; ks++)
            ldm_x4(qa[sh][ks], smaddr(&Qs[(sh * 16 + l4) * 40 + ks * 16 + (lane >> 4) * 8]));

    float hacc[2][4][4] = {};
    float zacc[2][2] = {};

    for (int ci = 0; ci < 16; ci++) {
        int buf = (ci & 1) * 10240;
        asm volatile("cp.async.wait_group 0;" ::: "memory");
        __syncthreads();

        // gate fragments into registers (single-buffered Ghs must be read before next issue)
        unsigned gf[2][4][2];
#pragma unroll
        for (int sh = 0; sh < 2; sh++)
#pragma unroll
            for (int nt = 0; nt < 4; nt++)
                ldm_x2(gf[sh][nt][0], gf[sh][nt][1],
                       smaddr(&Ghs[(sh * 16 + l4) * 264 + cw + nt * 8]));
        __syncthreads();
        if (ci < 15) issue_tile(ci + 1);

#pragma unroll
        for (int sh = 0; sh < 2; sh++) {
            unsigned pa[2][4];
#pragma unroll
            for (int nt = 0; nt < 4; nt++) {
                float S[4] = {0.f, 0.f, 0.f, 0.f};
#pragma unroll
                for (int ks = 0; ks < 2; ks++) {
                    unsigned b[2];
                    ldm_x2(b[0], b[1],
                           smaddr(&Ks[buf + (cw + nt * 8 + (l4 & 7)) * 40 + ks * 16 + (l4 >> 3) * 8]));
                    mma16816(S, qa[sh][ks], b);
                }
                __half2 x01 = __hmul2(__floats2half2_rn(S[0], S[1]), *(__half2*)&gf[sh][nt][0]);
                __half2 x23 = __hmul2(__floats2half2_rn(S[2], S[3]), *(__half2*)&gf[sh][nt][1]);
                __half2 p01 = h2ex2(x01);
                __half2 p23 = h2ex2(x23);
                float2 f01 = __half22float2(p01);
                float2 f23 = __half22float2(p23);
                zacc[sh][0] += f01.x + f01.y;
                zacc[sh][1] += f23.x + f23.y;
                unsigned u01 = *(unsigned*)&p01, u23 = *(unsigned*)&p23;
                if ((nt & 1) == 0) { pa[nt >> 1][0] = u01; pa[nt >> 1][1] = u23; }
                else               { pa[nt >> 1][2] = u01; pa[nt >> 1][3] = u23; }
            }
#pragma unroll
            for (int nt2 = 0; nt2 < 4; nt2++) {
#pragma unroll
                for (int ks2 = 0; ks2 < 2; ks2++) {
                    unsigned b[2];
                    ldm_x2_t(b[0], b[1],
                             smaddr(&Vs[buf + (cw + ks2 * 16 + l4) * 40 + nt2 * 8]));
                    mma16816(hacc[sh][nt2], pa[ks2], b);
                }
            }
        }
    }

#pragma unroll
    for (int sh = 0; sh < 2; sh++) {
        float z0 = zacc[sh][0], z1 = zacc[sh][1];
#pragma unroll
        for (int o = 1; o < 4; o <<= 1) {
            z0 += __shfl_xor_sync(0xffffffffu, z0, o);
            z1 += __shfl_xor_sync(0xffffffffu, z1, o);
        }
        if (cc == 0) {
            atomicAdd(&Zs[sh * 16 + gr], z0);
            atomicAdd(&Zs[sh * 16 + gr + 8], z1);
        }
#pragma unroll
        for (int nt2 = 0; nt2 < 4; nt2++) {
            atomicAdd(&Hs[(sh * 16 + gr) * 32 + nt2 * 8 + 2 * cc],           hacc[sh][nt2][0]);
            atomicAdd(&Hs[(sh * 16 + gr) * 32 + nt2 * 8 + 2 * cc + 1],       hacc[sh][nt2][1]);
            atomicAdd(&Hs[(sh * 16 + gr + 8) * 32 + nt2 * 8 + 2 * cc],       hacc[sh][nt2][2]);
            atomicAdd(&Hs[(sh * 16 + gr + 8) * 32 + nt2 * 8 + 2 * cc + 1],   hacc[sh][nt2][3]);
        }
    }
    __syncthreads();
    if (tid < 32) g_Z[(s0 + tid) * NH + h] = Zs[tid];
#pragma unroll
    for (int k = 0; k < 4; k++) {
        int idx = k * 256 + tid;
        int row = idx >> 5, d = idx & 31;
        g_Hnew[(size_t)(s0 + row) * D + h * 32 + d] = Hs[idx] / Zs[row];
    }
}

// ---------------- attn_map by QK recompute ----------------
// smem: Ks 67584 @0, Qs 8448 @67584, Ghs 4352 @76032, AMs 8448 @80384, iZ 512 @88832
#define AT_SMEM 89344
__global__ __launch_bounds__(256) void attn_recompute_kernel(float* __restrict__ AM)
{
    extern __shared__ __align__(16) char smraw[];
    __half* Ks  = (__half*)smraw;
    __half* Qs  = (__half*)(smraw + 67584);
    __half* Ghs = (__half*)(smraw + 76032);
    float*  AMs = (float*)(smraw + 80384);
    float*  iZ  = (float*)(smraw + 88832);

    const int c0 = blockIdx.x * 128;
    const int s0 = blockIdx.y * 16;
    const int tid = threadIdx.x;
    const int w = tid >> 5, lane = tid & 31;
    const int gr = lane >> 2, cc = lane & 3;
    const int l4 = lane & 15;
    const int hi8 = (lane >> 4) * 8;
    const int cw16 = w * 16;

#pragma unroll
    for (int t = 0; t < 16; t++) {
        int idx = t * 256 + tid;
        int r = idx >> 5, pp = idx & 31;
        cpa16(&Ks[r * 264 + pp * 8], &g_Kh[(size_t)(c0 + r) * D + pp * 8]);
    }
#pragma unroll
    for (int t = 0; t < 2; t++) {
        int idx = t * 256 + tid;
        int r = idx >> 5, pp = idx & 31;
        cpa16(&Qs[r * 264 + pp * 8], &g_Qh[(size_t)(s0 + r) * D + pp * 8]);
    }
    {
        int r = tid >> 4, pp = tid & 15;
        cpa16(&Ghs[r * 136 + pp * 8], &g_Gh[(size_t)(s0 + r) * NC + c0 + pp * 8]);
    }
    asm volatile("cp.async.commit_group;");
    if (tid < 128) {
        int s = tid >> 3, hh = tid & 7;
        iZ[tid] = 0.125f / g_Z[(s0 + s) * NH + hh];
    }
    asm volatile("cp.async.wait_group 0;" ::: "memory");
    __syncthreads();

    unsigned gfr[2][2];
#pragma unroll
    for (int nt = 0; nt < 2; nt++)
        ldm_x2(gfr[nt][0], gfr[nt][1], smaddr(&Ghs[l4 * 136 + cw16 + nt * 8]));

    float acc[2][4] = {};
#pragma unroll
    for (int h = 0; h < NH; h++) {
        unsigned qa[2][4];
#pragma unroll
        for (int ks = 0; ks < 2; ks++)
            ldm_x4(qa[ks], smaddr(&Qs[l4 * 264 + h * 32 + ks * 16 + hi8]));
        unsigned kb[2][4];
#pragma unroll
        for (int ks = 0; ks < 2; ks++)
            ldm_x4(kb[ks], smaddr(&Ks[(cw16 + l4) * 264 + h * 32 + ks * 16 + hi8]));
        float izA = iZ[gr * 8 + h];
        float izB = iZ[(gr + 8) * 8 + h];
#pragma unroll
        for (int nt = 0; nt < 2; nt++) {
            float S[4] = {0.f, 0.f, 0.f, 0.f};
#pragma unroll
            for (int ks = 0; ks < 2; ks++) {
                unsigned bb[2];
                bb[0] = kb[ks][nt];
                bb[1] = kb[ks][nt + 2];
                mma16816(S, qa[ks], bb);
            }
            __half2 x01 = __hmul2(__floats2half2_rn(S[0], S[1]), *(__half2*)&gfr[nt][0]);
            __half2 x23 = __hmul2(__floats2half2_rn(S[2], S[3]), *(__half2*)&gfr[nt][1]);
            float2 f01 = __half22float2(h2ex2(x01));
            float2 f23 = __half22float2(h2ex2(x23));
            acc[nt][0] += f01.x * izA;
            acc[nt][1] += f01.y * izA;
            acc[nt][2] += f23.x * izB;
            acc[nt][3] += f23.y * izB;
        }
    }

#pragma unroll
    for (int nt = 0; nt < 2; nt++) {
        int col = cw16 + nt * 8 + 2 * cc;
        *(float2*)&AMs[gr * 132 + col]       = make_float2(acc[nt][0], acc[nt][1]);
        *(float2*)&AMs[(gr + 8) * 132 + col] = make_float2(acc[nt][2], acc[nt][3]);
    }
    __syncthreads();
#pragma unroll
    for (int t = 0; t < 2; t++) {
        int idx = t * 256 + tid;
        int r = idx >> 5, p4 = idx & 31;
        *(float4*)&AM[(size_t)(s0 + r) * NC + c0 + p4 * 4] = *(const float4*)&AMs[r * 132 + p4 * 4];
    }
}

// ---------------- cross-attn epilogue LN ----------------
__global__ __launch_bounds__(256) void ln_ca_kernel(
    const float* __restrict__ g, const float* __restrict__ b, const float* __restrict__ fusion)
{
    int tid = threadIdx.x;
    if (blockIdx.x == 0 && tid < D) g_tok[tid] = fusion[tid];
    int warp = tid >> 5, lane = tid & 31;
    int row = blockIdx.x * 8 + warp;
    float x[8];
    float s = 0.f;
#pragma unroll
    for (int j = 0; j < 8; j++) {
        int c = lane + 32 * j;
        x[j] = g_tmp[(size_t)row * D + c] + g_HS[(size_t)row * D + c];
        s += x[j];
    }
    s = warpSum(s);
    float m = s * (1.0f / D);
    float vs = 0.f;
#pragma unroll
    for (int j = 0; j < 8; j++) { float d = x[j] - m; vs += d * d; }
    vs = warpSum(vs);
    float r = rsqrtf(vs * (1.0f / D) + 1e-5f);
#pragma unroll
    for (int j = 0; j < 8; j++) {
        int c = lane + 32 * j;
        g_tok[(size_t)(1 + row) * D + c] = (x[j] - m) * r * g[c] + b[c];
    }
}

// ---------------- q0 = fusion @ Wq.T + bq  (+ zero accumulators) ----------------
__global__ void q0_kernel(const float* __restrict__ fusion,
                          const float* __restrict__ w, const float* __restrict__ bqkv)
{
    __shared__ float fs[D];
    int tid = threadIdx.x;
    fs[tid] = fusion[tid];
    g_a0[tid] = 0.f;
    if (tid < NH) g_Z0[tid] = 0.f;
    __syncthreads();
    float a = bqkv[tid];
    for (int c = 0; c < D; c++) a += fs[c] * w[(size_t)tid * D + c];
    g_q0[tid] = a;
}

// ---------------- row-0 scores over tokens ----------------
__global__ __launch_bounds__(256) void score0_kernel()
{
    __shared__ float q0s[D];
    __shared__ float zpart[NH];
    int tid = threadIdx.x;
    if (tid < D) q0s[tid] = g_q0[tid];
    if (tid < NH) zpart[tid] = 0.f;
    __syncthreads();
    int warp = tid >> 5, lane = tid & 31;
    int wtotal = gridDim.x * 8;
    const float isq = 0.17677669529663687f;
    for (int u = blockIdx.x * 8 + warp; u < TT; u += wtotal) {
        float mine = 0.f;
#pragma unroll
        for (int j = 0; j < 8; j++) {
            int c = lane + 32 * j;
            float v = q0s[c] * g_k2[(size_t)u * D + c];
            v = warpSum(v);
            if (lane == j) mine = v;
        }
        if (lane < 8) {
            float p = __expf(mine * isq);
            g_p0[u * NH + lane] = p;
            atomicAdd(&zpart[lane], p);
        }
    }
    __syncthreads();
    if (tid < NH) atomicAdd(&g_Z0[tid], zpart[tid]);
}

// ---------------- row-0 AV ----------------
__global__ __launch_bounds__(256) void av0_kernel()
{
    int col = threadIdx.x;
    int h = col >> 5;
    int u0 = blockIdx.x * 257;
    int u1 = u0 + 257; if (u1 > TT) u1 = TT;
    float acc = 0.f;
    for (int u = u0; u < u1; u++)
        acc += g_p0[u * NH + h] * g_v2[(size_t)u * D + col];
    atomicAdd(&g_a0[col], acc);
}

// ---------------- final head ----------------
__device__ __forceinline__ float blockSum256(float v, volatile float* red) {
    int lane = threadIdx.x & 31, w = threadIdx.x >> 5;
    v = warpSum(v);
    __syncthreads();
    if (lane == 0) red[w] = v;
    __syncthreads();
    float s = 0.f;
#pragma unroll
    for (int i = 0; i < 8; i++) s += red[i];
    return s;
}

__global__ __launch_bounds__(256) void final_kernel(
    const float* __restrict__ fusion,
    const float* __restrict__ mow, const float* __restrict__ mob,
    const float* __restrict__ ln1g, const float* __restrict__ ln1b,
    const float* __restrict__ w1, const float* __restrict__ b1,
    const float* __restrict__ w2, const float* __restrict__ b2,
    const float* __restrict__ ln2g, const float* __restrict__ ln2b,
    float* __restrict__ out)
{
    __shared__ float a0[D], t1[D], h1[2 * D];
    __shared__ float red[8];
    int tid = threadIdx.x;
    a0[tid] = g_a0[tid] / g_Z0[tid >> 5];
    __syncthreads();
    float y = mob[tid];
    for (int j = 0; j < D; j++) y += a0[j] * mow[(size_t)tid * D + j];
    float tv = fusion[tid] + y;
    float m = blockSum256(tv, red) * (1.0f / D);
    float d = tv - m;
    float var = blockSum256(d * d, red) * (1.0f / D);
    float t = d * rsqrtf(var + 1e-5f) * ln1g[tid] + ln1b[tid];
    t1[tid] = t;
    __syncthreads();
    float hh[2];
#pragma unroll
    for (int r2 = 0; r2 < 2; r2++) {
        int jj = tid + r2 * 256;
        float a = b1[jj];
        for (int c = 0; c < D; c++) a += t1[c] * w1[(size_t)jj * D + c];
        hh[r2] = a * 0.5f * (1.f + erff(a * 0.70710678118654752f));
    }
    h1[tid] = hh[0];
    h1[tid + 256] = hh[1];
    __syncthreads();
    float o = b2[tid];
    for (int j = 0; j < 512; j++) o += h1[j] * w2[(size_t)tid * 512 + j];
    float t2v = t1[tid] + o;   // residual = LN1 output
    float m2 = blockSum256(t2v, red) * (1.0f / D);
    float d2 = t2v - m2;
    float v2 = blockSum256(d2 * d2, red) * (1.0f / D);
    out[tid] = d2 * rsqrtf(v2 + 1e-5f) * ln2g[tid] + ln2b[tid];
}

// ---------------- launcher ----------------
extern "C" void kernel_launch(void* const* d_in, const int* in_sizes, int n_in,
                              void* d_out, int out_size)
{
    const float* H_S     = (const float*)d_in[0];
    const float* H_C     = (const float*)d_in[1];
    const float* H_G     = (const float*)d_in[2];
    const float* G_glyph = (const float*)d_in[3];
    const float* Ws      = (const float*)d_in[4];
    const float* bs      = (const float*)d_in[5];
    const float* Wb      = (const float*)d_in[6];
    const float* bb      = (const float*)d_in[7];
    const float* Wg      = (const float*)d_in[8];
    const float* bg      = (const float*)d_in[9];
    const float* WQ      = (const float*)d_in[10];
    const float* WK      = (const float*)d_in[11];
    const float* WV      = (const float*)d_in[12];
    const float* WO      = (const float*)d_in[13];
    const float* bO      = (const float*)d_in[14];
    const float* ln_ca_g = (const float*)d_in[15];
    const float* ln_ca_b = (const float*)d_in[16];
    const float* fusion  = (const float*)d_in[17];
    const float* mha_in_w  = (const float*)d_in[18];
    const float* mha_in_b  = (const float*)d_in[19];
    const float* mha_out_w = (const float*)d_in[20];
    const float* mha_out_b = (const float*)d_in[21];
    const float* ln1_g   = (const float*)d_in[22];
    const float* ln1_b   = (const float*)d_in[23];
    const float* ln2_g   = (const float*)d_in[24];
    const float* ln2_b   = (const float*)d_in[25];
    const float* ffn_w1  = (const float*)d_in[26];
    const float* ffn_b1  = (const float*)d_in[27];
    const float* ffn_w2  = (const float*)d_in[28];
    const float* ffn_b2  = (const float*)d_in[29];

    float* out = (float*)d_out;
    float* z_fused  = out;        // 256
    float* attn_map = out + D;    // 2048 * 4096

    float *pHS, *pHC, *pHnew, *pTmp, *pTok, *pk2, *pv2;
    __half *pQh, *pKh, *pVh, *pGh;
    cudaGetSymbolAddress((void**)&pHS,  g_HS);
    cudaGetSymbolAddress((void**)&pHC,  g_HC);
    cudaGetSymbolAddress((void**)&pQh,  g_Qh);
    cudaGetSymbolAddress((void**)&pKh,  g_Kh);
    cudaGetSymbolAddress((void**)&pVh,  g_Vh);
    cudaGetSymbolAddress((void**)&pGh,  g_Gh);
    cudaGetSymbolAddress((void**)&pHnew,g_Hnew);
    cudaGetSymbolAddress((void**)&pTmp, g_tmp);
    cudaGetSymbolAddress((void**)&pTok, g_tok);
    cudaGetSymbolAddress((void**)&pk2,  g_k2);
    cudaGetSymbolAddress((void**)&pv2,  g_v2);

    static bool attrSet = false;
    if (!attrSet) {
        cudaFuncSetAttribute(ca_fused_kernel,
                             cudaFuncAttributeMaxDynamicSharedMemorySize, CA_SMEM);
        cudaFuncSetAttribute(attn_recompute_kernel,
                             cudaFuncAttributeMaxDynamicSharedMemorySize, AT_SMEM);
        attrSet = true;
    }

    // #1 HS projection + (z=1 slice) gate fp16 conversion
    gemm16_kernel<0><<<dim3(4, 32, 2), 256>>>(
        H_S, Ws, bs, pHS, nullptr, NS,
        H_S, Ws, bs, pHS, nullptr, NS,
        H_S, Ws, bs, pHS, nullptr, NS, D, 128, G_glyph, pGh);
    // #2 HC projection
    gemm16_kernel<0><<<dim3(4, 64), 256>>>(
        H_C, Wb, bb, pHC, nullptr, NC,
        H_C, Wb, bb, pHC, nullptr, NC,
        H_C, Wb, bb, pHC, nullptr, NC, D, 256, nullptr, nullptr);
    // #3 Q/K/V triple (fp16 out)
    gemm16_kernel<1><<<dim3(4, 64, 3), 256>>>(
        pHS, WQ, nullptr, nullptr, pQh, NS,
        pHC, WK, nullptr, nullptr, pKh, NC,
        pHC, WV, nullptr, nullptr, pVh, NC, D, 256, nullptr, nullptr);
    // #4 fused gated cross attention (Z + Hnew), 32 s-rows/block  <-- ncu capture target
    ca_fused_kernel<<<dim3(NH, NS / 32), 256, CA_SMEM>>>();
    // #5 HG projection into token slots
    gemm16_kernel<0><<<dim3(4, 32), 256>>>(
        H_G, Wg, bg, pTok + (size_t)(1 + NS) * D, nullptr, NG,
        H_G, Wg, bg, pTok + (size_t)(1 + NS) * D, nullptr, NG,
        H_G, Wg, bg, pTok + (size_t)(1 + NS) * D, nullptr, NG, D, 64, nullptr, nullptr);
    // #6 attn_map via QK recompute (needs g_Z)
    attn_recompute_kernel<<<dim3(NC / 128, NS / 16), 256, AT_SMEM>>>(attn_map);
    // O projection + residual LN -> tokens
    gemm16_kernel<0><<<dim3(4, 32), 256>>>(
        pHnew, WO, bO, pTmp, nullptr, NS,
        pHnew, WO, bO, pTmp, nullptr, NS,
        pHnew, WO, bO, pTmp, nullptr, NS, D, 256, nullptr, nullptr);
    ln_ca_kernel<<<NS / 8, 256>>>(ln_ca_g, ln_ca_b, fusion);
    // self-attn K/V over tokens (dual)
    gemm16_kernel<0><<<dim3(4, 65, 2), 256>>>(
        pTok, mha_in_w + 256 * 256, mha_in_b + 256, pk2, nullptr, TT,
        pTok, mha_in_w + 512 * 256, mha_in_b + 512, pv2, nullptr, TT,
        pTok, mha_in_w + 256 * 256, mha_in_b + 256, pk2, nullptr, TT, D, 256, nullptr, nullptr);
    // token-0 attention + head
    q0_kernel<<<1, 256>>>(fusion, mha_in_w, mha_in_b);
    score0_kernel<<<32, 256>>>();
    av0_kernel<<<16, 256>>>();
    final_kernel<<<1, 256>>>(fusion, mha_out_w, mha_out_b, ln1_g, ln1_b,
                             ffn_w1, ffn_b1, ffn_w2, ffn_b2, ln2_g, ln2_b, z_fused);
}

// round 10
// speedup vs baseline: 2.7312x; 1.0452x over previous
#include <cuda_runtime.h>
#include <cuda_fp16.h>

#define NS 2048
#define NC 4096
#define NG 2048
#define D  256
#define NH 8
#define TT 4097   // 1 + NS + NG

// ---------------- device scratch ----------------
__device__ float  g_HS[NS * D];
__device__ float  g_HC[NC * D];
__device__ __half g_Qh[NS * D];
__device__ __half g_Kh[NC * D];
__device__ __half g_Vh[NC * D];
__device__ __half g_Gh[(size_t)NS * NC];   // gate * (isq*log2e), fp16
__device__ float  g_Z[NS * NH];
__device__ float  g_Hnew[NS * D];
__device__ float  g_tmp[NS * D];
__device__ float  g_tok[TT * D];
__device__ float  g_k2[TT * D];
__device__ float  g_v2[TT * D];
__device__ float  g_q0[D];
__device__ float  g_Z0[NH];
__device__ float  g_a0[D];

__device__ __forceinline__ float warpSum(float v) {
#pragma unroll
    for (int o = 16; o; o >>= 1) v += __shfl_xor_sync(0xffffffffu, v, o);
    return v;
}

__device__ __forceinline__ void mma16816(float* c, const unsigned* a, const unsigned* b) {
    asm volatile(
        "mma.sync.aligned.m16n8k16.row.col.f32.f16.f16.f32 "
        "{%0,%1,%2,%3}, {%4,%5,%6,%7}, {%8,%9}, {%0,%1,%2,%3};\n"
        : "+f"(c[0]), "+f"(c[1]), "+f"(c[2]), "+f"(c[3])
        : "r"(a[0]), "r"(a[1]), "r"(a[2]), "r"(a[3]), "r"(b[0]), "r"(b[1]));
}

__device__ __forceinline__ unsigned smaddr(const void* p) {
    return (unsigned)__cvta_generic_to_shared(p);
}
__device__ __forceinline__ void ldm_x2(unsigned& r0, unsigned& r1, unsigned a) {
    asm volatile("ldmatrix.sync.aligned.m8n8.x2.shared.b16 {%0,%1}, [%2];"
                 : "=r"(r0), "=r"(r1) : "r"(a));
}
__device__ __forceinline__ void ldm_x2_t(unsigned& r0, unsigned& r1, unsigned a) {
    asm volatile("ldmatrix.sync.aligned.m8n8.x2.trans.shared.b16 {%0,%1}, [%2];"
                 : "=r"(r0), "=r"(r1) : "r"(a));
}
__device__ __forceinline__ void ldm_x4(unsigned* r, unsigned a) {
    asm volatile("ldmatrix.sync.aligned.m8n8.x4.shared.b16 {%0,%1,%2,%3}, [%4];"
                 : "=r"(r[0]), "=r"(r[1]), "=r"(r[2]), "=r"(r[3]) : "r"(a));
}
__device__ __forceinline__ void cpa16(void* smem, const void* gmem) {
    asm volatile("cp.async.cg.shared.global [%0], [%1], 16;"
                 :: "r"(smaddr(smem)), "l"(gmem));
}
__device__ __forceinline__ __half2 h2ex2(__half2 x) {
    unsigned r, xi = *(unsigned*)&x;
    asm("ex2.approx.f16x2 %0, %1;" : "=r"(r) : "r"(xi));
    return *(__half2*)&r;
}

#define CE 0.25506382f   // (1/sqrt(32)) * log2(e)

// ---------------- fp16 tensor-core GEMM (up to 3 problems via blockIdx.z, per-z K) ----------------
// Optionally the LAST z-slice converts G fp32 -> fp16*CE instead (gsrc != null).
template<int OM>
__global__ __launch_bounds__(256) void gemm16_kernel(
    const float* __restrict__ A0, const float* __restrict__ W0, const float* __restrict__ bs0,
    float* __restrict__ Cf0, __half* __restrict__ Ch0, int M0,
    const float* __restrict__ A1, const float* __restrict__ W1, const float* __restrict__ bs1,
    float* __restrict__ Cf1, __half* __restrict__ Ch1, int M1,
    const float* __restrict__ A2, const float* __restrict__ W2, const float* __restrict__ bs2,
    float* __restrict__ Cf2, __half* __restrict__ Ch2, int M2,
    int N, int K0p, int K1p, int K2p,
    const float* __restrict__ gsrc, __half* __restrict__ gdst)
{
    if (gsrc != nullptr && blockIdx.z == gridDim.z - 1) {
        int bid = blockIdx.y * gridDim.x + blockIdx.x;
        int t4 = bid * 256 + threadIdx.x;
        const int total4 = (NS * NC) / 4;
        int stride = gridDim.x * gridDim.y * 256;
        for (int i = t4; i < total4; i += stride) {
            float4 v = *(const float4*)&gsrc[(size_t)i * 4];
            __half2 h0 = __floats2half2_rn(v.x * CE, v.y * CE);
            __half2 h1 = __floats2half2_rn(v.z * CE, v.w * CE);
            *(int2*)&gdst[(size_t)i * 4] = make_int2(*(int*)&h0, *(int*)&h1);
        }
        return;
    }

    const int z = blockIdx.z;
    const float* A    = z == 0 ? A0  : (z == 1 ? A1  : A2);
    const float* W    = z == 0 ? W0  : (z == 1 ? W1  : W2);
    const float* bias = z == 0 ? bs0 : (z == 1 ? bs1 : bs2);
    float* Cf         = z == 0 ? Cf0 : (z == 1 ? Cf1 : Cf2);
    __half* Ch        = z == 0 ? Ch0 : (z == 1 ? Ch1 : Ch2);
    const int M       = z == 0 ? M0  : (z == 1 ? M1  : M2);
    const int K       = z == 0 ? K0p : (z == 1 ? K1p : K2p);

    const int bm = blockIdx.y * 64, bn = blockIdx.x * 64;
    if (bm >= M) return;

    __shared__ __half Ah[64 * 40];
    __shared__ __half Bh[64 * 40];

    const int tid = threadIdx.x;
    const int w = tid >> 5, lane = tid & 31;
    const int wr = w >> 1, wc = w & 1;
    const int gr = lane >> 2, cc = lane & 3;
    const int fr = tid >> 2, fc8 = (tid & 3) * 8;
    const int l4 = lane & 15;
    const int hi8 = (lane >> 4) * 8;

    float acc[4][4] = {};

    for (int k0 = 0; k0 < K; k0 += 32) {
        __syncthreads();
        {
            float4 a0v = make_float4(0.f, 0.f, 0.f, 0.f), a1v = a0v;
            if (bm + fr < M) {
                const float* ap = &A[(size_t)(bm + fr) * K + k0 + fc8];
                a0v = *(const float4*)ap;
                a1v = *(const float4*)(ap + 4);
            }
            __half2 h0 = __floats2half2_rn(a0v.x, a0v.y);
            __half2 h1 = __floats2half2_rn(a0v.z, a0v.w);
            __half2 h2 = __floats2half2_rn(a1v.x, a1v.y);
            __half2 h3 = __floats2half2_rn(a1v.z, a1v.w);
            int4 pk = make_int4(*(int*)&h0, *(int*)&h1, *(int*)&h2, *(int*)&h3);
            *(int4*)&Ah[fr * 40 + fc8] = pk;

            const float* wp = &W[(size_t)(bn + fr) * K + k0 + fc8];
            float4 b0v = *(const float4*)wp;
            float4 b1v = *(const float4*)(wp + 4);
            __half2 g0 = __floats2half2_rn(b0v.x, b0v.y);
            __half2 g1 = __floats2half2_rn(b0v.z, b0v.w);
            __half2 g2 = __floats2half2_rn(b1v.x, b1v.y);
            __half2 g3 = __floats2half2_rn(b1v.z, b1v.w);
            int4 pk2 = make_int4(*(int*)&g0, *(int*)&g1, *(int*)&g2, *(int*)&g3);
            *(int4*)&Bh[fr * 40 + fc8] = pk2;
        }
        __syncthreads();

#pragma unroll
        for (int ks = 0; ks < 2; ks++) {
            unsigned af[4];
            ldm_x4(af, smaddr(&Ah[(wr * 16 + l4) * 40 + ks * 16 + hi8]));
            unsigned bf[2][4];
#pragma unroll
            for (int p = 0; p < 2; p++)
                ldm_x4(bf[p], smaddr(&Bh[(wc * 32 + p * 16 + l4) * 40 + ks * 16 + hi8]));
#pragma unroll
            for (int nt = 0; nt < 4; nt++) {
                unsigned bb[2];
                bb[0] = bf[nt >> 1][(nt & 1)];
                bb[1] = bf[nt >> 1][(nt & 1) + 2];
                mma16816(acc[nt], af, bb);
            }
        }
    }

#pragma unroll
    for (int nt = 0; nt < 4; nt++) {
        int col = bn + wc * 32 + nt * 8 + 2 * cc;
        float b0 = bias ? bias[col] : 0.f;
        float b1 = bias ? bias[col + 1] : 0.f;
        int row0 = bm + wr * 16 + gr;
        int row1 = row0 + 8;
        if (row0 < M) {
            if (OM == 1) {
                Ch[(size_t)row0 * N + col]     = __float2half(acc[nt][0] + b0);
                Ch[(size_t)row0 * N + col + 1] = __float2half(acc[nt][1] + b1);
            } else {
                Cf[(size_t)row0 * N + col]     = acc[nt][0] + b0;
                Cf[(size_t)row0 * N + col + 1] = acc[nt][1] + b1;
            }
        }
        if (row1 < M) {
            if (OM == 1) {
                Ch[(size_t)row1 * N + col]     = __float2half(acc[nt][2] + b0);
                Ch[(size_t)row1 * N + col + 1] = __float2half(acc[nt][3] + b1);
            } else {
                Cf[(size_t)row1 * N + col]     = acc[nt][2] + b0;
                Cf[(size_t)row1 * N + col + 1] = acc[nt][3] + b1;
            }
        }
    }
}

// ---------------- fused gated cross-attention: 32 s-rows per block ----------------
// grid = (NH, NS/32). smem bytes:
//   Ks 2x20480 @0, Vs 2x20480 @40960, Ghs 16896 @81920 (single buffer),
//   Qs 2560 @98816, Hs 4096 @101376, Zs 128 @105472 -> total 105600
#define CA_SMEM 105600
__global__ __launch_bounds__(256, 2) void ca_fused_kernel()
{
    extern __shared__ __align__(16) char smraw[];
    __half* Ks  = (__half*)smraw;
    __half* Vs  = (__half*)(smraw + 40960);
    __half* Ghs = (__half*)(smraw + 81920);
    __half* Qs  = (__half*)(smraw + 98816);
    float*  Hs  = (float*)(smraw + 101376);
    float*  Zs  = (float*)(smraw + 105472);

    const int h = blockIdx.x;
    const int s0 = blockIdx.y * 32;
    const int tid = threadIdx.x;
    const int w = tid >> 5, lane = tid & 31;
    const int gr = lane >> 2, cc = lane & 3;
    const int cw = w * 32;
    const int l4 = lane & 15;

    auto issue_tile = [&](int ci) {
        int buf = (ci & 1) * 10240;
        int c0 = ci * 256;
        int pr = tid >> 2, pp4 = tid & 3;
#pragma unroll
        for (int rr = 0; rr < 4; rr++) {
            int row = rr * 64 + pr;
            size_t src = (size_t)(c0 + row) * D + h * 32 + pp4 * 8;
            cpa16(&Ks[buf + row * 40 + pp4 * 8], &g_Kh[src]);
            cpa16(&Vs[buf + row * 40 + pp4 * 8], &g_Vh[src]);
        }
#pragma unroll
        for (int t = 0; t < 4; t++) {
            int idx = t * 256 + tid;
            int r = idx >> 5, pp = idx & 31;
            cpa16(&Ghs[r * 264 + pp * 8], &g_Gh[(size_t)(s0 + r) * NC + c0 + pp * 8]);
        }
        asm volatile("cp.async.commit_group;");
    };

#pragma unroll
    for (int t = 0; t < 2; t++) {
        int idx = t * 256 + tid;
        int row = idx >> 4, c2 = (idx & 15) * 2;
        *(unsigned*)&Qs[row * 40 + c2] =
            *(const unsigned*)&g_Qh[(size_t)(s0 + row) * D + h * 32 + c2];
    }
#pragma unroll
    for (int k = 0; k < 4; k++) Hs[k * 256 + tid] = 0.f;
    if (tid < 32) Zs[tid] = 0.f;

    issue_tile(0);
    __syncthreads();

    unsigned qa[2][2][4];
#pragma unroll
    for (int sh = 0; sh < 2; sh++)
#pragma unroll
        for (int ks = 0; ks < 2; ks++)
            ldm_x4(qa[sh][ks], smaddr(&Qs[(sh * 16 + l4) * 40 + ks * 16 + (lane >> 4) * 8]));

    float hacc[2][4][4] = {};
    float zacc[2][2] = {};

    for (int ci = 0; ci < 16; ci++) {
        int buf = (ci & 1) * 10240;
        asm volatile("cp.async.wait_group 0;" ::: "memory");
        __syncthreads();

        unsigned gf[2][4][2];
#pragma unroll
        for (int sh = 0; sh < 2; sh++)
#pragma unroll
            for (int nt = 0; nt < 4; nt++)
                ldm_x2(gf[sh][nt][0], gf[sh][nt][1],
                       smaddr(&Ghs[(sh * 16 + l4) * 264 + cw + nt * 8]));
        __syncthreads();
        if (ci < 15) issue_tile(ci + 1);

#pragma unroll
        for (int sh = 0; sh < 2; sh++) {
            unsigned pa[2][4];
#pragma unroll
            for (int nt = 0; nt < 4; nt++) {
                float S[4] = {0.f, 0.f, 0.f, 0.f};
#pragma unroll
                for (int ks = 0; ks < 2; ks++) {
                    unsigned b[2];
                    ldm_x2(b[0], b[1],
                           smaddr(&Ks[buf + (cw + nt * 8 + (l4 & 7)) * 40 + ks * 16 + (l4 >> 3) * 8]));
                    mma16816(S, qa[sh][ks], b);
                }
                __half2 x01 = __hmul2(__floats2half2_rn(S[0], S[1]), *(__half2*)&gf[sh][nt][0]);
                __half2 x23 = __hmul2(__floats2half2_rn(S[2], S[3]), *(__half2*)&gf[sh][nt][1]);
                __half2 p01 = h2ex2(x01);
                __half2 p23 = h2ex2(x23);
                float2 f01 = __half22float2(p01);
                float2 f23 = __half22float2(p23);
                zacc[sh][0] += f01.x + f01.y;
                zacc[sh][1] += f23.x + f23.y;
                unsigned u01 = *(unsigned*)&p01, u23 = *(unsigned*)&p23;
                if ((nt & 1) == 0) { pa[nt >> 1][0] = u01; pa[nt >> 1][1] = u23; }
                else               { pa[nt >> 1][2] = u01; pa[nt >> 1][3] = u23; }
            }
#pragma unroll
            for (int nt2 = 0; nt2 < 4; nt2++) {
#pragma unroll
                for (int ks2 = 0; ks2 < 2; ks2++) {
                    unsigned b[2];
                    ldm_x2_t(b[0], b[1],
                             smaddr(&Vs[buf + (cw + ks2 * 16 + l4) * 40 + nt2 * 8]));
                    mma16816(hacc[sh][nt2], pa[ks2], b);
                }
            }
        }
    }

#pragma unroll
    for (int sh = 0; sh < 2; sh++) {
        float z0 = zacc[sh][0], z1 = zacc[sh][1];
#pragma unroll
        for (int o = 1; o < 4; o <<= 1) {
            z0 += __shfl_xor_sync(0xffffffffu, z0, o);
            z1 += __shfl_xor_sync(0xffffffffu, z1, o);
        }
        if (cc == 0) {
            atomicAdd(&Zs[sh * 16 + gr], z0);
            atomicAdd(&Zs[sh * 16 + gr + 8], z1);
        }
#pragma unroll
        for (int nt2 = 0; nt2 < 4; nt2++) {
            atomicAdd(&Hs[(sh * 16 + gr) * 32 + nt2 * 8 + 2 * cc],           hacc[sh][nt2][0]);
            atomicAdd(&Hs[(sh * 16 + gr) * 32 + nt2 * 8 + 2 * cc + 1],       hacc[sh][nt2][1]);
            atomicAdd(&Hs[(sh * 16 + gr + 8) * 32 + nt2 * 8 + 2 * cc],       hacc[sh][nt2][2]);
            atomicAdd(&Hs[(sh * 16 + gr + 8) * 32 + nt2 * 8 + 2 * cc + 1],   hacc[sh][nt2][3]);
        }
    }
    __syncthreads();
    if (tid < 32) g_Z[(s0 + tid) * NH + h] = Zs[tid];
#pragma unroll
    for (int k = 0; k < 4; k++) {
        int idx = k * 256 + tid;
        int row = idx >> 5, d = idx & 31;
        g_Hnew[(size_t)(s0 + row) * D + h * 32 + d] = Hs[idx] / Zs[row];
    }
}

// ---------------- attn_map by QK recompute: 32 s-rows per block ----------------
// smem: Ks 67584 @0, Qs 16896 @67584, Ghs 8704 @84480, AMs 16896 @93184, iZ 1024 @110080
#define AT_SMEM 111104
__global__ __launch_bounds__(256, 2) void attn_recompute_kernel(float* __restrict__ AM)
{
    extern __shared__ __align__(16) char smraw[];
    __half* Ks  = (__half*)smraw;
    __half* Qs  = (__half*)(smraw + 67584);
    __half* Ghs = (__half*)(smraw + 84480);
    float*  AMs = (float*)(smraw + 93184);
    float*  iZ  = (float*)(smraw + 110080);

    const int c0 = blockIdx.x * 128;
    const int s0 = blockIdx.y * 32;
    const int tid = threadIdx.x;
    const int w = tid >> 5, lane = tid & 31;
    const int gr = lane >> 2, cc = lane & 3;
    const int l4 = lane & 15;
    const int hi8 = (lane >> 4) * 8;
    const int cw16 = w * 16;

#pragma unroll
    for (int t = 0; t < 16; t++) {
        int idx = t * 256 + tid;
        int r = idx >> 5, pp = idx & 31;
        cpa16(&Ks[r * 264 + pp * 8], &g_Kh[(size_t)(c0 + r) * D + pp * 8]);
    }
#pragma unroll
    for (int t = 0; t < 4; t++) {
        int idx = t * 256 + tid;
        int r = idx >> 5, pp = idx & 31;
        cpa16(&Qs[r * 264 + pp * 8], &g_Qh[(size_t)(s0 + r) * D + pp * 8]);
    }
#pragma unroll
    for (int t = 0; t < 2; t++) {
        int idx = t * 256 + tid;
        int r = idx >> 4, pp = idx & 15;
        cpa16(&Ghs[r * 136 + pp * 8], &g_Gh[(size_t)(s0 + r) * NC + c0 + pp * 8]);
    }
    asm volatile("cp.async.commit_group;");
    {
        int s = tid >> 3, hh = tid & 7;
        iZ[tid] = 0.125f / g_Z[(s0 + s) * NH + hh];
    }
    asm volatile("cp.async.wait_group 0;" ::: "memory");
    __syncthreads();

    // gate fragments (constant across heads), for both s-halves
    unsigned gfr[2][2][2];
#pragma unroll
    for (int sh = 0; sh < 2; sh++)
#pragma unroll
        for (int nt = 0; nt < 2; nt++)
            ldm_x2(gfr[sh][nt][0], gfr[sh][nt][1],
                   smaddr(&Ghs[(sh * 16 + l4) * 136 + cw16 + nt * 8]));

    float acc[2][2][4] = {};
#pragma unroll
    for (int h = 0; h < NH; h++) {
        // K b-fragments shared by both s-halves
        unsigned kb[2][4];
#pragma unroll
        for (int ks = 0; ks < 2; ks++)
            ldm_x4(kb[ks], smaddr(&Ks[(cw16 + l4) * 264 + h * 32 + ks * 16 + hi8]));
#pragma unroll
        for (int sh = 0; sh < 2; sh++) {
            unsigned qa[2][4];
#pragma unroll
            for (int ks = 0; ks < 2; ks++)
                ldm_x4(qa[ks], smaddr(&Qs[(sh * 16 + l4) * 264 + h * 32 + ks * 16 + hi8]));
            float izA = iZ[(sh * 16 + gr) * 8 + h];
            float izB = iZ[(sh * 16 + gr + 8) * 8 + h];
#pragma unroll
            for (int nt = 0; nt < 2; nt++) {
                float S[4] = {0.f, 0.f, 0.f, 0.f};
#pragma unroll
                for (int ks = 0; ks < 2; ks++) {
                    unsigned bb[2];
                    bb[0] = kb[ks][nt];
                    bb[1] = kb[ks][nt + 2];
                    mma16816(S, qa[ks], bb);
                }
                __half2 x01 = __hmul2(__floats2half2_rn(S[0], S[1]), *(__half2*)&gfr[sh][nt][0]);
                __half2 x23 = __hmul2(__floats2half2_rn(S[2], S[3]), *(__half2*)&gfr[sh][nt][1]);
                float2 f01 = __half22float2(h2ex2(x01));
                float2 f23 = __half22float2(h2ex2(x23));
                acc[sh][nt][0] += f01.x * izA;
                acc[sh][nt][1] += f01.y * izA;
                acc[sh][nt][2] += f23.x * izB;
                acc[sh][nt][3] += f23.y * izB;
            }
        }
    }

#pragma unroll
    for (int sh = 0; sh < 2; sh++)
#pragma unroll
        for (int nt = 0; nt < 2; nt++) {
            int col = cw16 + nt * 8 + 2 * cc;
            *(float2*)&AMs[(sh * 16 + gr) * 132 + col]       = make_float2(acc[sh][nt][0], acc[sh][nt][1]);
            *(float2*)&AMs[(sh * 16 + gr + 8) * 132 + col]   = make_float2(acc[sh][nt][2], acc[sh][nt][3]);
        }
    __syncthreads();
#pragma unroll
    for (int t = 0; t < 4; t++) {
        int idx = t * 256 + tid;
        int r = idx >> 5, p4 = idx & 31;
        *(float4*)&AM[(size_t)(s0 + r) * NC + c0 + p4 * 4] = *(const float4*)&AMs[r * 132 + p4 * 4];
    }
}

// ---------------- cross-attn epilogue LN ----------------
__global__ __launch_bounds__(256) void ln_ca_kernel(
    const float* __restrict__ g, const float* __restrict__ b, const float* __restrict__ fusion)
{
    int tid = threadIdx.x;
    if (blockIdx.x == 0 && tid < D) g_tok[tid] = fusion[tid];
    int warp = tid >> 5, lane = tid & 31;
    int row = blockIdx.x * 8 + warp;
    float x[8];
    float s = 0.f;
#pragma unroll
    for (int j = 0; j < 8; j++) {
        int c = lane + 32 * j;
        x[j] = g_tmp[(size_t)row * D + c] + g_HS[(size_t)row * D + c];
        s += x[j];
    }
    s = warpSum(s);
    float m = s * (1.0f / D);
    float vs = 0.f;
#pragma unroll
    for (int j = 0; j < 8; j++) { float d = x[j] - m; vs += d * d; }
    vs = warpSum(vs);
    float r = rsqrtf(vs * (1.0f / D) + 1e-5f);
#pragma unroll
    for (int j = 0; j < 8; j++) {
        int c = lane + 32 * j;
        g_tok[(size_t)(1 + row) * D + c] = (x[j] - m) * r * g[c] + b[c];
    }
}

// ---------------- q0 = fusion @ Wq.T + bq  (+ zero accumulators) ----------------
__global__ void q0_kernel(const float* __restrict__ fusion,
                          const float* __restrict__ w, const float* __restrict__ bqkv)
{
    __shared__ float fs[D];
    int tid = threadIdx.x;
    fs[tid] = fusion[tid];
    g_a0[tid] = 0.f;
    if (tid < NH) g_Z0[tid] = 0.f;
    __syncthreads();
    float a = bqkv[tid];
    for (int c = 0; c < D; c++) a += fs[c] * w[(size_t)tid * D + c];
    g_q0[tid] = a;
}

// ---------------- fused row-0 scores + AV over tokens ----------------
__global__ __launch_bounds__(256) void sa0_kernel()
{
    __shared__ float q0s[D];
    __shared__ float zpart[NH];
    __shared__ float a0s[D];
    int tid = threadIdx.x;
    if (tid < D) q0s[tid] = g_q0[tid];
    a0s[tid] = 0.f;
    if (tid < NH) zpart[tid] = 0.f;
    __syncthreads();
    int warp = tid >> 5, lane = tid & 31;
    int wtotal = gridDim.x * 8;
    const float isq = 0.17677669529663687f;
    float acc[8] = {};
    float zacc = 0.f;
    for (int u = blockIdx.x * 8 + warp; u < TT; u += wtotal) {
        float mine = 0.f;
#pragma unroll
        for (int j = 0; j < 8; j++) {
            int c = lane + 32 * j;
            float v = q0s[c] * g_k2[(size_t)u * D + c];
            v = warpSum(v);
            if (lane == j) mine = v;
        }
        float pl = __expf(mine * isq);           // valid in lanes 0..7 (others exp(0)=1, unused)
        if (lane < 8) zacc += pl;
        float ph = __shfl_sync(0xffffffffu, pl, lane >> 2);
        const float* vrow = &g_v2[(size_t)u * D + lane * 8];
        float4 v0 = *(const float4*)vrow;
        float4 v1 = *(const float4*)(vrow + 4);
        acc[0] += ph * v0.x; acc[1] += ph * v0.y; acc[2] += ph * v0.z; acc[3] += ph * v0.w;
        acc[4] += ph * v1.x; acc[5] += ph * v1.y; acc[6] += ph * v1.z; acc[7] += ph * v1.w;
    }
    if (lane < 8) atomicAdd(&zpart[lane], zacc);
#pragma unroll
    for (int j = 0; j < 8; j++)
        atomicAdd(&a0s[lane * 8 + j], acc[j]);
    __syncthreads();
    atomicAdd(&g_a0[tid], a0s[tid]);
    if (tid < NH) atomicAdd(&g_Z0[tid], zpart[tid]);
}

// ---------------- final head ----------------
__device__ __forceinline__ float blockSum256(float v, volatile float* red) {
    int lane = threadIdx.x & 31, w = threadIdx.x >> 5;
    v = warpSum(v);
    __syncthreads();
    if (lane == 0) red[w] = v;
    __syncthreads();
    float s = 0.f;
#pragma unroll
    for (int i = 0; i < 8; i++) s += red[i];
    return s;
}

__global__ __launch_bounds__(256) void final_kernel(
    const float* __restrict__ fusion,
    const float* __restrict__ mow, const float* __restrict__ mob,
    const float* __restrict__ ln1g, const float* __restrict__ ln1b,
    const float* __restrict__ w1, const float* __restrict__ b1,
    const float* __restrict__ w2, const float* __restrict__ b2,
    const float* __restrict__ ln2g, const float* __restrict__ ln2b,
    float* __restrict__ out)
{
    __shared__ float a0[D], t1[D], h1[2 * D];
    __shared__ float red[8];
    int tid = threadIdx.x;
    a0[tid] = g_a0[tid] / g_Z0[tid >> 5];
    __syncthreads();
    float y = mob[tid];
    for (int j = 0; j < D; j++) y += a0[j] * mow[(size_t)tid * D + j];
    float tv = fusion[tid] + y;
    float m = blockSum256(tv, red) * (1.0f / D);
    float d = tv - m;
    float var = blockSum256(d * d, red) * (1.0f / D);
    float t = d * rsqrtf(var + 1e-5f) * ln1g[tid] + ln1b[tid];
    t1[tid] = t;
    __syncthreads();
    float hh[2];
#pragma unroll
    for (int r2 = 0; r2 < 2; r2++) {
        int jj = tid + r2 * 256;
        float a = b1[jj];
        for (int c = 0; c < D; c++) a += t1[c] * w1[(size_t)jj * D + c];
        hh[r2] = a * 0.5f * (1.f + erff(a * 0.70710678118654752f));
    }
    h1[tid] = hh[0];
    h1[tid + 256] = hh[1];
    __syncthreads();
    float o = b2[tid];
    for (int j = 0; j < 512; j++) o += h1[j] * w2[(size_t)tid * 512 + j];
    float t2v = t1[tid] + o;   // residual = LN1 output
    float m2 = blockSum256(t2v, red) * (1.0f / D);
    float d2 = t2v - m2;
    float v2 = blockSum256(d2 * d2, red) * (1.0f / D);
    out[tid] = d2 * rsqrtf(v2 + 1e-5f) * ln2g[tid] + ln2b[tid];
}

// ---------------- launcher ----------------
extern "C" void kernel_launch(void* const* d_in, const int* in_sizes, int n_in,
                              void* d_out, int out_size)
{
    const float* H_S     = (const float*)d_in[0];
    const float* H_C     = (const float*)d_in[1];
    const float* H_G     = (const float*)d_in[2];
    const float* G_glyph = (const float*)d_in[3];
    const float* Ws      = (const float*)d_in[4];
    const float* bs      = (const float*)d_in[5];
    const float* Wb      = (const float*)d_in[6];
    const float* bb      = (const float*)d_in[7];
    const float* Wg      = (const float*)d_in[8];
    const float* bg      = (const float*)d_in[9];
    const float* WQ      = (const float*)d_in[10];
    const float* WK      = (const float*)d_in[11];
    const float* WV      = (const float*)d_in[12];
    const float* WO      = (const float*)d_in[13];
    const float* bO      = (const float*)d_in[14];
    const float* ln_ca_g = (const float*)d_in[15];
    const float* ln_ca_b = (const float*)d_in[16];
    const float* fusion  = (const float*)d_in[17];
    const float* mha_in_w  = (const float*)d_in[18];
    const float* mha_in_b  = (const float*)d_in[19];
    const float* mha_out_w = (const float*)d_in[20];
    const float* mha_out_b = (const float*)d_in[21];
    const float* ln1_g   = (const float*)d_in[22];
    const float* ln1_b   = (const float*)d_in[23];
    const float* ln2_g   = (const float*)d_in[24];
    const float* ln2_b   = (const float*)d_in[25];
    const float* ffn_w1  = (const float*)d_in[26];
    const float* ffn_b1  = (const float*)d_in[27];
    const float* ffn_w2  = (const float*)d_in[28];
    const float* ffn_b2  = (const float*)d_in[29];

    float* out = (float*)d_out;
    float* z_fused  = out;        // 256
    float* attn_map = out + D;    // 2048 * 4096

    float *pHS, *pHC, *pHnew, *pTmp, *pTok, *pk2, *pv2;
    __half *pQh, *pKh, *pVh, *pGh;
    cudaGetSymbolAddress((void**)&pHS,  g_HS);
    cudaGetSymbolAddress((void**)&pHC,  g_HC);
    cudaGetSymbolAddress((void**)&pQh,  g_Qh);
    cudaGetSymbolAddress((void**)&pKh,  g_Kh);
    cudaGetSymbolAddress((void**)&pVh,  g_Vh);
    cudaGetSymbolAddress((void**)&pGh,  g_Gh);
    cudaGetSymbolAddress((void**)&pHnew,g_Hnew);
    cudaGetSymbolAddress((void**)&pTmp, g_tmp);
    cudaGetSymbolAddress((void**)&pTok, g_tok);
    cudaGetSymbolAddress((void**)&pk2,  g_k2);
    cudaGetSymbolAddress((void**)&pv2,  g_v2);

    static bool attrSet = false;
    if (!attrSet) {
        cudaFuncSetAttribute(ca_fused_kernel,
                             cudaFuncAttributeMaxDynamicSharedMemorySize, CA_SMEM);
        cudaFuncSetAttribute(attn_recompute_kernel,
                             cudaFuncAttributeMaxDynamicSharedMemorySize, AT_SMEM);
        attrSet = true;
    }

    // #1 HS projection (z0, K=128) + HG projection (z1, K=64) + gate conversion (z2)
    gemm16_kernel<0><<<dim3(4, 32, 3), 256>>>(
        H_S, Ws, bs, pHS, nullptr, NS,
        H_G, Wg, bg, pTok + (size_t)(1 + NS) * D, nullptr, NG,
        H_S, Ws, bs, pHS, nullptr, NS, D, 128, 64, 128, G_glyph, pGh);
    // #2 HC projection
    gemm16_kernel<0><<<dim3(4, 64), 256>>>(
        H_C, Wb, bb, pHC, nullptr, NC,
        H_C, Wb, bb, pHC, nullptr, NC,
        H_C, Wb, bb, pHC, nullptr, NC, D, 256, 256, 256, nullptr, nullptr);
    // #3 Q/K/V triple (fp16 out)
    gemm16_kernel<1><<<dim3(4, 64, 3), 256>>>(
        pHS, WQ, nullptr, nullptr, pQh, NS,
        pHC, WK, nullptr, nullptr, pKh, NC,
        pHC, WV, nullptr, nullptr, pVh, NC, D, 256, 256, 256, nullptr, nullptr);
    // #4 fused gated cross attention (Z + Hnew)  <-- ncu capture target
    ca_fused_kernel<<<dim3(NH, NS / 32), 256, CA_SMEM>>>();
    // #5 attn_map via QK recompute (needs g_Z), 32 s-rows
    attn_recompute_kernel<<<dim3(NC / 128, NS / 32), 256, AT_SMEM>>>(attn_map);
    // #6 O projection
    gemm16_kernel<0><<<dim3(4, 32), 256>>>(
        pHnew, WO, bO, pTmp, nullptr, NS,
        pHnew, WO, bO, pTmp, nullptr, NS,
        pHnew, WO, bO, pTmp, nullptr, NS, D, 256, 256, 256, nullptr, nullptr);
    ln_ca_kernel<<<NS / 8, 256>>>(ln_ca_g, ln_ca_b, fusion);
    // self-attn K/V over tokens (dual)
    gemm16_kernel<0><<<dim3(4, 65, 2), 256>>>(
        pTok, mha_in_w + 256 * 256, mha_in_b + 256, pk2, nullptr, TT,
        pTok, mha_in_w + 512 * 256, mha_in_b + 512, pv2, nullptr, TT,
        pTok, mha_in_w + 256 * 256, mha_in_b + 256, pk2, nullptr, TT, D, 256, 256, 256, nullptr, nullptr);
    // token-0 attention + head
    q0_kernel<<<1, 256>>>(fusion, mha_in_w, mha_in_b);
    sa0_kernel<<<32, 256>>>();
    final_kernel<<<1, 256>>>(fusion, mha_out_w, mha_out_b, ln1_g, ln1_b,
                             ffn_w1, ffn_b1, ffn_w2, ffn_b2, ln2_g, ln2_b, z_fused);
}

// round 11
// speedup vs baseline: 2.7936x; 1.0228x over previous
#include <cuda_runtime.h>
#include <cuda_fp16.h>

#define NS 2048
#define NC 4096
#define NG 2048
#define D  256
#define NH 8
#define TT 4097   // 1 + NS + NG
#define SA0_BLOCKS 32

// ---------------- device scratch ----------------
__device__ float  g_HS[NS * D];
__device__ float  g_HC[NC * D];
__device__ __half g_Qh[NS * D];
__device__ __half g_Kh[NC * D];
__device__ __half g_Vh[NC * D];
__device__ __half g_Gh[(size_t)NS * NC];   // gate * (isq*log2e), fp16
__device__ float  g_Z[NS * NH];
__device__ float  g_Hnew[NS * D];
__device__ float  g_tmp[NS * D];
__device__ float  g_tok[TT * D];
__device__ float  g_k2[TT * D];
__device__ float  g_v2[TT * D];
__device__ float  g_a0p[SA0_BLOCKS][D];
__device__ float  g_Z0p[SA0_BLOCKS][NH];

__device__ __forceinline__ float warpSum(float v) {
#pragma unroll
    for (int o = 16; o; o >>= 1) v += __shfl_xor_sync(0xffffffffu, v, o);
    return v;
}

__device__ __forceinline__ void mma16816(float* c, const unsigned* a, const unsigned* b) {
    asm volatile(
        "mma.sync.aligned.m16n8k16.row.col.f32.f16.f16.f32 "
        "{%0,%1,%2,%3}, {%4,%5,%6,%7}, {%8,%9}, {%0,%1,%2,%3};\n"
        : "+f"(c[0]), "+f"(c[1]), "+f"(c[2]), "+f"(c[3])
        : "r"(a[0]), "r"(a[1]), "r"(a[2]), "r"(a[3]), "r"(b[0]), "r"(b[1]));
}

__device__ __forceinline__ unsigned smaddr(const void* p) {
    return (unsigned)__cvta_generic_to_shared(p);
}
__device__ __forceinline__ void ldm_x2(unsigned& r0, unsigned& r1, unsigned a) {
    asm volatile("ldmatrix.sync.aligned.m8n8.x2.shared.b16 {%0,%1}, [%2];"
                 : "=r"(r0), "=r"(r1) : "r"(a));
}
__device__ __forceinline__ void ldm_x2_t(unsigned& r0, unsigned& r1, unsigned a) {
    asm volatile("ldmatrix.sync.aligned.m8n8.x2.trans.shared.b16 {%0,%1}, [%2];"
                 : "=r"(r0), "=r"(r1) : "r"(a));
}
__device__ __forceinline__ void ldm_x4(unsigned* r, unsigned a) {
    asm volatile("ldmatrix.sync.aligned.m8n8.x4.shared.b16 {%0,%1,%2,%3}, [%4];"
                 : "=r"(r[0]), "=r"(r[1]), "=r"(r[2]), "=r"(r[3]) : "r"(a));
}
__device__ __forceinline__ void cpa16(void* smem, const void* gmem) {
    asm volatile("cp.async.cg.shared.global [%0], [%1], 16;"
                 :: "r"(smaddr(smem)), "l"(gmem));
}
__device__ __forceinline__ __half2 h2ex2(__half2 x) {
    unsigned r, xi = *(unsigned*)&x;
    asm("ex2.approx.f16x2 %0, %1;" : "=r"(r) : "r"(xi));
    return *(__half2*)&r;
}

#define CE 0.25506382f   // (1/sqrt(32)) * log2(e)

// ---------------- fp16 tensor-core GEMM (up to 3 problems via blockIdx.z, per-z K) ----------------
// If gsrc != null, the LAST z-slice converts G fp32 -> fp16*CE instead.
template<int OM>
__global__ __launch_bounds__(256) void gemm16_kernel(
    const float* __restrict__ A0, const float* __restrict__ W0, const float* __restrict__ bs0,
    float* __restrict__ Cf0, __half* __restrict__ Ch0, int M0,
    const float* __restrict__ A1, const float* __restrict__ W1, const float* __restrict__ bs1,
    float* __restrict__ Cf1, __half* __restrict__ Ch1, int M1,
    const float* __restrict__ A2, const float* __restrict__ W2, const float* __restrict__ bs2,
    float* __restrict__ Cf2, __half* __restrict__ Ch2, int M2,
    int N, int K0p, int K1p, int K2p,
    const float* __restrict__ gsrc, __half* __restrict__ gdst)
{
    if (gsrc != nullptr && blockIdx.z == gridDim.z - 1) {
        int bid = blockIdx.y * gridDim.x + blockIdx.x;
        int t4 = bid * 256 + threadIdx.x;
        const int total4 = (NS * NC) / 4;
        int stride = gridDim.x * gridDim.y * 256;
        for (int i = t4; i < total4; i += stride) {
            float4 v = *(const float4*)&gsrc[(size_t)i * 4];
            __half2 h0 = __floats2half2_rn(v.x * CE, v.y * CE);
            __half2 h1 = __floats2half2_rn(v.z * CE, v.w * CE);
            *(int2*)&gdst[(size_t)i * 4] = make_int2(*(int*)&h0, *(int*)&h1);
        }
        return;
    }

    const int z = blockIdx.z;
    const float* A    = z == 0 ? A0  : (z == 1 ? A1  : A2);
    const float* W    = z == 0 ? W0  : (z == 1 ? W1  : W2);
    const float* bias = z == 0 ? bs0 : (z == 1 ? bs1 : bs2);
    float* Cf         = z == 0 ? Cf0 : (z == 1 ? Cf1 : Cf2);
    __half* Ch        = z == 0 ? Ch0 : (z == 1 ? Ch1 : Ch2);
    const int M       = z == 0 ? M0  : (z == 1 ? M1  : M2);
    const int K       = z == 0 ? K0p : (z == 1 ? K1p : K2p);

    const int bm = blockIdx.y * 64, bn = blockIdx.x * 64;
    if (bm >= M) return;

    __shared__ __half Ah[64 * 40];
    __shared__ __half Bh[64 * 40];

    const int tid = threadIdx.x;
    const int w = tid >> 5, lane = tid & 31;
    const int wr = w >> 1, wc = w & 1;
    const int gr = lane >> 2, cc = lane & 3;
    const int fr = tid >> 2, fc8 = (tid & 3) * 8;
    const int l4 = lane & 15;
    const int hi8 = (lane >> 4) * 8;

    float acc[4][4] = {};

    for (int k0 = 0; k0 < K; k0 += 32) {
        __syncthreads();
        {
            float4 a0v = make_float4(0.f, 0.f, 0.f, 0.f), a1v = a0v;
            if (bm + fr < M) {
                const float* ap = &A[(size_t)(bm + fr) * K + k0 + fc8];
                a0v = *(const float4*)ap;
                a1v = *(const float4*)(ap + 4);
            }
            __half2 h0 = __floats2half2_rn(a0v.x, a0v.y);
            __half2 h1 = __floats2half2_rn(a0v.z, a0v.w);
            __half2 h2 = __floats2half2_rn(a1v.x, a1v.y);
            __half2 h3 = __floats2half2_rn(a1v.z, a1v.w);
            int4 pk = make_int4(*(int*)&h0, *(int*)&h1, *(int*)&h2, *(int*)&h3);
            *(int4*)&Ah[fr * 40 + fc8] = pk;

            const float* wp = &W[(size_t)(bn + fr) * K + k0 + fc8];
            float4 b0v = *(const float4*)wp;
            float4 b1v = *(const float4*)(wp + 4);
            __half2 g0 = __floats2half2_rn(b0v.x, b0v.y);
            __half2 g1 = __floats2half2_rn(b0v.z, b0v.w);
            __half2 g2 = __floats2half2_rn(b1v.x, b1v.y);
            __half2 g3 = __floats2half2_rn(b1v.z, b1v.w);
            int4 pk2 = make_int4(*(int*)&g0, *(int*)&g1, *(int*)&g2, *(int*)&g3);
            *(int4*)&Bh[fr * 40 + fc8] = pk2;
        }
        __syncthreads();

#pragma unroll
        for (int ks = 0; ks < 2; ks++) {
            unsigned af[4];
            ldm_x4(af, smaddr(&Ah[(wr * 16 + l4) * 40 + ks * 16 + hi8]));
            unsigned bf[2][4];
#pragma unroll
            for (int p = 0; p < 2; p++)
                ldm_x4(bf[p], smaddr(&Bh[(wc * 32 + p * 16 + l4) * 40 + ks * 16 + hi8]));
#pragma unroll
            for (int nt = 0; nt < 4; nt++) {
                unsigned bb[2];
                bb[0] = bf[nt >> 1][(nt & 1)];
                bb[1] = bf[nt >> 1][(nt & 1) + 2];
                mma16816(acc[nt], af, bb);
            }
        }
    }

#pragma unroll
    for (int nt = 0; nt < 4; nt++) {
        int col = bn + wc * 32 + nt * 8 + 2 * cc;
        float b0 = bias ? bias[col] : 0.f;
        float b1 = bias ? bias[col + 1] : 0.f;
        int row0 = bm + wr * 16 + gr;
        int row1 = row0 + 8;
        if (row0 < M) {
            if (OM == 1) {
                Ch[(size_t)row0 * N + col]     = __float2half(acc[nt][0] + b0);
                Ch[(size_t)row0 * N + col + 1] = __float2half(acc[nt][1] + b1);
            } else {
                Cf[(size_t)row0 * N + col]     = acc[nt][0] + b0;
                Cf[(size_t)row0 * N + col + 1] = acc[nt][1] + b1;
            }
        }
        if (row1 < M) {
            if (OM == 1) {
                Ch[(size_t)row1 * N + col]     = __float2half(acc[nt][2] + b0);
                Ch[(size_t)row1 * N + col + 1] = __float2half(acc[nt][3] + b1);
            } else {
                Cf[(size_t)row1 * N + col]     = acc[nt][2] + b0;
                Cf[(size_t)row1 * N + col + 1] = acc[nt][3] + b1;
            }
        }
    }
}

// ---------------- fused gated cross-attention: 32 s-rows per block ----------------
#define CA_SMEM 105600
__global__ __launch_bounds__(256, 2) void ca_fused_kernel()
{
    extern __shared__ __align__(16) char smraw[];
    __half* Ks  = (__half*)smraw;
    __half* Vs  = (__half*)(smraw + 40960);
    __half* Ghs = (__half*)(smraw + 81920);
    __half* Qs  = (__half*)(smraw + 98816);
    float*  Hs  = (float*)(smraw + 101376);
    float*  Zs  = (float*)(smraw + 105472);

    const int h = blockIdx.x;
    const int s0 = blockIdx.y * 32;
    const int tid = threadIdx.x;
    const int w = tid >> 5, lane = tid & 31;
    const int gr = lane >> 2, cc = lane & 3;
    const int cw = w * 32;
    const int l4 = lane & 15;

    auto issue_tile = [&](int ci) {
        int buf = (ci & 1) * 10240;
        int c0 = ci * 256;
        int pr = tid >> 2, pp4 = tid & 3;
#pragma unroll
        for (int rr = 0; rr < 4; rr++) {
            int row = rr * 64 + pr;
            size_t src = (size_t)(c0 + row) * D + h * 32 + pp4 * 8;
            cpa16(&Ks[buf + row * 40 + pp4 * 8], &g_Kh[src]);
            cpa16(&Vs[buf + row * 40 + pp4 * 8], &g_Vh[src]);
        }
#pragma unroll
        for (int t = 0; t < 4; t++) {
            int idx = t * 256 + tid;
            int r = idx >> 5, pp = idx & 31;
            cpa16(&Ghs[r * 264 + pp * 8], &g_Gh[(size_t)(s0 + r) * NC + c0 + pp * 8]);
        }
        asm volatile("cp.async.commit_group;");
    };

#pragma unroll
    for (int t = 0; t < 2; t++) {
        int idx = t * 256 + tid;
        int row = idx >> 4, c2 = (idx & 15) * 2;
        *(unsigned*)&Qs[row * 40 + c2] =
            *(const unsigned*)&g_Qh[(size_t)(s0 + row) * D + h * 32 + c2];
    }
#pragma unroll
    for (int k = 0; k < 4; k++) Hs[k * 256 + tid] = 0.f;
    if (tid < 32) Zs[tid] = 0.f;

    issue_tile(0);
    __syncthreads();

    unsigned qa[2][2][4];
#pragma unroll
    for (int sh = 0; sh < 2; sh++)
#pragma unroll
        for (int ks = 0; ks < 2; ks++)
            ldm_x4(qa[sh][ks], smaddr(&Qs[(sh * 16 + l4) * 40 + ks * 16 + (lane >> 4) * 8]));

    float hacc[2][4][4] = {};
    float zacc[2][2] = {};

    for (int ci = 0; ci < 16; ci++) {
        int buf = (ci & 1) * 10240;
        asm volatile("cp.async.wait_group 0;" ::: "memory");
        __syncthreads();

        unsigned gf[2][4][2];
#pragma unroll
        for (int sh = 0; sh < 2; sh++)
#pragma unroll
            for (int nt = 0; nt < 4; nt++)
                ldm_x2(gf[sh][nt][0], gf[sh][nt][1],
                       smaddr(&Ghs[(sh * 16 + l4) * 264 + cw + nt * 8]));
        __syncthreads();
        if (ci < 15) issue_tile(ci + 1);

#pragma unroll
        for (int sh = 0; sh < 2; sh++) {
            unsigned pa[2][4];
#pragma unroll
            for (int nt = 0; nt < 4; nt++) {
                float S[4] = {0.f, 0.f, 0.f, 0.f};
#pragma unroll
                for (int ks = 0; ks < 2; ks++) {
                    unsigned b[2];
                    ldm_x2(b[0], b[1],
                           smaddr(&Ks[buf + (cw + nt * 8 + (l4 & 7)) * 40 + ks * 16 + (l4 >> 3) * 8]));
                    mma16816(S, qa[sh][ks], b);
                }
                __half2 x01 = __hmul2(__floats2half2_rn(S[0], S[1]), *(__half2*)&gf[sh][nt][0]);
                __half2 x23 = __hmul2(__floats2half2_rn(S[2], S[3]), *(__half2*)&gf[sh][nt][1]);
                __half2 p01 = h2ex2(x01);
                __half2 p23 = h2ex2(x23);
                float2 f01 = __half22float2(p01);
                float2 f23 = __half22float2(p23);
                zacc[sh][0] += f01.x + f01.y;
                zacc[sh][1] += f23.x + f23.y;
                unsigned u01 = *(unsigned*)&p01, u23 = *(unsigned*)&p23;
                if ((nt & 1) == 0) { pa[nt >> 1][0] = u01; pa[nt >> 1][1] = u23; }
                else               { pa[nt >> 1][2] = u01; pa[nt >> 1][3] = u23; }
            }
#pragma unroll
            for (int nt2 = 0; nt2 < 4; nt2++) {
#pragma unroll
                for (int ks2 = 0; ks2 < 2; ks2++) {
                    unsigned b[2];
                    ldm_x2_t(b[0], b[1],
                             smaddr(&Vs[buf + (cw + ks2 * 16 + l4) * 40 + nt2 * 8]));
                    mma16816(hacc[sh][nt2], pa[ks2], b);
                }
            }
        }
    }

#pragma unroll
    for (int sh = 0; sh < 2; sh++) {
        float z0 = zacc[sh][0], z1 = zacc[sh][1];
#pragma unroll
        for (int o = 1; o < 4; o <<= 1) {
            z0 += __shfl_xor_sync(0xffffffffu, z0, o);
            z1 += __shfl_xor_sync(0xffffffffu, z1, o);
        }
        if (cc == 0) {
            atomicAdd(&Zs[sh * 16 + gr], z0);
            atomicAdd(&Zs[sh * 16 + gr + 8], z1);
        }
#pragma unroll
        for (int nt2 = 0; nt2 < 4; nt2++) {
            atomicAdd(&Hs[(sh * 16 + gr) * 32 + nt2 * 8 + 2 * cc],           hacc[sh][nt2][0]);
            atomicAdd(&Hs[(sh * 16 + gr) * 32 + nt2 * 8 + 2 * cc + 1],       hacc[sh][nt2][1]);
            atomicAdd(&Hs[(sh * 16 + gr + 8) * 32 + nt2 * 8 + 2 * cc],       hacc[sh][nt2][2]);
            atomicAdd(&Hs[(sh * 16 + gr + 8) * 32 + nt2 * 8 + 2 * cc + 1],   hacc[sh][nt2][3]);
        }
    }
    __syncthreads();
    if (tid < 32) g_Z[(s0 + tid) * NH + h] = Zs[tid];
#pragma unroll
    for (int k = 0; k < 4; k++) {
        int idx = k * 256 + tid;
        int row = idx >> 5, d = idx & 31;
        g_Hnew[(size_t)(s0 + row) * D + h * 32 + d] = Hs[idx] / Zs[row];
    }
}

// ---------------- attn_map by QK recompute: 32 s-rows per block ----------------
#define AT_SMEM 111104
__global__ __launch_bounds__(256, 2) void attn_recompute_kernel(float* __restrict__ AM)
{
    extern __shared__ __align__(16) char smraw[];
    __half* Ks  = (__half*)smraw;
    __half* Qs  = (__half*)(smraw + 67584);
    __half* Ghs = (__half*)(smraw + 84480);
    float*  AMs = (float*)(smraw + 93184);
    float*  iZ  = (float*)(smraw + 110080);

    const int c0 = blockIdx.x * 128;
    const int s0 = blockIdx.y * 32;
    const int tid = threadIdx.x;
    const int w = tid >> 5, lane = tid & 31;
    const int gr = lane >> 2, cc = lane & 3;
    const int l4 = lane & 15;
    const int hi8 = (lane >> 4) * 8;
    const int cw16 = w * 16;

#pragma unroll
    for (int t = 0; t < 16; t++) {
        int idx = t * 256 + tid;
        int r = idx >> 5, pp = idx & 31;
        cpa16(&Ks[r * 264 + pp * 8], &g_Kh[(size_t)(c0 + r) * D + pp * 8]);
    }
#pragma unroll
    for (int t = 0; t < 4; t++) {
        int idx = t * 256 + tid;
        int r = idx >> 5, pp = idx & 31;
        cpa16(&Qs[r * 264 + pp * 8], &g_Qh[(size_t)(s0 + r) * D + pp * 8]);
    }
#pragma unroll
    for (int t = 0; t < 2; t++) {
        int idx = t * 256 + tid;
        int r = idx >> 4, pp = idx & 15;
        cpa16(&Ghs[r * 136 + pp * 8], &g_Gh[(size_t)(s0 + r) * NC + c0 + pp * 8]);
    }
    asm volatile("cp.async.commit_group;");
    {
        int s = tid >> 3, hh = tid & 7;
        iZ[tid] = 0.125f / g_Z[(s0 + s) * NH + hh];
    }
    asm volatile("cp.async.wait_group 0;" ::: "memory");
    __syncthreads();

    unsigned gfr[2][2][2];
#pragma unroll
    for (int sh = 0; sh < 2; sh++)
#pragma unroll
        for (int nt = 0; nt < 2; nt++)
            ldm_x2(gfr[sh][nt][0], gfr[sh][nt][1],
                   smaddr(&Ghs[(sh * 16 + l4) * 136 + cw16 + nt * 8]));

    float acc[2][2][4] = {};
#pragma unroll
    for (int h = 0; h < NH; h++) {
        unsigned kb[2][4];
#pragma unroll
        for (int ks = 0; ks < 2; ks++)
            ldm_x4(kb[ks], smaddr(&Ks[(cw16 + l4) * 264 + h * 32 + ks * 16 + hi8]));
#pragma unroll
        for (int sh = 0; sh < 2; sh++) {
            unsigned qa[2][4];
#pragma unroll
            for (int ks = 0; ks < 2; ks++)
                ldm_x4(qa[ks], smaddr(&Qs[(sh * 16 + l4) * 264 + h * 32 + ks * 16 + hi8]));
            float izA = iZ[(sh * 16 + gr) * 8 + h];
            float izB = iZ[(sh * 16 + gr + 8) * 8 + h];
#pragma unroll
            for (int nt = 0; nt < 2; nt++) {
                float S[4] = {0.f, 0.f, 0.f, 0.f};
#pragma unroll
                for (int ks = 0; ks < 2; ks++) {
                    unsigned bb[2];
                    bb[0] = kb[ks][nt];
                    bb[1] = kb[ks][nt + 2];
                    mma16816(S, qa[ks], bb);
                }
                __half2 x01 = __hmul2(__floats2half2_rn(S[0], S[1]), *(__half2*)&gfr[sh][nt][0]);
                __half2 x23 = __hmul2(__floats2half2_rn(S[2], S[3]), *(__half2*)&gfr[sh][nt][1]);
                float2 f01 = __half22float2(h2ex2(x01));
                float2 f23 = __half22float2(h2ex2(x23));
                acc[sh][nt][0] += f01.x * izA;
                acc[sh][nt][1] += f01.y * izA;
                acc[sh][nt][2] += f23.x * izB;
                acc[sh][nt][3] += f23.y * izB;
            }
        }
    }

#pragma unroll
    for (int sh = 0; sh < 2; sh++)
#pragma unroll
        for (int nt = 0; nt < 2; nt++) {
            int col = cw16 + nt * 8 + 2 * cc;
            *(float2*)&AMs[(sh * 16 + gr) * 132 + col]       = make_float2(acc[sh][nt][0], acc[sh][nt][1]);
            *(float2*)&AMs[(sh * 16 + gr + 8) * 132 + col]   = make_float2(acc[sh][nt][2], acc[sh][nt][3]);
        }
    __syncthreads();
#pragma unroll
    for (int t = 0; t < 4; t++) {
        int idx = t * 256 + tid;
        int r = idx >> 5, p4 = idx & 31;
        *(float4*)&AM[(size_t)(s0 + r) * NC + c0 + p4 * 4] = *(const float4*)&AMs[r * 132 + p4 * 4];
    }
}

// ---------------- cross-attn epilogue LN ----------------
__global__ __launch_bounds__(256) void ln_ca_kernel(
    const float* __restrict__ g, const float* __restrict__ b, const float* __restrict__ fusion)
{
    int tid = threadIdx.x;
    if (blockIdx.x == 0 && tid < D) g_tok[tid] = fusion[tid];
    int warp = tid >> 5, lane = tid & 31;
    int row = blockIdx.x * 8 + warp;
    float x[8];
    float s = 0.f;
#pragma unroll
    for (int j = 0; j < 8; j++) {
        int c = lane + 32 * j;
        x[j] = g_tmp[(size_t)row * D + c] + g_HS[(size_t)row * D + c];
        s += x[j];
    }
    s = warpSum(s);
    float m = s * (1.0f / D);
    float vs = 0.f;
#pragma unroll
    for (int j = 0; j < 8; j++) { float d = x[j] - m; vs += d * d; }
    vs = warpSum(vs);
    float r = rsqrtf(vs * (1.0f / D) + 1e-5f);
#pragma unroll
    for (int j = 0; j < 8; j++) {
        int c = lane + 32 * j;
        g_tok[(size_t)(1 + row) * D + c] = (x[j] - m) * r * g[c] + b[c];
    }
}

// ---------------- fused q0 + row-0 scores + AV over tokens (per-block partials) ----------------
__global__ __launch_bounds__(256) void sa0_kernel(
    const float* __restrict__ fusion,
    const float* __restrict__ w, const float* __restrict__ bqkv)
{
    __shared__ float fs[D];
    __shared__ float q0s[D];
    __shared__ float zpart[NH];
    __shared__ float a0s[D];
    int tid = threadIdx.x;
    fs[tid] = fusion[tid];
    a0s[tid] = 0.f;
    if (tid < NH) zpart[tid] = 0.f;
    __syncthreads();
    // q0 (redundant per block; 65K MAC)
    {
        float a = bqkv[tid];
        const float* wr_ = &w[(size_t)tid * D];
        for (int c = 0; c < D; c++) a += fs[c] * wr_[c];
        q0s[tid] = a;
    }
    __syncthreads();

    int warp = tid >> 5, lane = tid & 31;
    int wtotal = gridDim.x * 8;
    const float isq = 0.17677669529663687f;
    float acc[8] = {};
    float zacc = 0.f;
    for (int u = blockIdx.x * 8 + warp; u < TT; u += wtotal) {
        float mine = 0.f;
#pragma unroll
        for (int j = 0; j < 8; j++) {
            int c = lane + 32 * j;
            float v = q0s[c] * g_k2[(size_t)u * D + c];
            v = warpSum(v);
            if (lane == j) mine = v;
        }
        float pl = __expf(mine * isq);
        if (lane < 8) zacc += pl;
        float ph = __shfl_sync(0xffffffffu, pl, lane >> 2);
        const float* vrow = &g_v2[(size_t)u * D + lane * 8];
        float4 v0 = *(const float4*)vrow;
        float4 v1 = *(const float4*)(vrow + 4);
        acc[0] += ph * v0.x; acc[1] += ph * v0.y; acc[2] += ph * v0.z; acc[3] += ph * v0.w;
        acc[4] += ph * v1.x; acc[5] += ph * v1.y; acc[6] += ph * v1.z; acc[7] += ph * v1.w;
    }
    if (lane < 8) atomicAdd(&zpart[lane], zacc);
#pragma unroll
    for (int j = 0; j < 8; j++)
        atomicAdd(&a0s[lane * 8 + j], acc[j]);
    __syncthreads();
    g_a0p[blockIdx.x][tid] = a0s[tid];
    if (tid < NH) g_Z0p[blockIdx.x][tid] = zpart[tid];
}

// ---------------- final head ----------------
__device__ __forceinline__ float blockSum256(float v, volatile float* red) {
    int lane = threadIdx.x & 31, w = threadIdx.x >> 5;
    v = warpSum(v);
    __syncthreads();
    if (lane == 0) red[w] = v;
    __syncthreads();
    float s = 0.f;
#pragma unroll
    for (int i = 0; i < 8; i++) s += red[i];
    return s;
}

__global__ __launch_bounds__(256) void final_kernel(
    const float* __restrict__ fusion,
    const float* __restrict__ mow, const float* __restrict__ mob,
    const float* __restrict__ ln1g, const float* __restrict__ ln1b,
    const float* __restrict__ w1, const float* __restrict__ b1,
    const float* __restrict__ w2, const float* __restrict__ b2,
    const float* __restrict__ ln2g, const float* __restrict__ ln2b,
    float* __restrict__ out)
{
    __shared__ float a0[D], t1[D], h1[2 * D];
    __shared__ float red[8];
    int tid = threadIdx.x;
    {
        float av = 0.f, zv = 0.f;
        int hh = tid >> 5;
#pragma unroll
        for (int b = 0; b < SA0_BLOCKS; b++) {
            av += g_a0p[b][tid];
            zv += g_Z0p[b][hh];
        }
        a0[tid] = av / zv;
    }
    __syncthreads();
    float y = mob[tid];
    for (int j = 0; j < D; j++) y += a0[j] * mow[(size_t)tid * D + j];
    float tv = fusion[tid] + y;
    float m = blockSum256(tv, red) * (1.0f / D);
    float d = tv - m;
    float var = blockSum256(d * d, red) * (1.0f / D);
    float t = d * rsqrtf(var + 1e-5f) * ln1g[tid] + ln1b[tid];
    t1[tid] = t;
    __syncthreads();
    float hh2[2];
#pragma unroll
    for (int r2 = 0; r2 < 2; r2++) {
        int jj = tid + r2 * 256;
        float a = b1[jj];
        for (int c = 0; c < D; c++) a += t1[c] * w1[(size_t)jj * D + c];
        hh2[r2] = a * 0.5f * (1.f + erff(a * 0.70710678118654752f));
    }
    h1[tid] = hh2[0];
    h1[tid + 256] = hh2[1];
    __syncthreads();
    float o = b2[tid];
    for (int j = 0; j < 512; j++) o += h1[j] * w2[(size_t)tid * 512 + j];
    float t2v = t1[tid] + o;   // residual = LN1 output
    float m2 = blockSum256(t2v, red) * (1.0f / D);
    float d2 = t2v - m2;
    float v2 = blockSum256(d2 * d2, red) * (1.0f / D);
    out[tid] = d2 * rsqrtf(v2 + 1e-5f) * ln2g[tid] + ln2b[tid];
}

// ---------------- launcher ----------------
extern "C" void kernel_launch(void* const* d_in, const int* in_sizes, int n_in,
                              void* d_out, int out_size)
{
    const float* H_S     = (const float*)d_in[0];
    const float* H_C     = (const float*)d_in[1];
    const float* H_G     = (const float*)d_in[2];
    const float* G_glyph = (const float*)d_in[3];
    const float* Ws      = (const float*)d_in[4];
    const float* bs      = (const float*)d_in[5];
    const float* Wb      = (const float*)d_in[6];
    const float* bb      = (const float*)d_in[7];
    const float* Wg      = (const float*)d_in[8];
    const float* bg      = (const float*)d_in[9];
    const float* WQ      = (const float*)d_in[10];
    const float* WK      = (const float*)d_in[11];
    const float* WV      = (const float*)d_in[12];
    const float* WO      = (const float*)d_in[13];
    const float* bO      = (const float*)d_in[14];
    const float* ln_ca_g = (const float*)d_in[15];
    const float* ln_ca_b = (const float*)d_in[16];
    const float* fusion  = (const float*)d_in[17];
    const float* mha_in_w  = (const float*)d_in[18];
    const float* mha_in_b  = (const float*)d_in[19];
    const float* mha_out_w = (const float*)d_in[20];
    const float* mha_out_b = (const float*)d_in[21];
    const float* ln1_g   = (const float*)d_in[22];
    const float* ln1_b   = (const float*)d_in[23];
    const float* ln2_g   = (const float*)d_in[24];
    const float* ln2_b   = (const float*)d_in[25];
    const float* ffn_w1  = (const float*)d_in[26];
    const float* ffn_b1  = (const float*)d_in[27];
    const float* ffn_w2  = (const float*)d_in[28];
    const float* ffn_b2  = (const float*)d_in[29];

    float* out = (float*)d_out;
    float* z_fused  = out;        // 256
    float* attn_map = out + D;    // 2048 * 4096

    float *pHS, *pHC, *pHnew, *pTmp, *pTok, *pk2, *pv2;
    __half *pQh, *pKh, *pVh, *pGh;
    cudaGetSymbolAddress((void**)&pHS,  g_HS);
    cudaGetSymbolAddress((void**)&pHC,  g_HC);
    cudaGetSymbolAddress((void**)&pQh,  g_Qh);
    cudaGetSymbolAddress((void**)&pKh,  g_Kh);
    cudaGetSymbolAddress((void**)&pVh,  g_Vh);
    cudaGetSymbolAddress((void**)&pGh,  g_Gh);
    cudaGetSymbolAddress((void**)&pHnew,g_Hnew);
    cudaGetSymbolAddress((void**)&pTmp, g_tmp);
    cudaGetSymbolAddress((void**)&pTok, g_tok);
    cudaGetSymbolAddress((void**)&pk2,  g_k2);
    cudaGetSymbolAddress((void**)&pv2,  g_v2);

    static bool attrSet = false;
    if (!attrSet) {
        cudaFuncSetAttribute(ca_fused_kernel,
                             cudaFuncAttributeMaxDynamicSharedMemorySize, CA_SMEM);
        cudaFuncSetAttribute(attn_recompute_kernel,
                             cudaFuncAttributeMaxDynamicSharedMemorySize, AT_SMEM);
        attrSet = true;
    }

    // #1 HS (z0, K=128) + HG (z1, K=64) + HC (z2, K=256) + gate conversion (z3)
    gemm16_kernel<0><<<dim3(4, 64, 4), 256>>>(
        H_S, Ws, bs, pHS, nullptr, NS,
        H_G, Wg, bg, pTok + (size_t)(1 + NS) * D, nullptr, NG,
        H_C, Wb, bb, pHC, nullptr, NC, D, 128, 64, 256, G_glyph, pGh);
    // #2 Q/K/V triple (fp16 out)
    gemm16_kernel<1><<<dim3(4, 64, 3), 256>>>(
        pHS, WQ, nullptr, nullptr, pQh, NS,
        pHC, WK, nullptr, nullptr, pKh, NC,
        pHC, WV, nullptr, nullptr, pVh, NC, D, 256, 256, 256, nullptr, nullptr);
    // #3 fused gated cross attention (Z + Hnew)
    ca_fused_kernel<<<dim3(NH, NS / 32), 256, CA_SMEM>>>();
    // #4 attn_map via QK recompute  <-- ncu capture target this round
    attn_recompute_kernel<<<dim3(NC / 128, NS / 32), 256, AT_SMEM>>>(attn_map);
    // #5 O projection
    gemm16_kernel<0><<<dim3(4, 32), 256>>>(
        pHnew, WO, bO, pTmp, nullptr, NS,
        pHnew, WO, bO, pTmp, nullptr, NS,
        pHnew, WO, bO, pTmp, nullptr, NS, D, 256, 256, 256, nullptr, nullptr);
    // #6 residual LN -> tokens
    ln_ca_kernel<<<NS / 8, 256>>>(ln_ca_g, ln_ca_b, fusion);
    // #7 self-attn K/V over tokens (dual)
    gemm16_kernel<0><<<dim3(4, 65, 2), 256>>>(
        pTok, mha_in_w + 256 * 256, mha_in_b + 256, pk2, nullptr, TT,
        pTok, mha_in_w + 512 * 256, mha_in_b + 512, pv2, nullptr, TT,
        pTok, mha_in_w + 256 * 256, mha_in_b + 256, pk2, nullptr, TT, D, 256, 256, 256, nullptr, nullptr);
    // #8 token-0 attention (q0 + scores + AV, per-block partials)
    sa0_kernel<<<SA0_BLOCKS, 256>>>(fusion, mha_in_w, mha_in_b);
    // #9 head
    final_kernel<<<1, 256>>>(fusion, mha_out_w, mha_out_b, ln1_g, ln1_b,
                             ffn_w1, ffn_b1, ffn_w2, ffn_b2, ln2_g, ln2_b, z_fused);
}

// round 12
// speedup vs baseline: 2.8073x; 1.0049x over previous
#include <cuda_runtime.h>
#include <cuda_fp16.h>

#define NS 2048
#define NC 4096
#define NG 2048
#define D  256
#define NH 8
#define TT 4097   // 1 + NS + NG
#define SA0_BLOCKS 32

// ---------------- device scratch ----------------
__device__ float  g_HS[NS * D];
__device__ float  g_HC[NC * D];
__device__ __half g_Qh[NS * D];
__device__ __half g_Kh[NC * D];
__device__ __half g_Vh[NC * D];
__device__ __half g_Gh[(size_t)NS * NC];   // gate * (isq*log2e), fp16
__device__ float  g_Z[NS * NH];
__device__ float  g_Hnew[NS * D];
__device__ float  g_tmp[NS * D];
__device__ float  g_tok[TT * D];
__device__ float  g_k2[TT * D];
__device__ float  g_v2[TT * D];
__device__ float  g_a0p[SA0_BLOCKS][D];
__device__ float  g_Z0p[SA0_BLOCKS][NH];

__device__ __forceinline__ float warpSum(float v) {
#pragma unroll
    for (int o = 16; o; o >>= 1) v += __shfl_xor_sync(0xffffffffu, v, o);
    return v;
}

__device__ __forceinline__ void mma16816(float* c, const unsigned* a, const unsigned* b) {
    asm volatile(
        "mma.sync.aligned.m16n8k16.row.col.f32.f16.f16.f32 "
        "{%0,%1,%2,%3}, {%4,%5,%6,%7}, {%8,%9}, {%0,%1,%2,%3};\n"
        : "+f"(c[0]), "+f"(c[1]), "+f"(c[2]), "+f"(c[3])
        : "r"(a[0]), "r"(a[1]), "r"(a[2]), "r"(a[3]), "r"(b[0]), "r"(b[1]));
}

__device__ __forceinline__ unsigned smaddr(const void* p) {
    return (unsigned)__cvta_generic_to_shared(p);
}
__device__ __forceinline__ void ldm_x2(unsigned& r0, unsigned& r1, unsigned a) {
    asm volatile("ldmatrix.sync.aligned.m8n8.x2.shared.b16 {%0,%1}, [%2];"
                 : "=r"(r0), "=r"(r1) : "r"(a));
}
__device__ __forceinline__ void ldm_x2_t(unsigned& r0, unsigned& r1, unsigned a) {
    asm volatile("ldmatrix.sync.aligned.m8n8.x2.trans.shared.b16 {%0,%1}, [%2];"
                 : "=r"(r0), "=r"(r1) : "r"(a));
}
__device__ __forceinline__ void ldm_x4(unsigned* r, unsigned a) {
    asm volatile("ldmatrix.sync.aligned.m8n8.x4.shared.b16 {%0,%1,%2,%3}, [%4];"
                 : "=r"(r[0]), "=r"(r[1]), "=r"(r[2]), "=r"(r[3]) : "r"(a));
}
__device__ __forceinline__ void cpa16(void* smem, const void* gmem) {
    asm volatile("cp.async.cg.shared.global [%0], [%1], 16;"
                 :: "r"(smaddr(smem)), "l"(gmem));
}
__device__ __forceinline__ __half2 h2ex2(__half2 x) {
    unsigned r, xi = *(unsigned*)&x;
    asm("ex2.approx.f16x2 %0, %1;" : "=r"(r) : "r"(xi));
    return *(__half2*)&r;
}

#define CE 0.25506382f   // (1/sqrt(32)) * log2(e)

// ---------------- fp16 tensor-core GEMM (up to 3 problems via blockIdx.z, per-z K) ----------------
// If gsrc != null, the LAST z-slice converts G fp32 -> fp16*CE instead.
template<int OM>
__global__ __launch_bounds__(256) void gemm16_kernel(
    const float* __restrict__ A0, const float* __restrict__ W0, const float* __restrict__ bs0,
    float* __restrict__ Cf0, __half* __restrict__ Ch0, int M0,
    const float* __restrict__ A1, const float* __restrict__ W1, const float* __restrict__ bs1,
    float* __restrict__ Cf1, __half* __restrict__ Ch1, int M1,
    const float* __restrict__ A2, const float* __restrict__ W2, const float* __restrict__ bs2,
    float* __restrict__ Cf2, __half* __restrict__ Ch2, int M2,
    int N, int K0p, int K1p, int K2p,
    const float* __restrict__ gsrc, __half* __restrict__ gdst)
{
    if (gsrc != nullptr && blockIdx.z == gridDim.z - 1) {
        int bid = blockIdx.y * gridDim.x + blockIdx.x;
        int t4 = bid * 256 + threadIdx.x;
        const int total4 = (NS * NC) / 4;
        int stride = gridDim.x * gridDim.y * 256;
        for (int i = t4; i < total4; i += stride) {
            float4 v = *(const float4*)&gsrc[(size_t)i * 4];
            __half2 h0 = __floats2half2_rn(v.x * CE, v.y * CE);
            __half2 h1 = __floats2half2_rn(v.z * CE, v.w * CE);
            *(int2*)&gdst[(size_t)i * 4] = make_int2(*(int*)&h0, *(int*)&h1);
        }
        return;
    }

    const int z = blockIdx.z;
    const float* A    = z == 0 ? A0  : (z == 1 ? A1  : A2);
    const float* W    = z == 0 ? W0  : (z == 1 ? W1  : W2);
    const float* bias = z == 0 ? bs0 : (z == 1 ? bs1 : bs2);
    float* Cf         = z == 0 ? Cf0 : (z == 1 ? Cf1 : Cf2);
    __half* Ch        = z == 0 ? Ch0 : (z == 1 ? Ch1 : Ch2);
    const int M       = z == 0 ? M0  : (z == 1 ? M1  : M2);
    const int K       = z == 0 ? K0p : (z == 1 ? K1p : K2p);

    const int bm = blockIdx.y * 64, bn = blockIdx.x * 64;
    if (bm >= M) return;

    __shared__ __half Ah[64 * 40];
    __shared__ __half Bh[64 * 40];

    const int tid = threadIdx.x;
    const int w = tid >> 5, lane = tid & 31;
    const int wr = w >> 1, wc = w & 1;
    const int gr = lane >> 2, cc = lane & 3;
    const int fr = tid >> 2, fc8 = (tid & 3) * 8;
    const int l4 = lane & 15;
    const int hi8 = (lane >> 4) * 8;

    float acc[4][4] = {};

    for (int k0 = 0; k0 < K; k0 += 32) {
        __syncthreads();
        {
            float4 a0v = make_float4(0.f, 0.f, 0.f, 0.f), a1v = a0v;
            if (bm + fr < M) {
                const float* ap = &A[(size_t)(bm + fr) * K + k0 + fc8];
                a0v = *(const float4*)ap;
                a1v = *(const float4*)(ap + 4);
            }
            __half2 h0 = __floats2half2_rn(a0v.x, a0v.y);
            __half2 h1 = __floats2half2_rn(a0v.z, a0v.w);
            __half2 h2 = __floats2half2_rn(a1v.x, a1v.y);
            __half2 h3 = __floats2half2_rn(a1v.z, a1v.w);
            int4 pk = make_int4(*(int*)&h0, *(int*)&h1, *(int*)&h2, *(int*)&h3);
            *(int4*)&Ah[fr * 40 + fc8] = pk;

            const float* wp = &W[(size_t)(bn + fr) * K + k0 + fc8];
            float4 b0v = *(const float4*)wp;
            float4 b1v = *(const float4*)(wp + 4);
            __half2 g0 = __floats2half2_rn(b0v.x, b0v.y);
            __half2 g1 = __floats2half2_rn(b0v.z, b0v.w);
            __half2 g2 = __floats2half2_rn(b1v.x, b1v.y);
            __half2 g3 = __floats2half2_rn(b1v.z, b1v.w);
            int4 pk2 = make_int4(*(int*)&g0, *(int*)&g1, *(int*)&g2, *(int*)&g3);
            *(int4*)&Bh[fr * 40 + fc8] = pk2;
        }
        __syncthreads();

#pragma unroll
        for (int ks = 0; ks < 2; ks++) {
            unsigned af[4];
            ldm_x4(af, smaddr(&Ah[(wr * 16 + l4) * 40 + ks * 16 + hi8]));
            unsigned bf[2][4];
#pragma unroll
            for (int p = 0; p < 2; p++)
                ldm_x4(bf[p], smaddr(&Bh[(wc * 32 + p * 16 + l4) * 40 + ks * 16 + hi8]));
#pragma unroll
            for (int nt = 0; nt < 4; nt++) {
                unsigned bb[2];
                bb[0] = bf[nt >> 1][(nt & 1)];
                bb[1] = bf[nt >> 1][(nt & 1) + 2];
                mma16816(acc[nt], af, bb);
            }
        }
    }

#pragma unroll
    for (int nt = 0; nt < 4; nt++) {
        int col = bn + wc * 32 + nt * 8 + 2 * cc;
        float b0 = bias ? bias[col] : 0.f;
        float b1 = bias ? bias[col + 1] : 0.f;
        int row0 = bm + wr * 16 + gr;
        int row1 = row0 + 8;
        if (row0 < M) {
            if (OM == 1) {
                Ch[(size_t)row0 * N + col]     = __float2half(acc[nt][0] + b0);
                Ch[(size_t)row0 * N + col + 1] = __float2half(acc[nt][1] + b1);
            } else {
                Cf[(size_t)row0 * N + col]     = acc[nt][0] + b0;
                Cf[(size_t)row0 * N + col + 1] = acc[nt][1] + b1;
            }
        }
        if (row1 < M) {
            if (OM == 1) {
                Ch[(size_t)row1 * N + col]     = __float2half(acc[nt][2] + b0);
                Ch[(size_t)row1 * N + col + 1] = __float2half(acc[nt][3] + b1);
            } else {
                Cf[(size_t)row1 * N + col]     = acc[nt][2] + b0;
                Cf[(size_t)row1 * N + col + 1] = acc[nt][3] + b1;
            }
        }
    }
}

// ---------------- fused gated cross-attention: 32 s-rows per block ----------------
#define CA_SMEM 105600
__global__ __launch_bounds__(256, 2) void ca_fused_kernel()
{
    extern __shared__ __align__(16) char smraw[];
    __half* Ks  = (__half*)smraw;
    __half* Vs  = (__half*)(smraw + 40960);
    __half* Ghs = (__half*)(smraw + 81920);
    __half* Qs  = (__half*)(smraw + 98816);
    float*  Hs  = (float*)(smraw + 101376);
    float*  Zs  = (float*)(smraw + 105472);

    const int h = blockIdx.x;
    const int s0 = blockIdx.y * 32;
    const int tid = threadIdx.x;
    const int w = tid >> 5, lane = tid & 31;
    const int gr = lane >> 2, cc = lane & 3;
    const int cw = w * 32;
    const int l4 = lane & 15;

    auto issue_tile = [&](int ci) {
        int buf = (ci & 1) * 10240;
        int c0 = ci * 256;
        int pr = tid >> 2, pp4 = tid & 3;
#pragma unroll
        for (int rr = 0; rr < 4; rr++) {
            int row = rr * 64 + pr;
            size_t src = (size_t)(c0 + row) * D + h * 32 + pp4 * 8;
            cpa16(&Ks[buf + row * 40 + pp4 * 8], &g_Kh[src]);
            cpa16(&Vs[buf + row * 40 + pp4 * 8], &g_Vh[src]);
        }
#pragma unroll
        for (int t = 0; t < 4; t++) {
            int idx = t * 256 + tid;
            int r = idx >> 5, pp = idx & 31;
            cpa16(&Ghs[r * 264 + pp * 8], &g_Gh[(size_t)(s0 + r) * NC + c0 + pp * 8]);
        }
        asm volatile("cp.async.commit_group;");
    };

#pragma unroll
    for (int t = 0; t < 2; t++) {
        int idx = t * 256 + tid;
        int row = idx >> 4, c2 = (idx & 15) * 2;
        *(unsigned*)&Qs[row * 40 + c2] =
            *(const unsigned*)&g_Qh[(size_t)(s0 + row) * D + h * 32 + c2];
    }
#pragma unroll
    for (int k = 0; k < 4; k++) Hs[k * 256 + tid] = 0.f;
    if (tid < 32) Zs[tid] = 0.f;

    issue_tile(0);
    __syncthreads();

    unsigned qa[2][2][4];
#pragma unroll
    for (int sh = 0; sh < 2; sh++)
#pragma unroll
        for (int ks = 0; ks < 2; ks++)
            ldm_x4(qa[sh][ks], smaddr(&Qs[(sh * 16 + l4) * 40 + ks * 16 + (lane >> 4) * 8]));

    float hacc[2][4][4] = {};
    float zacc[2][2] = {};

    for (int ci = 0; ci < 16; ci++) {
        int buf = (ci & 1) * 10240;
        asm volatile("cp.async.wait_group 0;" ::: "memory");
        __syncthreads();

        unsigned gf[2][4][2];
#pragma unroll
        for (int sh = 0; sh < 2; sh++)
#pragma unroll
            for (int nt = 0; nt < 4; nt++)
                ldm_x2(gf[sh][nt][0], gf[sh][nt][1],
                       smaddr(&Ghs[(sh * 16 + l4) * 264 + cw + nt * 8]));
        __syncthreads();
        if (ci < 15) issue_tile(ci + 1);

#pragma unroll
        for (int sh = 0; sh < 2; sh++) {
            unsigned pa[2][4];
#pragma unroll
            for (int nt = 0; nt < 4; nt++) {
                float S[4] = {0.f, 0.f, 0.f, 0.f};
#pragma unroll
                for (int ks = 0; ks < 2; ks++) {
                    unsigned b[2];
                    ldm_x2(b[0], b[1],
                           smaddr(&Ks[buf + (cw + nt * 8 + (l4 & 7)) * 40 + ks * 16 + (l4 >> 3) * 8]));
                    mma16816(S, qa[sh][ks], b);
                }
                __half2 x01 = __hmul2(__floats2half2_rn(S[0], S[1]), *(__half2*)&gf[sh][nt][0]);
                __half2 x23 = __hmul2(__floats2half2_rn(S[2], S[3]), *(__half2*)&gf[sh][nt][1]);
                __half2 p01 = h2ex2(x01);
                __half2 p23 = h2ex2(x23);
                float2 f01 = __half22float2(p01);
                float2 f23 = __half22float2(p23);
                zacc[sh][0] += f01.x + f01.y;
                zacc[sh][1] += f23.x + f23.y;
                unsigned u01 = *(unsigned*)&p01, u23 = *(unsigned*)&p23;
                if ((nt & 1) == 0) { pa[nt >> 1][0] = u01; pa[nt >> 1][1] = u23; }
                else               { pa[nt >> 1][2] = u01; pa[nt >> 1][3] = u23; }
            }
#pragma unroll
            for (int nt2 = 0; nt2 < 4; nt2++) {
#pragma unroll
                for (int ks2 = 0; ks2 < 2; ks2++) {
                    unsigned b[2];
                    ldm_x2_t(b[0], b[1],
                             smaddr(&Vs[buf + (cw + ks2 * 16 + l4) * 40 + nt2 * 8]));
                    mma16816(hacc[sh][nt2], pa[ks2], b);
                }
            }
        }
    }

#pragma unroll
    for (int sh = 0; sh < 2; sh++) {
        float z0 = zacc[sh][0], z1 = zacc[sh][1];
#pragma unroll
        for (int o = 1; o < 4; o <<= 1) {
            z0 += __shfl_xor_sync(0xffffffffu, z0, o);
            z1 += __shfl_xor_sync(0xffffffffu, z1, o);
        }
        if (cc == 0) {
            atomicAdd(&Zs[sh * 16 + gr], z0);
            atomicAdd(&Zs[sh * 16 + gr + 8], z1);
        }
#pragma unroll
        for (int nt2 = 0; nt2 < 4; nt2++) {
            atomicAdd(&Hs[(sh * 16 + gr) * 32 + nt2 * 8 + 2 * cc],           hacc[sh][nt2][0]);
            atomicAdd(&Hs[(sh * 16 + gr) * 32 + nt2 * 8 + 2 * cc + 1],       hacc[sh][nt2][1]);
            atomicAdd(&Hs[(sh * 16 + gr + 8) * 32 + nt2 * 8 + 2 * cc],       hacc[sh][nt2][2]);
            atomicAdd(&Hs[(sh * 16 + gr + 8) * 32 + nt2 * 8 + 2 * cc + 1],   hacc[sh][nt2][3]);
        }
    }
    __syncthreads();
    if (tid < 32) g_Z[(s0 + tid) * NH + h] = Zs[tid];
#pragma unroll
    for (int k = 0; k < 4; k++) {
        int idx = k * 256 + tid;
        int row = idx >> 5, d = idx & 31;
        g_Hnew[(size_t)(s0 + row) * D + h * 32 + d] = Hs[idx] / Zs[row];
    }
}

// ---------------- attn_map by QK recompute: 32 s-rows per block ----------------
#define AT_SMEM 111104
__global__ __launch_bounds__(256, 2) void attn_recompute_kernel(float* __restrict__ AM)
{
    extern __shared__ __align__(16) char smraw[];
    __half* Ks  = (__half*)smraw;
    __half* Qs  = (__half*)(smraw + 67584);
    __half* Ghs = (__half*)(smraw + 84480);
    float*  AMs = (float*)(smraw + 93184);
    float*  iZ  = (float*)(smraw + 110080);

    const int c0 = blockIdx.x * 128;
    const int s0 = blockIdx.y * 32;
    const int tid = threadIdx.x;
    const int w = tid >> 5, lane = tid & 31;
    const int gr = lane >> 2, cc = lane & 3;
    const int l4 = lane & 15;
    const int hi8 = (lane >> 4) * 8;
    const int cw16 = w * 16;

#pragma unroll
    for (int t = 0; t < 16; t++) {
        int idx = t * 256 + tid;
        int r = idx >> 5, pp = idx & 31;
        cpa16(&Ks[r * 264 + pp * 8], &g_Kh[(size_t)(c0 + r) * D + pp * 8]);
    }
#pragma unroll
    for (int t = 0; t < 4; t++) {
        int idx = t * 256 + tid;
        int r = idx >> 5, pp = idx & 31;
        cpa16(&Qs[r * 264 + pp * 8], &g_Qh[(size_t)(s0 + r) * D + pp * 8]);
    }
#pragma unroll
    for (int t = 0; t < 2; t++) {
        int idx = t * 256 + tid;
        int r = idx >> 4, pp = idx & 15;
        cpa16(&Ghs[r * 136 + pp * 8], &g_Gh[(size_t)(s0 + r) * NC + c0 + pp * 8]);
    }
    asm volatile("cp.async.commit_group;");
    {
        int s = tid >> 3, hh = tid & 7;
        iZ[tid] = 0.125f / g_Z[(s0 + s) * NH + hh];
    }
    asm volatile("cp.async.wait_group 0;" ::: "memory");
    __syncthreads();

    unsigned gfr[2][2][2];
#pragma unroll
    for (int sh = 0; sh < 2; sh++)
#pragma unroll
        for (int nt = 0; nt < 2; nt++)
            ldm_x2(gfr[sh][nt][0], gfr[sh][nt][1],
                   smaddr(&Ghs[(sh * 16 + l4) * 136 + cw16 + nt * 8]));

    float acc[2][2][4] = {};
#pragma unroll
    for (int h = 0; h < NH; h++) {
        unsigned kb[2][4];
#pragma unroll
        for (int ks = 0; ks < 2; ks++)
            ldm_x4(kb[ks], smaddr(&Ks[(cw16 + l4) * 264 + h * 32 + ks * 16 + hi8]));
#pragma unroll
        for (int sh = 0; sh < 2; sh++) {
            unsigned qa[2][4];
#pragma unroll
            for (int ks = 0; ks < 2; ks++)
                ldm_x4(qa[ks], smaddr(&Qs[(sh * 16 + l4) * 264 + h * 32 + ks * 16 + hi8]));
            float izA = iZ[(sh * 16 + gr) * 8 + h];
            float izB = iZ[(sh * 16 + gr + 8) * 8 + h];
#pragma unroll
            for (int nt = 0; nt < 2; nt++) {
                float S[4] = {0.f, 0.f, 0.f, 0.f};
#pragma unroll
                for (int ks = 0; ks < 2; ks++) {
                    unsigned bb[2];
                    bb[0] = kb[ks][nt];
                    bb[1] = kb[ks][nt + 2];
                    mma16816(S, qa[ks], bb);
                }
                __half2 x01 = __hmul2(__floats2half2_rn(S[0], S[1]), *(__half2*)&gfr[sh][nt][0]);
                __half2 x23 = __hmul2(__floats2half2_rn(S[2], S[3]), *(__half2*)&gfr[sh][nt][1]);
                float2 f01 = __half22float2(h2ex2(x01));
                float2 f23 = __half22float2(h2ex2(x23));
                acc[sh][nt][0] += f01.x * izA;
                acc[sh][nt][1] += f01.y * izA;
                acc[sh][nt][2] += f23.x * izB;
                acc[sh][nt][3] += f23.y * izB;
            }
        }
    }

#pragma unroll
    for (int sh = 0; sh < 2; sh++)
#pragma unroll
        for (int nt = 0; nt < 2; nt++) {
            int col = cw16 + nt * 8 + 2 * cc;
            *(float2*)&AMs[(sh * 16 + gr) * 132 + col]       = make_float2(acc[sh][nt][0], acc[sh][nt][1]);
            *(float2*)&AMs[(sh * 16 + gr + 8) * 132 + col]   = make_float2(acc[sh][nt][2], acc[sh][nt][3]);
        }
    __syncthreads();
#pragma unroll
    for (int t = 0; t < 4; t++) {
        int idx = t * 256 + tid;
        int r = idx >> 5, p4 = idx & 31;
        *(float4*)&AM[(size_t)(s0 + r) * NC + c0 + p4 * 4] = *(const float4*)&AMs[r * 132 + p4 * 4];
    }
}

// ---------------- cross-attn epilogue LN ----------------
__global__ __launch_bounds__(256) void ln_ca_kernel(
    const float* __restrict__ g, const float* __restrict__ b, const float* __restrict__ fusion)
{
    int tid = threadIdx.x;
    if (blockIdx.x == 0 && tid < D) g_tok[tid] = fusion[tid];
    int warp = tid >> 5, lane = tid & 31;
    int row = blockIdx.x * 8 + warp;
    float x[8];
    float s = 0.f;
#pragma unroll
    for (int j = 0; j < 8; j++) {
        int c = lane + 32 * j;
        x[j] = g_tmp[(size_t)row * D + c] + g_HS[(size_t)row * D + c];
        s += x[j];
    }
    s = warpSum(s);
    float m = s * (1.0f / D);
    float vs = 0.f;
#pragma unroll
    for (int j = 0; j < 8; j++) { float d = x[j] - m; vs += d * d; }
    vs = warpSum(vs);
    float r = rsqrtf(vs * (1.0f / D) + 1e-5f);
#pragma unroll
    for (int j = 0; j < 8; j++) {
        int c = lane + 32 * j;
        g_tok[(size_t)(1 + row) * D + c] = (x[j] - m) * r * g[c] + b[c];
    }
}

// ---------------- fused q0 + row-0 scores + AV over tokens (per-block partials) ----------------
__global__ __launch_bounds__(256) void sa0_kernel(
    const float* __restrict__ fusion,
    const float* __restrict__ w, const float* __restrict__ bqkv)
{
    __shared__ float fs[D];
    __shared__ float q0s[D];
    __shared__ float zpart[NH];
    __shared__ float a0s[D];
    int tid = threadIdx.x;
    fs[tid] = fusion[tid];
    a0s[tid] = 0.f;
    if (tid < NH) zpart[tid] = 0.f;
    __syncthreads();
    {
        float a = bqkv[tid];
        const float* wr_ = &w[(size_t)tid * D];
        for (int c = 0; c < D; c++) a += fs[c] * wr_[c];
        q0s[tid] = a;
    }
    __syncthreads();

    int warp = tid >> 5, lane = tid & 31;
    int wtotal = gridDim.x * 8;
    const float isq = 0.17677669529663687f;
    float acc[8] = {};
    float zacc = 0.f;
    for (int u = blockIdx.x * 8 + warp; u < TT; u += wtotal) {
        float mine = 0.f;
#pragma unroll
        for (int j = 0; j < 8; j++) {
            int c = lane + 32 * j;
            float v = q0s[c] * g_k2[(size_t)u * D + c];
            v = warpSum(v);
            if (lane == j) mine = v;
        }
        float pl = __expf(mine * isq);
        if (lane < 8) zacc += pl;
        float ph = __shfl_sync(0xffffffffu, pl, lane >> 2);
        const float* vrow = &g_v2[(size_t)u * D + lane * 8];
        float4 v0 = *(const float4*)vrow;
        float4 v1 = *(const float4*)(vrow + 4);
        acc[0] += ph * v0.x; acc[1] += ph * v0.y; acc[2] += ph * v0.z; acc[3] += ph * v0.w;
        acc[4] += ph * v1.x; acc[5] += ph * v1.y; acc[6] += ph * v1.z; acc[7] += ph * v1.w;
    }
    if (lane < 8) atomicAdd(&zpart[lane], zacc);
#pragma unroll
    for (int j = 0; j < 8; j++)
        atomicAdd(&a0s[lane * 8 + j], acc[j]);
    __syncthreads();
    g_a0p[blockIdx.x][tid] = a0s[tid];
    if (tid < NH) g_Z0p[blockIdx.x][tid] = zpart[tid];
}

// ---------------- final head ----------------
__device__ __forceinline__ float blockSum256(float v, volatile float* red) {
    int lane = threadIdx.x & 31, w = threadIdx.x >> 5;
    v = warpSum(v);
    __syncthreads();
    if (lane == 0) red[w] = v;
    __syncthreads();
    float s = 0.f;
#pragma unroll
    for (int i = 0; i < 8; i++) s += red[i];
    return s;
}

__global__ __launch_bounds__(256) void final_kernel(
    const float* __restrict__ fusion,
    const float* __restrict__ mow, const float* __restrict__ mob,
    const float* __restrict__ ln1g, const float* __restrict__ ln1b,
    const float* __restrict__ w1, const float* __restrict__ b1,
    const float* __restrict__ w2, const float* __restrict__ b2,
    const float* __restrict__ ln2g, const float* __restrict__ ln2b,
    float* __restrict__ out)
{
    __shared__ float a0[D], t1[D], h1[2 * D];
    __shared__ float red[8];
    int tid = threadIdx.x;
    {
        float av = 0.f, zv = 0.f;
        int hh = tid >> 5;
#pragma unroll
        for (int b = 0; b < SA0_BLOCKS; b++) {
            av += g_a0p[b][tid];
            zv += g_Z0p[b][hh];
        }
        a0[tid] = av / zv;
    }
    __syncthreads();
    float y = mob[tid];
    for (int j = 0; j < D; j++) y += a0[j] * mow[(size_t)tid * D + j];
    float tv = fusion[tid] + y;
    float m = blockSum256(tv, red) * (1.0f / D);
    float d = tv - m;
    float var = blockSum256(d * d, red) * (1.0f / D);
    float t = d * rsqrtf(var + 1e-5f) * ln1g[tid] + ln1b[tid];
    t1[tid] = t;
    __syncthreads();
    float hh2[2];
#pragma unroll
    for (int r2 = 0; r2 < 2; r2++) {
        int jj = tid + r2 * 256;
        float a = b1[jj];
        for (int c = 0; c < D; c++) a += t1[c] * w1[(size_t)jj * D + c];
        hh2[r2] = a * 0.5f * (1.f + erff(a * 0.70710678118654752f));
    }
    h1[tid] = hh2[0];
    h1[tid + 256] = hh2[1];
    __syncthreads();
    float o = b2[tid];
    for (int j = 0; j < 512; j++) o += h1[j] * w2[(size_t)tid * 512 + j];
    float t2v = t1[tid] + o;   // residual = LN1 output
    float m2 = blockSum256(t2v, red) * (1.0f / D);
    float d2 = t2v - m2;
    float v2 = blockSum256(d2 * d2, red) * (1.0f / D);
    out[tid] = d2 * rsqrtf(v2 + 1e-5f) * ln2g[tid] + ln2b[tid];
}

// ---------------- launcher ----------------
extern "C" void kernel_launch(void* const* d_in, const int* in_sizes, int n_in,
                              void* d_out, int out_size)
{
    const float* H_S     = (const float*)d_in[0];
    const float* H_C     = (const float*)d_in[1];
    const float* H_G     = (const float*)d_in[2];
    const float* G_glyph = (const float*)d_in[3];
    const float* Ws      = (const float*)d_in[4];
    const float* bs      = (const float*)d_in[5];
    const float* Wb      = (const float*)d_in[6];
    const float* bb      = (const float*)d_in[7];
    const float* Wg      = (const float*)d_in[8];
    const float* bg      = (const float*)d_in[9];
    const float* WQ      = (const float*)d_in[10];
    const float* WK      = (const float*)d_in[11];
    const float* WV      = (const float*)d_in[12];
    const float* WO      = (const float*)d_in[13];
    const float* bO      = (const float*)d_in[14];
    const float* ln_ca_g = (const float*)d_in[15];
    const float* ln_ca_b = (const float*)d_in[16];
    const float* fusion  = (const float*)d_in[17];
    const float* mha_in_w  = (const float*)d_in[18];
    const float* mha_in_b  = (const float*)d_in[19];
    const float* mha_out_w = (const float*)d_in[20];
    const float* mha_out_b = (const float*)d_in[21];
    const float* ln1_g   = (const float*)d_in[22];
    const float* ln1_b   = (const float*)d_in[23];
    const float* ln2_g   = (const float*)d_in[24];
    const float* ln2_b   = (const float*)d_in[25];
    const float* ffn_w1  = (const float*)d_in[26];
    const float* ffn_b1  = (const float*)d_in[27];
    const float* ffn_w2  = (const float*)d_in[28];
    const float* ffn_b2  = (const float*)d_in[29];

    float* out = (float*)d_out;
    float* z_fused  = out;        // 256
    float* attn_map = out + D;    // 2048 * 4096

    float *pHS, *pHC, *pHnew, *pTmp, *pTok, *pk2, *pv2;
    __half *pQh, *pKh, *pVh, *pGh;
    cudaGetSymbolAddress((void**)&pHS,  g_HS);
    cudaGetSymbolAddress((void**)&pHC,  g_HC);
    cudaGetSymbolAddress((void**)&pQh,  g_Qh);
    cudaGetSymbolAddress((void**)&pKh,  g_Kh);
    cudaGetSymbolAddress((void**)&pVh,  g_Vh);
    cudaGetSymbolAddress((void**)&pGh,  g_Gh);
    cudaGetSymbolAddress((void**)&pHnew,g_Hnew);
    cudaGetSymbolAddress((void**)&pTmp, g_tmp);
    cudaGetSymbolAddress((void**)&pTok, g_tok);
    cudaGetSymbolAddress((void**)&pk2,  g_k2);
    cudaGetSymbolAddress((void**)&pv2,  g_v2);

    static bool attrSet = false;
    static cudaStream_t s1;
    static cudaEvent_t evFork, evJoin;
    if (!attrSet) {
        cudaFuncSetAttribute(ca_fused_kernel,
                             cudaFuncAttributeMaxDynamicSharedMemorySize, CA_SMEM);
        cudaFuncSetAttribute(attn_recompute_kernel,
                             cudaFuncAttributeMaxDynamicSharedMemorySize, AT_SMEM);
        cudaStreamCreateWithFlags(&s1, cudaStreamNonBlocking);
        cudaEventCreateWithFlags(&evFork, cudaEventDisableTiming);
        cudaEventCreateWithFlags(&evJoin, cudaEventDisableTiming);
        attrSet = true;
    }

    // #1 HS (z0, K=128) + HG (z1, K=64) + HC (z2, K=256) + gate conversion (z3)
    gemm16_kernel<0><<<dim3(4, 64, 4), 256>>>(
        H_S, Ws, bs, pHS, nullptr, NS,
        H_G, Wg, bg, pTok + (size_t)(1 + NS) * D, nullptr, NG,
        H_C, Wb, bb, pHC, nullptr, NC, D, 128, 64, 256, G_glyph, pGh);
    // #2 Q/K/V triple (fp16 out)
    gemm16_kernel<1><<<dim3(4, 64, 3), 256>>>(
        pHS, WQ, nullptr, nullptr, pQh, NS,
        pHC, WK, nullptr, nullptr, pKh, NC,
        pHC, WV, nullptr, nullptr, pVh, NC, D, 256, 256, 256, nullptr, nullptr);
    // #3 fused gated cross attention (Z + Hnew)
    ca_fused_kernel<<<dim3(NH, NS / 32), 256, CA_SMEM>>>();

    // fork: attn_map recompute runs concurrently with the O-proj..final chain
    cudaEventRecord(evFork, (cudaStream_t)0);
    cudaStreamWaitEvent(s1, evFork, 0);
    attn_recompute_kernel<<<dim3(NC / 128, NS / 32), 256, AT_SMEM, s1>>>(attn_map);
    cudaEventRecord(evJoin, s1);

    // main chain (stream 0)
    gemm16_kernel<0><<<dim3(4, 32), 256>>>(
        pHnew, WO, bO, pTmp, nullptr, NS,
        pHnew, WO, bO, pTmp, nullptr, NS,
        pHnew, WO, bO, pTmp, nullptr, NS, D, 256, 256, 256, nullptr, nullptr);
    ln_ca_kernel<<<NS / 8, 256>>>(ln_ca_g, ln_ca_b, fusion);
    gemm16_kernel<0><<<dim3(4, 65, 2), 256>>>(
        pTok, mha_in_w + 256 * 256, mha_in_b + 256, pk2, nullptr, TT,
        pTok, mha_in_w + 512 * 256, mha_in_b + 512, pv2, nullptr, TT,
        pTok, mha_in_w + 256 * 256, mha_in_b + 256, pk2, nullptr, TT, D, 256, 256, 256, nullptr, nullptr);
    sa0_kernel<<<SA0_BLOCKS, 256>>>(fusion, mha_in_w, mha_in_b);
    final_kernel<<<1, 256>>>(fusion, mha_out_w, mha_out_b, ln1_g, ln1_b,
                             ffn_w1, ffn_b1, ffn_w2, ffn_b2, ln2_g, ln2_b, z_fused);

    // join
    cudaStreamWaitEvent((cudaStream_t)0, evJoin, 0);
}

// round 13
// speedup vs baseline: 2.8466x; 1.0140x over previous
#include <cuda_runtime.h>
#include <cuda_fp16.h>

#define NS 2048
#define NC 4096
#define NG 2048
#define D  256
#define NH 8
#define TT 4097   // 1 + NS + NG
#define SA0_BLOCKS 32

// ---------------- device scratch ----------------
__device__ float  g_HS[NS * D];
__device__ float  g_HC[NC * D];
__device__ __half g_Qh[NS * D];
__device__ __half g_Kh[NC * D];
__device__ __half g_Vh[NC * D];
__device__ __half g_Gh[(size_t)NS * NC];   // gate * (isq*log2e), fp16
__device__ float  g_Z[NS * NH];
__device__ float  g_Hnew[NS * D];
__device__ float  g_tmp[NS * D];
__device__ float  g_tok[TT * D];
__device__ float  g_k2[TT * D];
__device__ float  g_v2[TT * D];
__device__ float  g_a0p[SA0_BLOCKS][D];
__device__ float  g_Z0p[SA0_BLOCKS][NH];

__device__ __forceinline__ float warpSum(float v) {
#pragma unroll
    for (int o = 16; o; o >>= 1) v += __shfl_xor_sync(0xffffffffu, v, o);
    return v;
}

__device__ __forceinline__ void mma16816(float* c, const unsigned* a, const unsigned* b) {
    asm volatile(
        "mma.sync.aligned.m16n8k16.row.col.f32.f16.f16.f32 "
        "{%0,%1,%2,%3}, {%4,%5,%6,%7}, {%8,%9}, {%0,%1,%2,%3};\n"
        : "+f"(c[0]), "+f"(c[1]), "+f"(c[2]), "+f"(c[3])
        : "r"(a[0]), "r"(a[1]), "r"(a[2]), "r"(a[3]), "r"(b[0]), "r"(b[1]));
}

__device__ __forceinline__ unsigned smaddr(const void* p) {
    return (unsigned)__cvta_generic_to_shared(p);
}
__device__ __forceinline__ void ldm_x2(unsigned& r0, unsigned& r1, unsigned a) {
    asm volatile("ldmatrix.sync.aligned.m8n8.x2.shared.b16 {%0,%1}, [%2];"
                 : "=r"(r0), "=r"(r1) : "r"(a));
}
__device__ __forceinline__ void ldm_x2_t(unsigned& r0, unsigned& r1, unsigned a) {
    asm volatile("ldmatrix.sync.aligned.m8n8.x2.trans.shared.b16 {%0,%1}, [%2];"
                 : "=r"(r0), "=r"(r1) : "r"(a));
}
__device__ __forceinline__ void ldm_x4(unsigned* r, unsigned a) {
    asm volatile("ldmatrix.sync.aligned.m8n8.x4.shared.b16 {%0,%1,%2,%3}, [%4];"
                 : "=r"(r[0]), "=r"(r[1]), "=r"(r[2]), "=r"(r[3]) : "r"(a));
}
__device__ __forceinline__ void cpa16(void* smem, const void* gmem) {
    asm volatile("cp.async.cg.shared.global [%0], [%1], 16;"
                 :: "r"(smaddr(smem)), "l"(gmem));
}
__device__ __forceinline__ __half2 h2ex2(__half2 x) {
    unsigned r, xi = *(unsigned*)&x;
    asm("ex2.approx.f16x2 %0, %1;" : "=r"(r) : "r"(xi));
    return *(__half2*)&r;
}

#define CE 0.25506382f   // (1/sqrt(32)) * log2(e)

// ---------------- fp16 tensor-core GEMM (up to 3 problems via blockIdx.z, per-z K) ----------------
// If gsrc != null, the LAST z-slice converts G fp32 -> fp16*CE instead.
template<int OM>
__global__ __launch_bounds__(256) void gemm16_kernel(
    const float* __restrict__ A0, const float* __restrict__ W0, const float* __restrict__ bs0,
    float* __restrict__ Cf0, __half* __restrict__ Ch0, int M0,
    const float* __restrict__ A1, const float* __restrict__ W1, const float* __restrict__ bs1,
    float* __restrict__ Cf1, __half* __restrict__ Ch1, int M1,
    const float* __restrict__ A2, const float* __restrict__ W2, const float* __restrict__ bs2,
    float* __restrict__ Cf2, __half* __restrict__ Ch2, int M2,
    int N, int K0p, int K1p, int K2p,
    const float* __restrict__ gsrc, __half* __restrict__ gdst)
{
    if (gsrc != nullptr && blockIdx.z == gridDim.z - 1) {
        int bid = blockIdx.y * gridDim.x + blockIdx.x;
        int t4 = bid * 256 + threadIdx.x;
        const int total4 = (NS * NC) / 4;
        int stride = gridDim.x * gridDim.y * 256;
        for (int i = t4; i < total4; i += stride) {
            float4 v = *(const float4*)&gsrc[(size_t)i * 4];
            __half2 h0 = __floats2half2_rn(v.x * CE, v.y * CE);
            __half2 h1 = __floats2half2_rn(v.z * CE, v.w * CE);
            *(int2*)&gdst[(size_t)i * 4] = make_int2(*(int*)&h0, *(int*)&h1);
        }
        return;
    }

    const int z = blockIdx.z;
    const float* A    = z == 0 ? A0  : (z == 1 ? A1  : A2);
    const float* W    = z == 0 ? W0  : (z == 1 ? W1  : W2);
    const float* bias = z == 0 ? bs0 : (z == 1 ? bs1 : bs2);
    float* Cf         = z == 0 ? Cf0 : (z == 1 ? Cf1 : Cf2);
    __half* Ch        = z == 0 ? Ch0 : (z == 1 ? Ch1 : Ch2);
    const int M       = z == 0 ? M0  : (z == 1 ? M1  : M2);
    const int K       = z == 0 ? K0p : (z == 1 ? K1p : K2p);

    const int bm = blockIdx.y * 64, bn = blockIdx.x * 64;
    if (bm >= M) return;

    __shared__ __half Ah[64 * 40];
    __shared__ __half Bh[64 * 40];

    const int tid = threadIdx.x;
    const int w = tid >> 5, lane = tid & 31;
    const int wr = w >> 1, wc = w & 1;
    const int gr = lane >> 2, cc = lane & 3;
    const int fr = tid >> 2, fc8 = (tid & 3) * 8;
    const int l4 = lane & 15;
    const int hi8 = (lane >> 4) * 8;

    float acc[4][4] = {};

    for (int k0 = 0; k0 < K; k0 += 32) {
        __syncthreads();
        {
            float4 a0v = make_float4(0.f, 0.f, 0.f, 0.f), a1v = a0v;
            if (bm + fr < M) {
                const float* ap = &A[(size_t)(bm + fr) * K + k0 + fc8];
                a0v = *(const float4*)ap;
                a1v = *(const float4*)(ap + 4);
            }
            __half2 h0 = __floats2half2_rn(a0v.x, a0v.y);
            __half2 h1 = __floats2half2_rn(a0v.z, a0v.w);
            __half2 h2 = __floats2half2_rn(a1v.x, a1v.y);
            __half2 h3 = __floats2half2_rn(a1v.z, a1v.w);
            int4 pk = make_int4(*(int*)&h0, *(int*)&h1, *(int*)&h2, *(int*)&h3);
            *(int4*)&Ah[fr * 40 + fc8] = pk;

            const float* wp = &W[(size_t)(bn + fr) * K + k0 + fc8];
            float4 b0v = *(const float4*)wp;
            float4 b1v = *(const float4*)(wp + 4);
            __half2 g0 = __floats2half2_rn(b0v.x, b0v.y);
            __half2 g1 = __floats2half2_rn(b0v.z, b0v.w);
            __half2 g2 = __floats2half2_rn(b1v.x, b1v.y);
            __half2 g3 = __floats2half2_rn(b1v.z, b1v.w);
            int4 pk2 = make_int4(*(int*)&g0, *(int*)&g1, *(int*)&g2, *(int*)&g3);
            *(int4*)&Bh[fr * 40 + fc8] = pk2;
        }
        __syncthreads();

#pragma unroll
        for (int ks = 0; ks < 2; ks++) {
            unsigned af[4];
            ldm_x4(af, smaddr(&Ah[(wr * 16 + l4) * 40 + ks * 16 + hi8]));
            unsigned bf[2][4];
#pragma unroll
            for (int p = 0; p < 2; p++)
                ldm_x4(bf[p], smaddr(&Bh[(wc * 32 + p * 16 + l4) * 40 + ks * 16 + hi8]));
#pragma unroll
            for (int nt = 0; nt < 4; nt++) {
                unsigned bb[2];
                bb[0] = bf[nt >> 1][(nt & 1)];
                bb[1] = bf[nt >> 1][(nt & 1) + 2];
                mma16816(acc[nt], af, bb);
            }
        }
    }

#pragma unroll
    for (int nt = 0; nt < 4; nt++) {
        int col = bn + wc * 32 + nt * 8 + 2 * cc;
        float b0 = bias ? bias[col] : 0.f;
        float b1 = bias ? bias[col + 1] : 0.f;
        int row0 = bm + wr * 16 + gr;
        int row1 = row0 + 8;
        if (row0 < M) {
            if (OM == 1) {
                Ch[(size_t)row0 * N + col]     = __float2half(acc[nt][0] + b0);
                Ch[(size_t)row0 * N + col + 1] = __float2half(acc[nt][1] + b1);
            } else {
                Cf[(size_t)row0 * N + col]     = acc[nt][0] + b0;
                Cf[(size_t)row0 * N + col + 1] = acc[nt][1] + b1;
            }
        }
        if (row1 < M) {
            if (OM == 1) {
                Ch[(size_t)row1 * N + col]     = __float2half(acc[nt][2] + b0);
                Ch[(size_t)row1 * N + col + 1] = __float2half(acc[nt][3] + b1);
            } else {
                Cf[(size_t)row1 * N + col]     = acc[nt][2] + b0;
                Cf[(size_t)row1 * N + col + 1] = acc[nt][3] + b1;
            }
        }
    }
}

// ---------------- fused gated cross-attention: 32 s-rows per block, Z via mma ----------------
#define CA_SMEM 105600
__global__ __launch_bounds__(256, 2) void ca_fused_kernel()
{
    extern __shared__ __align__(16) char smraw[];
    __half* Ks  = (__half*)smraw;
    __half* Vs  = (__half*)(smraw + 40960);
    __half* Ghs = (__half*)(smraw + 81920);
    __half* Qs  = (__half*)(smraw + 98816);
    float*  Hs  = (float*)(smraw + 101376);
    float*  Zs  = (float*)(smraw + 105472);

    const int h = blockIdx.x;
    const int s0 = blockIdx.y * 32;
    const int tid = threadIdx.x;
    const int w = tid >> 5, lane = tid & 31;
    const int gr = lane >> 2, cc = lane & 3;
    const int cw = w * 32;
    const int l4 = lane & 15;

    auto issue_tile = [&](int ci) {
        int buf = (ci & 1) * 10240;
        int c0 = ci * 256;
        int pr = tid >> 2, pp4 = tid & 3;
#pragma unroll
        for (int rr = 0; rr < 4; rr++) {
            int row = rr * 64 + pr;
            size_t src = (size_t)(c0 + row) * D + h * 32 + pp4 * 8;
            cpa16(&Ks[buf + row * 40 + pp4 * 8], &g_Kh[src]);
            cpa16(&Vs[buf + row * 40 + pp4 * 8], &g_Vh[src]);
        }
#pragma unroll
        for (int t = 0; t < 4; t++) {
            int idx = t * 256 + tid;
            int r = idx >> 5, pp = idx & 31;
            cpa16(&Ghs[r * 264 + pp * 8], &g_Gh[(size_t)(s0 + r) * NC + c0 + pp * 8]);
        }
        asm volatile("cp.async.commit_group;");
    };

#pragma unroll
    for (int t = 0; t < 2; t++) {
        int idx = t * 256 + tid;
        int row = idx >> 4, c2 = (idx & 15) * 2;
        *(unsigned*)&Qs[row * 40 + c2] =
            *(const unsigned*)&g_Qh[(size_t)(s0 + row) * D + h * 32 + c2];
    }
#pragma unroll
    for (int k = 0; k < 4; k++) Hs[k * 256 + tid] = 0.f;
    if (tid < 32) Zs[tid] = 0.f;

    issue_tile(0);
    __syncthreads();

    unsigned qa[2][2][4];
#pragma unroll
    for (int sh = 0; sh < 2; sh++)
#pragma unroll
        for (int ks = 0; ks < 2; ks++)
            ldm_x4(qa[sh][ks], smaddr(&Qs[(sh * 16 + l4) * 40 + ks * 16 + (lane >> 4) * 8]));

    float hacc[2][4][4] = {};
    float zmma[2][4] = {};
    const unsigned onesb[2] = {0x3C003C00u, 0x3C003C00u};   // all-ones fp16 B fragment

    for (int ci = 0; ci < 16; ci++) {
        int buf = (ci & 1) * 10240;
        asm volatile("cp.async.wait_group 0;" ::: "memory");
        __syncthreads();

        unsigned gf[2][4][2];
#pragma unroll
        for (int sh = 0; sh < 2; sh++)
#pragma unroll
            for (int nt = 0; nt < 4; nt++)
                ldm_x2(gf[sh][nt][0], gf[sh][nt][1],
                       smaddr(&Ghs[(sh * 16 + l4) * 264 + cw + nt * 8]));
        __syncthreads();
        if (ci < 15) issue_tile(ci + 1);

#pragma unroll
        for (int sh = 0; sh < 2; sh++) {
            unsigned pa[2][4];
#pragma unroll
            for (int nt = 0; nt < 4; nt++) {
                float S[4] = {0.f, 0.f, 0.f, 0.f};
#pragma unroll
                for (int ks = 0; ks < 2; ks++) {
                    unsigned b[2];
                    ldm_x2(b[0], b[1],
                           smaddr(&Ks[buf + (cw + nt * 8 + (l4 & 7)) * 40 + ks * 16 + (l4 >> 3) * 8]));
                    mma16816(S, qa[sh][ks], b);
                }
                __half2 x01 = __hmul2(__floats2half2_rn(S[0], S[1]), *(__half2*)&gf[sh][nt][0]);
                __half2 x23 = __hmul2(__floats2half2_rn(S[2], S[3]), *(__half2*)&gf[sh][nt][1]);
                __half2 p01 = h2ex2(x01);
                __half2 p23 = h2ex2(x23);
                unsigned u01 = *(unsigned*)&p01, u23 = *(unsigned*)&p23;
                if ((nt & 1) == 0) { pa[nt >> 1][0] = u01; pa[nt >> 1][1] = u23; }
                else               { pa[nt >> 1][2] = u01; pa[nt >> 1][3] = u23; }
            }
            // Z = P @ ones via tensor core (all B cols identical -> c[0]=rowsum gr, c[2]=rowsum gr+8)
#pragma unroll
            for (int ks2 = 0; ks2 < 2; ks2++)
                mma16816(zmma[sh], pa[ks2], onesb);
#pragma unroll
            for (int nt2 = 0; nt2 < 4; nt2++) {
#pragma unroll
                for (int ks2 = 0; ks2 < 2; ks2++) {
                    unsigned b[2];
                    ldm_x2_t(b[0], b[1],
                             smaddr(&Vs[buf + (cw + ks2 * 16 + l4) * 40 + nt2 * 8]));
                    mma16816(hacc[sh][nt2], pa[ks2], b);
                }
            }
        }
    }

#pragma unroll
    for (int sh = 0; sh < 2; sh++) {
        if (cc == 0) {
            atomicAdd(&Zs[sh * 16 + gr], zmma[sh][0]);
            atomicAdd(&Zs[sh * 16 + gr + 8], zmma[sh][2]);
        }
#pragma unroll
        for (int nt2 = 0; nt2 < 4; nt2++) {
            atomicAdd(&Hs[(sh * 16 + gr) * 32 + nt2 * 8 + 2 * cc],           hacc[sh][nt2][0]);
            atomicAdd(&Hs[(sh * 16 + gr) * 32 + nt2 * 8 + 2 * cc + 1],       hacc[sh][nt2][1]);
            atomicAdd(&Hs[(sh * 16 + gr + 8) * 32 + nt2 * 8 + 2 * cc],       hacc[sh][nt2][2]);
            atomicAdd(&Hs[(sh * 16 + gr + 8) * 32 + nt2 * 8 + 2 * cc + 1],   hacc[sh][nt2][3]);
        }
    }
    __syncthreads();
    if (tid < 32) g_Z[(s0 + tid) * NH + h] = Zs[tid];
#pragma unroll
    for (int k = 0; k < 4; k++) {
        int idx = k * 256 + tid;
        int row = idx >> 5, d = idx & 31;
        g_Hnew[(size_t)(s0 + row) * D + h * 32 + d] = Hs[idx] / Zs[row];
    }
}

// ---------------- attn_map by QK recompute: 32 s-rows per block ----------------
#define AT_SMEM 111104
__global__ __launch_bounds__(256, 2) void attn_recompute_kernel(float* __restrict__ AM)
{
    extern __shared__ __align__(16) char smraw[];
    __half* Ks  = (__half*)smraw;
    __half* Qs  = (__half*)(smraw + 67584);
    __half* Ghs = (__half*)(smraw + 84480);
    float*  AMs = (float*)(smraw + 93184);
    float*  iZ  = (float*)(smraw + 110080);

    const int c0 = blockIdx.x * 128;
    const int s0 = blockIdx.y * 32;
    const int tid = threadIdx.x;
    const int w = tid >> 5, lane = tid & 31;
    const int gr = lane >> 2, cc = lane & 3;
    const int l4 = lane & 15;
    const int hi8 = (lane >> 4) * 8;
    const int cw16 = w * 16;

#pragma unroll
    for (int t = 0; t < 16; t++) {
        int idx = t * 256 + tid;
        int r = idx >> 5, pp = idx & 31;
        cpa16(&Ks[r * 264 + pp * 8], &g_Kh[(size_t)(c0 + r) * D + pp * 8]);
    }
#pragma unroll
    for (int t = 0; t < 4; t++) {
        int idx = t * 256 + tid;
        int r = idx >> 5, pp = idx & 31;
        cpa16(&Qs[r * 264 + pp * 8], &g_Qh[(size_t)(s0 + r) * D + pp * 8]);
    }
#pragma unroll
    for (int t = 0; t < 2; t++) {
        int idx = t * 256 + tid;
        int r = idx >> 4, pp = idx & 15;
        cpa16(&Ghs[r * 136 + pp * 8], &g_Gh[(size_t)(s0 + r) * NC + c0 + pp * 8]);
    }
    asm volatile("cp.async.commit_group;");
    {
        int s = tid >> 3, hh = tid & 7;
        iZ[tid] = 0.125f / g_Z[(s0 + s) * NH + hh];
    }
    asm volatile("cp.async.wait_group 0;" ::: "memory");
    __syncthreads();

    unsigned gfr[2][2][2];
#pragma unroll
    for (int sh = 0; sh < 2; sh++)
#pragma unroll
        for (int nt = 0; nt < 2; nt++)
            ldm_x2(gfr[sh][nt][0], gfr[sh][nt][1],
                   smaddr(&Ghs[(sh * 16 + l4) * 136 + cw16 + nt * 8]));

    float acc[2][2][4] = {};
#pragma unroll
    for (int h = 0; h < NH; h++) {
        unsigned kb[2][4];
#pragma unroll
        for (int ks = 0; ks < 2; ks++)
            ldm_x4(kb[ks], smaddr(&Ks[(cw16 + l4) * 264 + h * 32 + ks * 16 + hi8]));
#pragma unroll
        for (int sh = 0; sh < 2; sh++) {
            unsigned qa[2][4];
#pragma unroll
            for (int ks = 0; ks < 2; ks++)
                ldm_x4(qa[ks], smaddr(&Qs[(sh * 16 + l4) * 264 + h * 32 + ks * 16 + hi8]));
            float izA = iZ[(sh * 16 + gr) * 8 + h];
            float izB = iZ[(sh * 16 + gr + 8) * 8 + h];
#pragma unroll
            for (int nt = 0; nt < 2; nt++) {
                float S[4] = {0.f, 0.f, 0.f, 0.f};
#pragma unroll
                for (int ks = 0; ks < 2; ks++) {
                    unsigned bb[2];
                    bb[0] = kb[ks][nt];
                    bb[1] = kb[ks][nt + 2];
                    mma16816(S, qa[ks], bb);
                }
                __half2 x01 = __hmul2(__floats2half2_rn(S[0], S[1]), *(__half2*)&gfr[sh][nt][0]);
                __half2 x23 = __hmul2(__floats2half2_rn(S[2], S[3]), *(__half2*)&gfr[sh][nt][1]);
                float2 f01 = __half22float2(h2ex2(x01));
                float2 f23 = __half22float2(h2ex2(x23));
                acc[sh][nt][0] += f01.x * izA;
                acc[sh][nt][1] += f01.y * izA;
                acc[sh][nt][2] += f23.x * izB;
                acc[sh][nt][3] += f23.y * izB;
            }
        }
    }

#pragma unroll
    for (int sh = 0; sh < 2; sh++)
#pragma unroll
        for (int nt = 0; nt < 2; nt++) {
            int col = cw16 + nt * 8 + 2 * cc;
            *(float2*)&AMs[(sh * 16 + gr) * 132 + col]       = make_float2(acc[sh][nt][0], acc[sh][nt][1]);
            *(float2*)&AMs[(sh * 16 + gr + 8) * 132 + col]   = make_float2(acc[sh][nt][2], acc[sh][nt][3]);
        }
    __syncthreads();
#pragma unroll
    for (int t = 0; t < 4; t++) {
        int idx = t * 256 + tid;
        int r = idx >> 5, p4 = idx & 31;
        *(float4*)&AM[(size_t)(s0 + r) * NC + c0 + p4 * 4] = *(const float4*)&AMs[r * 132 + p4 * 4];
    }
}

// ---------------- cross-attn epilogue LN ----------------
__global__ __launch_bounds__(256) void ln_ca_kernel(
    const float* __restrict__ g, const float* __restrict__ b, const float* __restrict__ fusion)
{
    int tid = threadIdx.x;
    if (blockIdx.x == 0 && tid < D) g_tok[tid] = fusion[tid];
    int warp = tid >> 5, lane = tid & 31;
    int row = blockIdx.x * 8 + warp;
    float x[8];
    float s = 0.f;
#pragma unroll
    for (int j = 0; j < 8; j++) {
        int c = lane + 32 * j;
        x[j] = g_tmp[(size_t)row * D + c] + g_HS[(size_t)row * D + c];
        s += x[j];
    }
    s = warpSum(s);
    float m = s * (1.0f / D);
    float vs = 0.f;
#pragma unroll
    for (int j = 0; j < 8; j++) { float d = x[j] - m; vs += d * d; }
    vs = warpSum(vs);
    float r = rsqrtf(vs * (1.0f / D) + 1e-5f);
#pragma unroll
    for (int j = 0; j < 8; j++) {
        int c = lane + 32 * j;
        g_tok[(size_t)(1 + row) * D + c] = (x[j] - m) * r * g[c] + b[c];
    }
}

// ---------------- fused q0 + row-0 scores + AV over tokens (per-block partials) ----------------
__global__ __launch_bounds__(256) void sa0_kernel(
    const float* __restrict__ fusion,
    const float* __restrict__ w, const float* __restrict__ bqkv)
{
    __shared__ float fs[D];
    __shared__ float q0s[D];
    __shared__ float zpart[NH];
    __shared__ float a0s[D];
    int tid = threadIdx.x;
    fs[tid] = fusion[tid];
    a0s[tid] = 0.f;
    if (tid < NH) zpart[tid] = 0.f;
    __syncthreads();
    {
        float a = bqkv[tid];
        const float* wr_ = &w[(size_t)tid * D];
        for (int c = 0; c < D; c++) a += fs[c] * wr_[c];
        q0s[tid] = a;
    }
    __syncthreads();

    int warp = tid >> 5, lane = tid & 31;
    int wtotal = gridDim.x * 8;
    const float isq = 0.17677669529663687f;
    float acc[8] = {};
    float zacc = 0.f;
    for (int u = blockIdx.x * 8 + warp; u < TT; u += wtotal) {
        float mine = 0.f;
#pragma unroll
        for (int j = 0; j < 8; j++) {
            int c = lane + 32 * j;
            float v = q0s[c] * g_k2[(size_t)u * D + c];
            v = warpSum(v);
            if (lane == j) mine = v;
        }
        float pl = __expf(mine * isq);
        if (lane < 8) zacc += pl;
        float ph = __shfl_sync(0xffffffffu, pl, lane >> 2);
        const float* vrow = &g_v2[(size_t)u * D + lane * 8];
        float4 v0 = *(const float4*)vrow;
        float4 v1 = *(const float4*)(vrow + 4);
        acc[0] += ph * v0.x; acc[1] += ph * v0.y; acc[2] += ph * v0.z; acc[3] += ph * v0.w;
        acc[4] += ph * v1.x; acc[5] += ph * v1.y; acc[6] += ph * v1.z; acc[7] += ph * v1.w;
    }
    if (lane < 8) atomicAdd(&zpart[lane], zacc);
#pragma unroll
    for (int j = 0; j < 8; j++)
        atomicAdd(&a0s[lane * 8 + j], acc[j]);
    __syncthreads();
    g_a0p[blockIdx.x][tid] = a0s[tid];
    if (tid < NH) g_Z0p[blockIdx.x][tid] = zpart[tid];
}

// ---------------- final head ----------------
__device__ __forceinline__ float blockSum256(float v, volatile float* red) {
    int lane = threadIdx.x & 31, w = threadIdx.x >> 5;
    v = warpSum(v);
    __syncthreads();
    if (lane == 0) red[w] = v;
    __syncthreads();
    float s = 0.f;
#pragma unroll
    for (int i = 0; i < 8; i++) s += red[i];
    return s;
}

__global__ __launch_bounds__(256) void final_kernel(
    const float* __restrict__ fusion,
    const float* __restrict__ mow, const float* __restrict__ mob,
    const float* __restrict__ ln1g, const float* __restrict__ ln1b,
    const float* __restrict__ w1, const float* __restrict__ b1,
    const float* __restrict__ w2, const float* __restrict__ b2,
    const float* __restrict__ ln2g, const float* __restrict__ ln2b,
    float* __restrict__ out)
{
    __shared__ float a0[D], t1[D], h1[2 * D];
    __shared__ float red[8];
    int tid = threadIdx.x;
    {
        float av = 0.f, zv = 0.f;
        int hh = tid >> 5;
#pragma unroll
        for (int b = 0; b < SA0_BLOCKS; b++) {
            av += g_a0p[b][tid];
            zv += g_Z0p[b][hh];
        }
        a0[tid] = av / zv;
    }
    __syncthreads();
    float y = mob[tid];
    for (int j = 0; j < D; j++) y += a0[j] * mow[(size_t)tid * D + j];
    float tv = fusion[tid] + y;
    float m = blockSum256(tv, red) * (1.0f / D);
    float d = tv - m;
    float var = blockSum256(d * d, red) * (1.0f / D);
    float t = d * rsqrtf(var + 1e-5f) * ln1g[tid] + ln1b[tid];
    t1[tid] = t;
    __syncthreads();
    float hh2[2];
#pragma unroll
    for (int r2 = 0; r2 < 2; r2++) {
        int jj = tid + r2 * 256;
        float a = b1[jj];
        for (int c = 0; c < D; c++) a += t1[c] * w1[(size_t)jj * D + c];
        hh2[r2] = a * 0.5f * (1.f + erff(a * 0.70710678118654752f));
    }
    h1[tid] = hh2[0];
    h1[tid + 256] = hh2[1];
    __syncthreads();
    float o = b2[tid];
    for (int j = 0; j < 512; j++) o += h1[j] * w2[(size_t)tid * 512 + j];
    float t2v = t1[tid] + o;   // residual = LN1 output
    float m2 = blockSum256(t2v, red) * (1.0f / D);
    float d2 = t2v - m2;
    float v2 = blockSum256(d2 * d2, red) * (1.0f / D);
    out[tid] = d2 * rsqrtf(v2 + 1e-5f) * ln2g[tid] + ln2b[tid];
}

// ---------------- launcher ----------------
extern "C" void kernel_launch(void* const* d_in, const int* in_sizes, int n_in,
                              void* d_out, int out_size)
{
    const float* H_S     = (const float*)d_in[0];
    const float* H_C     = (const float*)d_in[1];
    const float* H_G     = (const float*)d_in[2];
    const float* G_glyph = (const float*)d_in[3];
    const float* Ws      = (const float*)d_in[4];
    const float* bs      = (const float*)d_in[5];
    const float* Wb      = (const float*)d_in[6];
    const float* bb      = (const float*)d_in[7];
    const float* Wg      = (const float*)d_in[8];
    const float* bg      = (const float*)d_in[9];
    const float* WQ      = (const float*)d_in[10];
    const float* WK      = (const float*)d_in[11];
    const float* WV      = (const float*)d_in[12];
    const float* WO      = (const float*)d_in[13];
    const float* bO      = (const float*)d_in[14];
    const float* ln_ca_g = (const float*)d_in[15];
    const float* ln_ca_b = (const float*)d_in[16];
    const float* fusion  = (const float*)d_in[17];
    const float* mha_in_w  = (const float*)d_in[18];
    const float* mha_in_b  = (const float*)d_in[19];
    const float* mha_out_w = (const float*)d_in[20];
    const float* mha_out_b = (const float*)d_in[21];
    const float* ln1_g   = (const float*)d_in[22];
    const float* ln1_b   = (const float*)d_in[23];
    const float* ln2_g   = (const float*)d_in[24];
    const float* ln2_b   = (const float*)d_in[25];
    const float* ffn_w1  = (const float*)d_in[26];
    const float* ffn_b1  = (const float*)d_in[27];
    const float* ffn_w2  = (const float*)d_in[28];
    const float* ffn_b2  = (const float*)d_in[29];

    float* out = (float*)d_out;
    float* z_fused  = out;        // 256
    float* attn_map = out + D;    // 2048 * 4096

    float *pHS, *pHC, *pHnew, *pTmp, *pTok, *pk2, *pv2;
    __half *pQh, *pKh, *pVh, *pGh;
    cudaGetSymbolAddress((void**)&pHS,  g_HS);
    cudaGetSymbolAddress((void**)&pHC,  g_HC);
    cudaGetSymbolAddress((void**)&pQh,  g_Qh);
    cudaGetSymbolAddress((void**)&pKh,  g_Kh);
    cudaGetSymbolAddress((void**)&pVh,  g_Vh);
    cudaGetSymbolAddress((void**)&pGh,  g_Gh);
    cudaGetSymbolAddress((void**)&pHnew,g_Hnew);
    cudaGetSymbolAddress((void**)&pTmp, g_tmp);
    cudaGetSymbolAddress((void**)&pTok, g_tok);
    cudaGetSymbolAddress((void**)&pk2,  g_k2);
    cudaGetSymbolAddress((void**)&pv2,  g_v2);

    static bool attrSet = false;
    static cudaStream_t s1;
    static cudaEvent_t evFork, evJoin;
    if (!attrSet) {
        cudaFuncSetAttribute(ca_fused_kernel,
                             cudaFuncAttributeMaxDynamicSharedMemorySize, CA_SMEM);
        cudaFuncSetAttribute(attn_recompute_kernel,
                             cudaFuncAttributeMaxDynamicSharedMemorySize, AT_SMEM);
        int loPri, hiPri;
        cudaDeviceGetStreamPriorityRange(&loPri, &hiPri);
        cudaStreamCreateWithPriority(&s1, cudaStreamNonBlocking, loPri);  // LOW priority
        cudaEventCreateWithFlags(&evFork, cudaEventDisableTiming);
        cudaEventCreateWithFlags(&evJoin, cudaEventDisableTiming);
        attrSet = true;
    }

    // #1 HS (z0, K=128) + HG (z1, K=64) + HC (z2, K=256) + gate conversion (z3)
    gemm16_kernel<0><<<dim3(4, 64, 4), 256>>>(
        H_S, Ws, bs, pHS, nullptr, NS,
        H_G, Wg, bg, pTok + (size_t)(1 + NS) * D, nullptr, NG,
        H_C, Wb, bb, pHC, nullptr, NC, D, 128, 64, 256, G_glyph, pGh);
    // #2 Q/K/V triple (fp16 out)
    gemm16_kernel<1><<<dim3(4, 64, 3), 256>>>(
        pHS, WQ, nullptr, nullptr, pQh, NS,
        pHC, WK, nullptr, nullptr, pKh, NC,
        pHC, WV, nullptr, nullptr, pVh, NC, D, 256, 256, 256, nullptr, nullptr);
    // #3 fused gated cross attention (Z + Hnew)
    ca_fused_kernel<<<dim3(NH, NS / 32), 256, CA_SMEM>>>();

    // fork point (record after ca_fused)
    cudaEventRecord(evFork, (cudaStream_t)0);

    // main chain first (stream 0, higher effective priority)
    gemm16_kernel<0><<<dim3(4, 32), 256>>>(
        pHnew, WO, bO, pTmp, nullptr, NS,
        pHnew, WO, bO, pTmp, nullptr, NS,
        pHnew, WO, bO, pTmp, nullptr, NS, D, 256, 256, 256, nullptr, nullptr);
    ln_ca_kernel<<<NS / 8, 256>>>(ln_ca_g, ln_ca_b, fusion);
    gemm16_kernel<0><<<dim3(4, 65, 2), 256>>>(
        pTok, mha_in_w + 256 * 256, mha_in_b + 256, pk2, nullptr, TT,
        pTok, mha_in_w + 512 * 256, mha_in_b + 512, pv2, nullptr, TT,
        pTok, mha_in_w + 256 * 256, mha_in_b + 256, pk2, nullptr, TT, D, 256, 256, 256, nullptr, nullptr);
    sa0_kernel<<<SA0_BLOCKS, 256>>>(fusion, mha_in_w, mha_in_b);
    final_kernel<<<1, 256>>>(fusion, mha_out_w, mha_out_b, ln1_g, ln1_b,
                             ffn_w1, ffn_b1, ffn_w2, ffn_b2, ln2_g, ln2_b, z_fused);

    // low-priority attn_map recompute backfills idle SMs
    cudaStreamWaitEvent(s1, evFork, 0);
    attn_recompute_kernel<<<dim3(NC / 128, NS / 32), 256, AT_SMEM, s1>>>(attn_map);
    cudaEventRecord(evJoin, s1);
    cudaStreamWaitEvent((cudaStream_t)0, evJoin, 0);
}